// round 3
// baseline (speedup 1.0000x reference)
#include <cuda_runtime.h>
#include <cuda_bf16.h>

#define BQ  4
#define SQ  4096
#define LM  8192
#define DD  256
#define KNN 16

// Scratch (device globals: allocation-free, graph-capture safe)
__device__ float g_q [BQ*SQ*DD];   // 16 MB: query = mlp(posemb(q_coor))
__device__ float g_kv[(size_t)BQ*LM*DD]; // 32 MB: kv_pe = mlp(posemb(mem_coor)) + memory
__device__ int   g_idx[BQ*SQ*KNN]; // 1 MB : top-16 neighbor indices

#define EMB_LD 129
#define H_LD   257
#define SMEM_MLP ((64*EMB_LD + 64*H_LD + 16*128) * 4)
#define SMEM_TOPK (2 * LM * 4)

// ---------------------------------------------------------------------------
// Tiled fp32 GEMM inner routine: acc[8][8] += A_s(64 x ktot, lda) * W(ktot x 256)
// restricted to output cols [pass*128, pass*128+128).
// 128 threads as 16(tx: cols) x 8(ty: rows), 8x8 micro-tile per thread,
// BK=16 staged through smem ws[16][128].
// ---------------------------------------------------------------------------
__device__ __forceinline__ void gemm_pass(float acc[8][8],
    const float* __restrict__ A_s, int lda, int ktot,
    const float* __restrict__ W, float* ws, int pass, int tx, int ty, int tid)
{
    for (int kk = 0; kk < ktot; kk += 16) {
        __syncthreads();  // protect previous ws consumers / order A_s writes
        #pragma unroll
        for (int i = 0; i < 4; ++i) {
            int li = tid + i * 128;          // 512 float4 = 16 x 128 floats
            int rr = li >> 5, cc = li & 31;
            ((float4*)ws)[li] =
                *(const float4*)(W + (size_t)(kk + rr) * 256 + pass * 128 + cc * 4);
        }
        __syncthreads();
        #pragma unroll
        for (int k = 0; k < 16; ++k) {
            float a[8];
            #pragma unroll
            for (int i = 0; i < 8; ++i) a[i] = A_s[(ty * 8 + i) * lda + kk + k];
            float4 b0 = *(const float4*)(ws + k * 128 + 4 * tx);
            float4 b1 = *(const float4*)(ws + k * 128 + 64 + 4 * tx);
            float bv[8] = {b0.x, b0.y, b0.z, b0.w, b1.x, b1.y, b1.z, b1.w};
            #pragma unroll
            for (int i = 0; i < 8; ++i)
                #pragma unroll
                for (int j = 0; j < 8; ++j)
                    acc[i][j] = fmaf(a[i], bv[j], acc[i][j]);
        }
    }
}

// ---------------------------------------------------------------------------
// Kernel 1: fused PETR positional embedding + 2-layer MLP (fp32).
// One block = 64 rows; emb(64x128) and h(64x256) staged in smem.
// KV path adds `memory` and writes g_kv; query path writes g_q.
// ---------------------------------------------------------------------------
template<bool KV>
__global__ void __launch_bounds__(128, 1) mlp_kernel(
    const float* __restrict__ coor,
    const float* __restrict__ bW1, const float* __restrict__ bb1,
    const float* __restrict__ bW2, const float* __restrict__ bb2,
    const float* __restrict__ memory)
{
    extern __shared__ float sm[];
    float* emb_s = sm;                           // 64 x EMB_LD
    float* h_s   = sm + 64 * EMB_LD;             // 64 x H_LD
    float* ws    = sm + 64 * EMB_LD + 64 * H_LD; // 16 x 128
    const int tid = threadIdx.x;
    const int tx = tid & 15, ty = tid >> 4;
    const int row0 = blockIdx.x * 64;

    // ---- positional embedding: cols [0,64) from y, [64,128) from x.
    //      pair j within a half: sin(v), cos(v); v = coord*2pi*10000^(-j/32)
    for (int i = tid; i < 64 * 64; i += 128) {
        int r = i >> 6, jj = i & 63;
        int half = jj >> 5;      // 0 -> y (coord idx 1), 1 -> x (coord idx 0)
        int j = jj & 31;
        float coord = coor[2 * (row0 + r) + (half ? 0 : 1)];
        float freq = exp2f(-(float)j * 0.4152410118609203f); // 10000^(-j/32)
        float v = coord * 6.283185307179586477f * freq;
        float sv, cv;
        sincosf(v, &sv, &cv);
        emb_s[r * EMB_LD + half * 64 + 2 * j]     = sv;
        emb_s[r * EMB_LD + half * 64 + 2 * j + 1] = cv;
    }

    // ---- layer 1: h = relu(emb @ W1 + b1), two 128-col passes
    for (int pass = 0; pass < 2; ++pass) {
        float acc[8][8];
        #pragma unroll
        for (int i = 0; i < 8; ++i)
            #pragma unroll
            for (int j = 0; j < 8; ++j) acc[i][j] = 0.0f;
        gemm_pass(acc, emb_s, EMB_LD, 128, bW1, ws, pass, tx, ty, tid);
        #pragma unroll
        for (int i = 0; i < 8; ++i)
            #pragma unroll
            for (int j = 0; j < 8; ++j) {
                int col = pass * 128 + ((j < 4) ? (4 * tx + j) : (64 + 4 * tx + j - 4));
                float v = acc[i][j] + bb1[col];
                h_s[(ty * 8 + i) * H_LD + col] = fmaxf(v, 0.0f);
            }
    }

    // ---- layer 2: out = h @ W2 + b2 (+ memory for KV path)
    for (int pass = 0; pass < 2; ++pass) {
        float acc[8][8];
        #pragma unroll
        for (int i = 0; i < 8; ++i)
            #pragma unroll
            for (int j = 0; j < 8; ++j) acc[i][j] = 0.0f;
        gemm_pass(acc, h_s, H_LD, 256, bW2, ws, pass, tx, ty, tid);
        #pragma unroll
        for (int i = 0; i < 8; ++i)
            #pragma unroll
            for (int j = 0; j < 8; ++j) {
                int col = pass * 128 + ((j < 4) ? (4 * tx + j) : (64 + 4 * tx + j - 4));
                int n = row0 + ty * 8 + i;
                float v = acc[i][j] + bb2[col];
                if (KV) {
                    v += memory[(size_t)n * 256 + col];
                    g_kv[(size_t)n * 256 + col] = v;
                } else {
                    g_q[(size_t)n * 256 + col] = v;
                }
            }
    }
}

// ---------------------------------------------------------------------------
// Kernel 2: exact top-16 nearest neighbors (ascending d2, ties -> lower index).
// Warp per query; batch mem_coor cached in smem (SoA). Per lane: sorted-16
// register list over its 256 candidates (min-of-4 gate). Then 16 rounds of
// warp-wide lexicographic argmin merge.
// d2 rounding model of the reference (XLA):
//   m2 = add(mul,mul) (separate HLO ops, no contraction)
//   dot = fma(qy,my, qx*mx)  (dot HLO: implementation uses FMA internally)
//   d2 = (q2 + m2) - 2*dot
// ---------------------------------------------------------------------------
__global__ void __launch_bounds__(256, 1) topk_kernel(
    const float* __restrict__ q_coor, const float* __restrict__ mem_coor)
{
    extern __shared__ float sm2[];
    float* sx = sm2;
    float* sy = sm2 + LM;
    const int tid = threadIdx.x;
    const int b = blockIdx.y;
    const float2* mc = (const float2*)(mem_coor + (size_t)b * LM * 2);
    for (int i = tid; i < LM; i += 256) {
        float2 p = mc[i];
        sx[i] = p.x; sy[i] = p.y;
    }
    __syncthreads();

    const int wid = tid >> 5, lane = tid & 31;
    const int s = blockIdx.x * 8 + wid;
    const int qn = b * SQ + s;
    const float qx = q_coor[2 * qn], qy = q_coor[2 * qn + 1];
    const float q2 = __fadd_rn(__fmul_rn(qx, qx), __fmul_rn(qy, qy));

    float ld[16]; int li[16];
    #pragma unroll
    for (int j = 0; j < 16; ++j) { ld[j] = 3.4e38f; li[j] = 0; }

    for (int t = 0; t < LM / 128; ++t) {
        const int c0 = t * 128 + lane;
        float dm[4];
        #pragma unroll
        for (int m = 0; m < 4; ++m) {
            int c = c0 + m * 32;
            float mx = sx[c], my = sy[c];
            float m2 = __fadd_rn(__fmul_rn(mx, mx), __fmul_rn(my, my));
            float dt = __fmaf_rn(qy, my, __fmul_rn(qx, mx));   // dot HLO -> FMA
            dm[m] = __fsub_rn(__fadd_rn(q2, m2), __fmul_rn(2.0f, dt));
        }
        float mn = fminf(fminf(dm[0], dm[1]), fminf(dm[2], dm[3]));
        if (mn < ld[15]) {
            #pragma unroll
            for (int m = 0; m < 4; ++m) {
                float v = dm[m];
                if (v < ld[15]) {
                    ld[15] = v; li[15] = c0 + m * 32;
                    #pragma unroll
                    for (int jj = 15; jj > 0; --jj) {
                        if (ld[jj] < ld[jj - 1]) {  // strict: stable for equal d2
                            float td = ld[jj]; ld[jj] = ld[jj - 1]; ld[jj - 1] = td;
                            int  ti = li[jj]; li[jj] = li[jj - 1]; li[jj - 1] = ti;
                        }
                    }
                }
            }
        }
    }

    __syncthreads();  // all warps done with coords; reuse smem for merge lists
    float* md = sx;
    int*   mi = (int*)sy;
    const int base = tid * 17;  // pad to 17 floats to avoid bank conflicts
    #pragma unroll
    for (int j = 0; j < 16; ++j) { md[base + j] = ld[j]; mi[base + j] = li[j]; }
    __syncwarp();

    int p = 0;
    for (int r = 0; r < 16; ++r) {
        float bv = (p < 16) ? md[base + p] : 3.4e38f;
        int   bi = (p < 16) ? mi[base + p] : 0x7fffffff;
        int   bl = lane;
        #pragma unroll
        for (int off = 16; off; off >>= 1) {
            float ov = __shfl_down_sync(0xffffffffu, bv, off);
            int   oi = __shfl_down_sync(0xffffffffu, bi, off);
            int   ol = __shfl_down_sync(0xffffffffu, bl, off);
            if (ov < bv || (ov == bv && oi < bi)) { bv = ov; bi = oi; bl = ol; }
        }
        bi = __shfl_sync(0xffffffffu, bi, 0);
        bl = __shfl_sync(0xffffffffu, bl, 0);
        if (lane == 0) g_idx[qn * 16 + r] = bi;
        if (lane == bl) ++p;
    }
}

// ---------------------------------------------------------------------------
// Kernel 3: gather + softmax over feature dim D + multiply by memory.
// Block per query (512 thr = 16 warps); warp j handles neighbor j.
// Warp-local butterfly reductions only (no block barriers).
// ---------------------------------------------------------------------------
__global__ void __launch_bounds__(512, 1) attn_kernel(
    const float* __restrict__ memory, float* __restrict__ out)
{
    const int s = blockIdx.x, b = blockIdx.y;
    const int qn = b * SQ + s;
    const int w = threadIdx.x >> 5, lane = threadIdx.x & 31;

    const float4* qp = (const float4*)(g_q + (size_t)qn * 256);
    float4 q0 = qp[lane * 2], q1 = qp[lane * 2 + 1];

    const int idx = g_idx[qn * 16 + w];
    const float4* kvp = (const float4*)(g_kv + ((size_t)b * LM + idx) * 256);
    float4 k0 = kvp[lane * 2], k1 = kvp[lane * 2 + 1];

    float p[8];
    p[0] = q0.x * k0.x; p[1] = q0.y * k0.y; p[2] = q0.z * k0.z; p[3] = q0.w * k0.w;
    p[4] = q1.x * k1.x; p[5] = q1.y * k1.y; p[6] = q1.z * k1.z; p[7] = q1.w * k1.w;
    #pragma unroll
    for (int i = 0; i < 8; ++i) p[i] *= 0.0625f;  // 1/sqrt(256)

    float mx = p[0];
    #pragma unroll
    for (int i = 1; i < 8; ++i) mx = fmaxf(mx, p[i]);
    #pragma unroll
    for (int off = 16; off; off >>= 1)
        mx = fmaxf(mx, __shfl_xor_sync(0xffffffffu, mx, off));

    float sum = 0.0f;
    #pragma unroll
    for (int i = 0; i < 8; ++i) { p[i] = __expf(p[i] - mx); sum += p[i]; }
    #pragma unroll
    for (int off = 16; off; off >>= 1)
        sum += __shfl_xor_sync(0xffffffffu, sum, off);
    const float inv = __frcp_rn(sum);

    const float4* mp = (const float4*)(memory + ((size_t)b * LM + idx) * 256);
    float4 m0 = mp[lane * 2], m1 = mp[lane * 2 + 1];

    float4 r0, r1;
    r0.x = p[0] * inv * m0.x; r0.y = p[1] * inv * m0.y;
    r0.z = p[2] * inv * m0.z; r0.w = p[3] * inv * m0.w;
    r1.x = p[4] * inv * m1.x; r1.y = p[5] * inv * m1.y;
    r1.z = p[6] * inv * m1.z; r1.w = p[7] * inv * m1.w;

    float4* op = (float4*)(out + ((size_t)(qn * 16 + w)) * 256);
    op[lane * 2]     = r0;
    op[lane * 2 + 1] = r1;
}

// ---------------------------------------------------------------------------

extern "C" void kernel_launch(void* const* d_in, const int* in_sizes, int n_in,
                              void* d_out, int out_size)
{
    const float* memory   = (const float*)d_in[0];
    const float* mem_coor = (const float*)d_in[1];
    const float* q_coor   = (const float*)d_in[2];
    const float* Wq1 = (const float*)d_in[3];
    const float* bq1 = (const float*)d_in[4];
    const float* Wq2 = (const float*)d_in[5];
    const float* bq2 = (const float*)d_in[6];
    const float* Wk1 = (const float*)d_in[7];
    const float* bk1 = (const float*)d_in[8];
    const float* Wk2 = (const float*)d_in[9];
    const float* bk2 = (const float*)d_in[10];
    float* out = (float*)d_out;

    cudaFuncSetAttribute(mlp_kernel<false>,
        cudaFuncAttributeMaxDynamicSharedMemorySize, SMEM_MLP);
    cudaFuncSetAttribute(mlp_kernel<true>,
        cudaFuncAttributeMaxDynamicSharedMemorySize, SMEM_MLP);
    cudaFuncSetAttribute(topk_kernel,
        cudaFuncAttributeMaxDynamicSharedMemorySize, SMEM_TOPK);

    // K1: query MLP (16384 rows) and KV MLP (32768 rows)
    mlp_kernel<false><<<(BQ * SQ) / 64, 128, SMEM_MLP>>>(
        q_coor, Wq1, bq1, Wq2, bq2, nullptr);
    mlp_kernel<true><<<(BQ * LM) / 64, 128, SMEM_MLP>>>(
        mem_coor, Wk1, bk1, Wk2, bk2, memory);

    // K2: top-16 neighbors
    topk_kernel<<<dim3(SQ / 8, BQ), 256, SMEM_TOPK>>>(q_coor, mem_coor);

    // K3: gather + softmax(D) + multiply
    attn_kernel<<<dim3(SQ, BQ), 512>>>(memory, out);
}

// round 5
// speedup vs baseline: 1.2680x; 1.2680x over previous
#include <cuda_runtime.h>
#include <cuda_bf16.h>
#include <cstdint>

#define BQ  4
#define SQ  4096
#define LM  8192
#define DD  256
#define KNN 16

// Scratch (device globals: allocation-free, graph-capture safe)
__device__ __align__(16) float g_q [BQ*SQ*DD];         // 16 MB
__device__ __align__(16) float g_kv[(size_t)BQ*LM*DD]; // 32 MB
__device__ int   g_idx[BQ*SQ*KNN];                     // 1 MB
// bf16 transposed weights: w1t[n*128+k] = W1[k][n]; w2t[n*256+k] = W2[k][n]
__device__ __align__(16) __nv_bfloat16 g_w1t_q[256*128];
__device__ __align__(16) __nv_bfloat16 g_w2t_q[256*256];
__device__ __align__(16) __nv_bfloat16 g_w1t_k[256*128];
__device__ __align__(16) __nv_bfloat16 g_w2t_k[256*256];

// ---------------------------------------------------------------------------
// smem layout for the MLP kernel (bf16 elements, padded rows -> no conflicts)
//   A1 (emb):  128 rows x 136  -> 34816 B
//   WB (wts):  256 rows x 136  -> 69632 B  (W1t, then W2t chunk0, chunk1)
//   H  (hid):  128 rows x 264  -> 67584 B
// total 172032 B dynamic smem (fits 227KB carveout), 1 CTA/SM
// ---------------------------------------------------------------------------
#define LDA 136
#define LDB 136
#define LDH 264
#define SM_A1 0
#define SM_WB (128 * LDA)            /* element offsets (bf16) */
#define SM_H  (SM_WB + 256 * LDB)
#define SMEM_MLP_BYTES ((SM_H + 128 * LDH) * 2)

#define SMEM_TOPK (2 * LM * 4)

// bf16 mma.sync m16n8k16 (sm_80+ HMMA; legal at compute_103 base target)
__device__ __forceinline__ void mma_bf16(float c[4],
    uint32_t a0, uint32_t a1, uint32_t a2, uint32_t a3,
    uint32_t b0, uint32_t b1)
{
    asm volatile(
        "mma.sync.aligned.m16n8k16.row.col.f32.bf16.bf16.f32 "
        "{%0,%1,%2,%3}, {%4,%5,%6,%7}, {%8,%9}, {%0,%1,%2,%3};"
        : "+f"(c[0]), "+f"(c[1]), "+f"(c[2]), "+f"(c[3])
        : "r"(a0), "r"(a1), "r"(a2), "r"(a3), "r"(b0), "r"(b1));
}

// ---------------------------------------------------------------------------
// Kernel 0: weight prep — transpose + bf16-convert both weight sets.
// ---------------------------------------------------------------------------
__global__ void prep_weights(const float* __restrict__ Wq1, const float* __restrict__ Wq2,
                             const float* __restrict__ Wk1, const float* __restrict__ Wk2)
{
    int idx = blockIdx.x * 256 + threadIdx.x;  // 65536 total
    {
        int n = idx >> 8, k = idx & 255;
        g_w2t_q[idx] = __float2bfloat16(Wq2[k * 256 + n]);
        g_w2t_k[idx] = __float2bfloat16(Wk2[k * 256 + n]);
    }
    if (idx < 32768) {
        int n = idx >> 7, k = idx & 127;
        g_w1t_q[idx] = __float2bfloat16(Wq1[k * 256 + n]);
        g_w1t_k[idx] = __float2bfloat16(Wk1[k * 256 + n]);
    }
}

// ---------------------------------------------------------------------------
// Kernel 1: fused posemb + 2-layer MLP via mma.sync (bf16 in, fp32 accum).
// 384 CTAs: [0,128) query rows of g_q, [128,384) KV rows of g_kv.
// 512 threads = 16 warps as 4(row)x4(col); warp tile 32x64.
// Fragment lane maps (PTX ISA m16n8k16):
//   A a0:(r=l>>2, k=(l&3)*2) a1:r+8 a2:k+8 a3:both   B b0:(n=l>>2, k=(l&3)*2) b1:k+8
//   C c0:(r=l>>2, c=(l&3)*2) c1:c+1 c2:r+8 c3:r+8,c+1
// ---------------------------------------------------------------------------
__global__ void __launch_bounds__(512, 1) mlp_mma_kernel(
    const float* __restrict__ q_coor, const float* __restrict__ mem_coor,
    const float* __restrict__ bq1, const float* __restrict__ bq2,
    const float* __restrict__ bk1, const float* __restrict__ bk2,
    const float* __restrict__ memory)
{
    extern __shared__ __nv_bfloat16 sm[];
    const int tid  = threadIdx.x;
    const int w    = tid >> 5, lane = tid & 31;
    const int wr   = w >> 2, wc = w & 3;          // warp grid 4x4
    const int lr   = lane >> 2, lc = lane & 3;    // quad decomposition

    const bool KV = blockIdx.x >= 128;
    const int  cta = KV ? (blockIdx.x - 128) : blockIdx.x;
    const int  row0 = cta * 128;
    const float* coor = KV ? mem_coor : q_coor;
    const __nv_bfloat16* w1t = KV ? g_w1t_k : g_w1t_q;
    const __nv_bfloat16* w2t = KV ? g_w2t_k : g_w2t_q;
    const float* b1 = KV ? bk1 : bq1;
    const float* b2 = KV ? bk2 : bq2;
    float* dst = KV ? g_kv : g_q;

    // ---- stage emb (posemb, bf16) into A1 and W1^T into WB
    for (int p = tid; p < 128 * 64; p += 512) {
        int r = p >> 6, pp = p & 63;
        int half = pp >> 5, j = pp & 31;
        float coord = coor[2 * (row0 + r) + (half ? 0 : 1)];
        float freq = exp2f(-(float)j * 0.4152410118609203f);   // 10000^(-j/32)
        float v = coord * 6.283185307179586477f * freq;
        float sv, cv;
        sincosf(v, &sv, &cv);
        *(__nv_bfloat162*)(sm + SM_A1 + r * LDA + half * 64 + 2 * j) =
            __floats2bfloat162_rn(sv, cv);
    }
    for (int p = tid; p < 256 * 16; p += 512) {       // 16 uint4 per 128-elem row
        int n = p >> 4, ch = p & 15;
        *(uint4*)(sm + SM_WB + n * LDB + ch * 8) = *(const uint4*)(w1t + n * 128 + ch * 8);
    }
    __syncthreads();

    // ---- layer 1: C1 = emb @ W1^T   (K=128, 8 k-steps)
    float c1[2][8][4];
    #pragma unroll
    for (int mi = 0; mi < 2; ++mi)
        #pragma unroll
        for (int ni = 0; ni < 8; ++ni)
            #pragma unroll
            for (int q = 0; q < 4; ++q) c1[mi][ni][q] = 0.0f;

    #pragma unroll
    for (int ks = 0; ks < 8; ++ks) {
        const int k0 = ks * 16;
        uint32_t a[2][4], b[8][2];
        #pragma unroll
        for (int mi = 0; mi < 2; ++mi) {
            const __nv_bfloat16* ap = sm + SM_A1 + (wr * 32 + mi * 16 + lr) * LDA + k0 + lc * 2;
            a[mi][0] = *(const uint32_t*)ap;
            a[mi][1] = *(const uint32_t*)(ap + 8 * LDA);
            a[mi][2] = *(const uint32_t*)(ap + 8);
            a[mi][3] = *(const uint32_t*)(ap + 8 * LDA + 8);
        }
        #pragma unroll
        for (int ni = 0; ni < 8; ++ni) {
            const __nv_bfloat16* bp = sm + SM_WB + (wc * 64 + ni * 8 + lr) * LDB + k0 + lc * 2;
            b[ni][0] = *(const uint32_t*)bp;
            b[ni][1] = *(const uint32_t*)(bp + 8);
        }
        #pragma unroll
        for (int mi = 0; mi < 2; ++mi)
            #pragma unroll
            for (int ni = 0; ni < 8; ++ni)
                mma_bf16(c1[mi][ni], a[mi][0], a[mi][1], a[mi][2], a[mi][3],
                         b[ni][0], b[ni][1]);
    }

    // ---- epilogue 1: +b1, relu, bf16 -> H
    #pragma unroll
    for (int mi = 0; mi < 2; ++mi)
        #pragma unroll
        for (int ni = 0; ni < 8; ++ni) {
            int col = wc * 64 + ni * 8 + lc * 2;
            int row = wr * 32 + mi * 16 + lr;
            float bl = __ldg(&b1[col]), bh = __ldg(&b1[col + 1]);
            float v0 = fmaxf(c1[mi][ni][0] + bl, 0.0f);
            float v1 = fmaxf(c1[mi][ni][1] + bh, 0.0f);
            float v2 = fmaxf(c1[mi][ni][2] + bl, 0.0f);
            float v3 = fmaxf(c1[mi][ni][3] + bh, 0.0f);
            *(__nv_bfloat162*)(sm + SM_H + row * LDH + col) = __floats2bfloat162_rn(v0, v1);
            *(__nv_bfloat162*)(sm + SM_H + (row + 8) * LDH + col) = __floats2bfloat162_rn(v2, v3);
        }
    __syncthreads();   // H complete; all warps done reading WB (W1)

    // ---- layer 2: C2 = h @ W2^T  (K=256, two 128-k chunks through WB)
    float c2[2][8][4];
    #pragma unroll
    for (int mi = 0; mi < 2; ++mi)
        #pragma unroll
        for (int ni = 0; ni < 8; ++ni)
            #pragma unroll
            for (int q = 0; q < 4; ++q) c2[mi][ni][q] = 0.0f;

    #pragma unroll 1
    for (int chunk = 0; chunk < 2; ++chunk) {
        for (int p = tid; p < 256 * 16; p += 512) {
            int n = p >> 4, ch = p & 15;
            *(uint4*)(sm + SM_WB + n * LDB + ch * 8) =
                *(const uint4*)(w2t + n * 256 + chunk * 128 + ch * 8);
        }
        __syncthreads();
        #pragma unroll
        for (int ks = 0; ks < 8; ++ks) {
            const int kg = chunk * 128 + ks * 16;   // global k into H
            const int kl = ks * 16;                 // local k into WB
            uint32_t a[2][4], b[8][2];
            #pragma unroll
            for (int mi = 0; mi < 2; ++mi) {
                const __nv_bfloat16* ap = sm + SM_H + (wr * 32 + mi * 16 + lr) * LDH + kg + lc * 2;
                a[mi][0] = *(const uint32_t*)ap;
                a[mi][1] = *(const uint32_t*)(ap + 8 * LDH);
                a[mi][2] = *(const uint32_t*)(ap + 8);
                a[mi][3] = *(const uint32_t*)(ap + 8 * LDH + 8);
            }
            #pragma unroll
            for (int ni = 0; ni < 8; ++ni) {
                const __nv_bfloat16* bp = sm + SM_WB + (wc * 64 + ni * 8 + lr) * LDB + kl + lc * 2;
                b[ni][0] = *(const uint32_t*)bp;
                b[ni][1] = *(const uint32_t*)(bp + 8);
            }
            #pragma unroll
            for (int mi = 0; mi < 2; ++mi)
                #pragma unroll
                for (int ni = 0; ni < 8; ++ni)
                    mma_bf16(c2[mi][ni], a[mi][0], a[mi][1], a[mi][2], a[mi][3],
                             b[ni][0], b[ni][1]);
        }
        __syncthreads();   // done reading WB before next chunk overwrite
    }

    // ---- epilogue 2: +b2 (+memory for KV) -> fp32 global
    #pragma unroll
    for (int mi = 0; mi < 2; ++mi)
        #pragma unroll
        for (int ni = 0; ni < 8; ++ni) {
            int col = wc * 64 + ni * 8 + lc * 2;
            int r0g = row0 + wr * 32 + mi * 16 + lr;
            float bl = __ldg(&b2[col]), bh = __ldg(&b2[col + 1]);
            float2 v0 = make_float2(c2[mi][ni][0] + bl, c2[mi][ni][1] + bh);
            float2 v1 = make_float2(c2[mi][ni][2] + bl, c2[mi][ni][3] + bh);
            size_t o0 = (size_t)r0g * 256 + col;
            size_t o1 = (size_t)(r0g + 8) * 256 + col;
            if (KV) {
                float2 m0 = *(const float2*)(memory + o0);
                float2 m1 = *(const float2*)(memory + o1);
                v0.x += m0.x; v0.y += m0.y; v1.x += m1.x; v1.y += m1.y;
            }
            *(float2*)(dst + o0) = v0;
            *(float2*)(dst + o1) = v1;
        }
}

// ---------------------------------------------------------------------------
// Kernel 2: exact top-16 nearest neighbors (unchanged from passing R3).
// ---------------------------------------------------------------------------
__global__ void __launch_bounds__(256, 1) topk_kernel(
    const float* __restrict__ q_coor, const float* __restrict__ mem_coor)
{
    extern __shared__ float sm2[];
    float* sx = sm2;
    float* sy = sm2 + LM;
    const int tid = threadIdx.x;
    const int b = blockIdx.y;
    const float2* mc = (const float2*)(mem_coor + (size_t)b * LM * 2);
    for (int i = tid; i < LM; i += 256) {
        float2 p = mc[i];
        sx[i] = p.x; sy[i] = p.y;
    }
    __syncthreads();

    const int wid = tid >> 5, lane = tid & 31;
    const int s = blockIdx.x * 8 + wid;
    const int qn = b * SQ + s;
    const float qx = q_coor[2 * qn], qy = q_coor[2 * qn + 1];
    const float q2 = __fadd_rn(__fmul_rn(qx, qx), __fmul_rn(qy, qy));

    float ld[16]; int li[16];
    #pragma unroll
    for (int j = 0; j < 16; ++j) { ld[j] = 3.4e38f; li[j] = 0; }

    for (int t = 0; t < LM / 128; ++t) {
        const int c0 = t * 128 + lane;
        float dm[4];
        #pragma unroll
        for (int m = 0; m < 4; ++m) {
            int c = c0 + m * 32;
            float mx = sx[c], my = sy[c];
            float m2 = __fadd_rn(__fmul_rn(mx, mx), __fmul_rn(my, my));
            float dt = __fmaf_rn(qy, my, __fmul_rn(qx, mx));   // dot HLO -> FMA
            dm[m] = __fsub_rn(__fadd_rn(q2, m2), __fmul_rn(2.0f, dt));
        }
        float mn = fminf(fminf(dm[0], dm[1]), fminf(dm[2], dm[3]));
        if (mn < ld[15]) {
            #pragma unroll
            for (int m = 0; m < 4; ++m) {
                float v = dm[m];
                if (v < ld[15]) {
                    ld[15] = v; li[15] = c0 + m * 32;
                    #pragma unroll
                    for (int jj = 15; jj > 0; --jj) {
                        if (ld[jj] < ld[jj - 1]) {
                            float td = ld[jj]; ld[jj] = ld[jj - 1]; ld[jj - 1] = td;
                            int  ti = li[jj]; li[jj] = li[jj - 1]; li[jj - 1] = ti;
                        }
                    }
                }
            }
        }
    }

    __syncthreads();
    float* md = sx;
    int*   mi = (int*)sy;
    const int base = tid * 17;
    #pragma unroll
    for (int j = 0; j < 16; ++j) { md[base + j] = ld[j]; mi[base + j] = li[j]; }
    __syncwarp();

    int p = 0;
    for (int r = 0; r < 16; ++r) {
        float bv = (p < 16) ? md[base + p] : 3.4e38f;
        int   bi = (p < 16) ? mi[base + p] : 0x7fffffff;
        int   bl = lane;
        #pragma unroll
        for (int off = 16; off; off >>= 1) {
            float ov = __shfl_down_sync(0xffffffffu, bv, off);
            int   oi = __shfl_down_sync(0xffffffffu, bi, off);
            int   ol = __shfl_down_sync(0xffffffffu, bl, off);
            if (ov < bv || (ov == bv && oi < bi)) { bv = ov; bi = oi; bl = ol; }
        }
        bi = __shfl_sync(0xffffffffu, bi, 0);
        bl = __shfl_sync(0xffffffffu, bl, 0);
        if (lane == 0) g_idx[qn * 16 + r] = bi;
        if (lane == bl) ++p;
    }
}

// ---------------------------------------------------------------------------
// Kernel 3: gather + softmax over D + multiply (unchanged from passing R3).
// ---------------------------------------------------------------------------
__global__ void __launch_bounds__(512, 1) attn_kernel(
    const float* __restrict__ memory, float* __restrict__ out)
{
    const int s = blockIdx.x, b = blockIdx.y;
    const int qn = b * SQ + s;
    const int w = threadIdx.x >> 5, lane = threadIdx.x & 31;

    const float4* qp = (const float4*)(g_q + (size_t)qn * 256);
    float4 q0 = qp[lane * 2], q1 = qp[lane * 2 + 1];

    const int idx = g_idx[qn * 16 + w];
    const float4* kvp = (const float4*)(g_kv + ((size_t)b * LM + idx) * 256);
    float4 k0 = kvp[lane * 2], k1 = kvp[lane * 2 + 1];

    float p[8];
    p[0] = q0.x * k0.x; p[1] = q0.y * k0.y; p[2] = q0.z * k0.z; p[3] = q0.w * k0.w;
    p[4] = q1.x * k1.x; p[5] = q1.y * k1.y; p[6] = q1.z * k1.z; p[7] = q1.w * k1.w;
    #pragma unroll
    for (int i = 0; i < 8; ++i) p[i] *= 0.0625f;

    float mx = p[0];
    #pragma unroll
    for (int i = 1; i < 8; ++i) mx = fmaxf(mx, p[i]);
    #pragma unroll
    for (int off = 16; off; off >>= 1)
        mx = fmaxf(mx, __shfl_xor_sync(0xffffffffu, mx, off));

    float sum = 0.0f;
    #pragma unroll
    for (int i = 0; i < 8; ++i) { p[i] = __expf(p[i] - mx); sum += p[i]; }
    #pragma unroll
    for (int off = 16; off; off >>= 1)
        sum += __shfl_xor_sync(0xffffffffu, sum, off);
    const float inv = __frcp_rn(sum);

    const float4* mp = (const float4*)(memory + ((size_t)b * LM + idx) * 256);
    float4 m0 = mp[lane * 2], m1 = mp[lane * 2 + 1];

    float4 r0, r1;
    r0.x = p[0] * inv * m0.x; r0.y = p[1] * inv * m0.y;
    r0.z = p[2] * inv * m0.z; r0.w = p[3] * inv * m0.w;
    r1.x = p[4] * inv * m1.x; r1.y = p[5] * inv * m1.y;
    r1.z = p[6] * inv * m1.z; r1.w = p[7] * inv * m1.w;

    float4* op = (float4*)(out + ((size_t)(qn * 16 + w)) * 256);
    op[lane * 2]     = r0;
    op[lane * 2 + 1] = r1;
}

// ---------------------------------------------------------------------------

extern "C" void kernel_launch(void* const* d_in, const int* in_sizes, int n_in,
                              void* d_out, int out_size)
{
    const float* memory   = (const float*)d_in[0];
    const float* mem_coor = (const float*)d_in[1];
    const float* q_coor   = (const float*)d_in[2];
    const float* Wq1 = (const float*)d_in[3];
    const float* bq1 = (const float*)d_in[4];
    const float* Wq2 = (const float*)d_in[5];
    const float* bq2 = (const float*)d_in[6];
    const float* Wk1 = (const float*)d_in[7];
    const float* bk1 = (const float*)d_in[8];
    const float* Wk2 = (const float*)d_in[9];
    const float* bk2 = (const float*)d_in[10];
    float* out = (float*)d_out;

    cudaFuncSetAttribute(mlp_mma_kernel,
        cudaFuncAttributeMaxDynamicSharedMemorySize, SMEM_MLP_BYTES);
    cudaFuncSetAttribute(topk_kernel,
        cudaFuncAttributeMaxDynamicSharedMemorySize, SMEM_TOPK);

    // K0: weight transpose + bf16
    prep_weights<<<256, 256>>>(Wq1, Wq2, Wk1, Wk2);

    // K1: fused query+KV MLP on mma.sync (CTAs 0..127 query, 128..383 KV)
    mlp_mma_kernel<<<384, 512, SMEM_MLP_BYTES>>>(
        q_coor, mem_coor, bq1, bq2, bk1, bk2, memory);

    // K2: top-16 neighbors
    topk_kernel<<<dim3(SQ / 8, BQ), 256, SMEM_TOPK>>>(q_coor, mem_coor);

    // K3: gather + softmax(D) + multiply
    attn_kernel<<<dim3(SQ, BQ), 512>>>(memory, out);
}

// round 6
// speedup vs baseline: 1.9978x; 1.5756x over previous
#include <cuda_runtime.h>
#include <cuda_bf16.h>
#include <cstdint>

#define BQ  4
#define SQ  4096
#define LM  8192
#define DD  256
#define KNN 16

// Scratch (device globals: allocation-free, graph-capture safe)
__device__ __align__(16) float g_q [BQ*SQ*DD];         // 16 MB
__device__ __align__(16) float g_kv[(size_t)BQ*LM*DD]; // 32 MB
__device__ int   g_idx[BQ*SQ*KNN];                     // 1 MB
// bf16 transposed weights: w1t[n*128+k] = W1[k][n]; w2t[n*256+k] = W2[k][n]
__device__ __align__(16) __nv_bfloat16 g_w1t_q[256*128];
__device__ __align__(16) __nv_bfloat16 g_w2t_q[256*256];
__device__ __align__(16) __nv_bfloat16 g_w1t_k[256*128];
__device__ __align__(16) __nv_bfloat16 g_w2t_k[256*256];

// ---------------------------------------------------------------------------
// smem layout for the MLP kernel (bf16 elements, padded rows -> no conflicts)
// ---------------------------------------------------------------------------
#define LDA 136
#define LDB 136
#define LDH 264
#define SM_A1 0
#define SM_WB (128 * LDA)            /* element offsets (bf16) */
#define SM_H  (SM_WB + 256 * LDB)
#define SMEM_MLP_BYTES ((SM_H + 128 * LDH) * 2)

// topk smem: float2 xy[8192] (64K) + float m2[8192] (32K) + u64 buf[8][48] (3K)
#define TK_BUFCAP 48
#define SMEM_TOPK (LM * 8 + LM * 4 + 8 * TK_BUFCAP * 8)

// bf16 mma.sync m16n8k16 (sm_80+ HMMA; legal at compute_103 base target)
__device__ __forceinline__ void mma_bf16(float c[4],
    uint32_t a0, uint32_t a1, uint32_t a2, uint32_t a3,
    uint32_t b0, uint32_t b1)
{
    asm volatile(
        "mma.sync.aligned.m16n8k16.row.col.f32.bf16.bf16.f32 "
        "{%0,%1,%2,%3}, {%4,%5,%6,%7}, {%8,%9}, {%0,%1,%2,%3};"
        : "+f"(c[0]), "+f"(c[1]), "+f"(c[2]), "+f"(c[3])
        : "r"(a0), "r"(a1), "r"(a2), "r"(a3), "r"(b0), "r"(b1));
}

// orderable-float transforms (total order matching float <, handles negatives)
__device__ __forceinline__ uint32_t f2ord(float f) {
    uint32_t u = __float_as_uint(f);
    return u ^ ((uint32_t)((int)u >> 31) | 0x80000000u);
}
__device__ __forceinline__ float ord2f(uint32_t o) {
    uint32_t u = o ^ ((uint32_t)((int)(~o) >> 31) | 0x80000000u);
    return __uint_as_float(u);
}

// ---------------------------------------------------------------------------
// Kernel 0: weight prep — transpose + bf16-convert both weight sets.
// ---------------------------------------------------------------------------
__global__ void prep_weights(const float* __restrict__ Wq1, const float* __restrict__ Wq2,
                             const float* __restrict__ Wk1, const float* __restrict__ Wk2)
{
    int idx = blockIdx.x * 256 + threadIdx.x;  // 65536 total
    {
        int n = idx >> 8, k = idx & 255;
        g_w2t_q[idx] = __float2bfloat16(Wq2[k * 256 + n]);
        g_w2t_k[idx] = __float2bfloat16(Wk2[k * 256 + n]);
    }
    if (idx < 32768) {
        int n = idx >> 7, k = idx & 127;
        g_w1t_q[idx] = __float2bfloat16(Wq1[k * 256 + n]);
        g_w1t_k[idx] = __float2bfloat16(Wk1[k * 256 + n]);
    }
}

// ---------------------------------------------------------------------------
// Kernel 1: fused posemb + 2-layer MLP via mma.sync (unchanged from R5 pass).
// ---------------------------------------------------------------------------
__global__ void __launch_bounds__(512, 1) mlp_mma_kernel(
    const float* __restrict__ q_coor, const float* __restrict__ mem_coor,
    const float* __restrict__ bq1, const float* __restrict__ bq2,
    const float* __restrict__ bk1, const float* __restrict__ bk2,
    const float* __restrict__ memory)
{
    extern __shared__ __nv_bfloat16 sm[];
    const int tid  = threadIdx.x;
    const int w    = tid >> 5, lane = tid & 31;
    const int wr   = w >> 2, wc = w & 3;
    const int lr   = lane >> 2, lc = lane & 3;

    const bool KV = blockIdx.x >= 128;
    const int  cta = KV ? (blockIdx.x - 128) : blockIdx.x;
    const int  row0 = cta * 128;
    const float* coor = KV ? mem_coor : q_coor;
    const __nv_bfloat16* w1t = KV ? g_w1t_k : g_w1t_q;
    const __nv_bfloat16* w2t = KV ? g_w2t_k : g_w2t_q;
    const float* b1 = KV ? bk1 : bq1;
    const float* b2 = KV ? bk2 : bq2;
    float* dst = KV ? g_kv : g_q;

    for (int p = tid; p < 128 * 64; p += 512) {
        int r = p >> 6, pp = p & 63;
        int half = pp >> 5, j = pp & 31;
        float coord = coor[2 * (row0 + r) + (half ? 0 : 1)];
        float freq = exp2f(-(float)j * 0.4152410118609203f);
        float v = coord * 6.283185307179586477f * freq;
        float sv, cv;
        sincosf(v, &sv, &cv);
        *(__nv_bfloat162*)(sm + SM_A1 + r * LDA + half * 64 + 2 * j) =
            __floats2bfloat162_rn(sv, cv);
    }
    for (int p = tid; p < 256 * 16; p += 512) {
        int n = p >> 4, ch = p & 15;
        *(uint4*)(sm + SM_WB + n * LDB + ch * 8) = *(const uint4*)(w1t + n * 128 + ch * 8);
    }
    __syncthreads();

    float c1[2][8][4];
    #pragma unroll
    for (int mi = 0; mi < 2; ++mi)
        #pragma unroll
        for (int ni = 0; ni < 8; ++ni)
            #pragma unroll
            for (int q = 0; q < 4; ++q) c1[mi][ni][q] = 0.0f;

    #pragma unroll
    for (int ks = 0; ks < 8; ++ks) {
        const int k0 = ks * 16;
        uint32_t a[2][4], b[8][2];
        #pragma unroll
        for (int mi = 0; mi < 2; ++mi) {
            const __nv_bfloat16* ap = sm + SM_A1 + (wr * 32 + mi * 16 + lr) * LDA + k0 + lc * 2;
            a[mi][0] = *(const uint32_t*)ap;
            a[mi][1] = *(const uint32_t*)(ap + 8 * LDA);
            a[mi][2] = *(const uint32_t*)(ap + 8);
            a[mi][3] = *(const uint32_t*)(ap + 8 * LDA + 8);
        }
        #pragma unroll
        for (int ni = 0; ni < 8; ++ni) {
            const __nv_bfloat16* bp = sm + SM_WB + (wc * 64 + ni * 8 + lr) * LDB + k0 + lc * 2;
            b[ni][0] = *(const uint32_t*)bp;
            b[ni][1] = *(const uint32_t*)(bp + 8);
        }
        #pragma unroll
        for (int mi = 0; mi < 2; ++mi)
            #pragma unroll
            for (int ni = 0; ni < 8; ++ni)
                mma_bf16(c1[mi][ni], a[mi][0], a[mi][1], a[mi][2], a[mi][3],
                         b[ni][0], b[ni][1]);
    }

    #pragma unroll
    for (int mi = 0; mi < 2; ++mi)
        #pragma unroll
        for (int ni = 0; ni < 8; ++ni) {
            int col = wc * 64 + ni * 8 + lc * 2;
            int row = wr * 32 + mi * 16 + lr;
            float bl = __ldg(&b1[col]), bh = __ldg(&b1[col + 1]);
            float v0 = fmaxf(c1[mi][ni][0] + bl, 0.0f);
            float v1 = fmaxf(c1[mi][ni][1] + bh, 0.0f);
            float v2 = fmaxf(c1[mi][ni][2] + bl, 0.0f);
            float v3 = fmaxf(c1[mi][ni][3] + bh, 0.0f);
            *(__nv_bfloat162*)(sm + SM_H + row * LDH + col) = __floats2bfloat162_rn(v0, v1);
            *(__nv_bfloat162*)(sm + SM_H + (row + 8) * LDH + col) = __floats2bfloat162_rn(v2, v3);
        }
    __syncthreads();

    float c2[2][8][4];
    #pragma unroll
    for (int mi = 0; mi < 2; ++mi)
        #pragma unroll
        for (int ni = 0; ni < 8; ++ni)
            #pragma unroll
            for (int q = 0; q < 4; ++q) c2[mi][ni][q] = 0.0f;

    #pragma unroll 1
    for (int chunk = 0; chunk < 2; ++chunk) {
        for (int p = tid; p < 256 * 16; p += 512) {
            int n = p >> 4, ch = p & 15;
            *(uint4*)(sm + SM_WB + n * LDB + ch * 8) =
                *(const uint4*)(w2t + n * 256 + chunk * 128 + ch * 8);
        }
        __syncthreads();
        #pragma unroll
        for (int ks = 0; ks < 8; ++ks) {
            const int kg = chunk * 128 + ks * 16;
            const int kl = ks * 16;
            uint32_t a[2][4], b[8][2];
            #pragma unroll
            for (int mi = 0; mi < 2; ++mi) {
                const __nv_bfloat16* ap = sm + SM_H + (wr * 32 + mi * 16 + lr) * LDH + kg + lc * 2;
                a[mi][0] = *(const uint32_t*)ap;
                a[mi][1] = *(const uint32_t*)(ap + 8 * LDH);
                a[mi][2] = *(const uint32_t*)(ap + 8);
                a[mi][3] = *(const uint32_t*)(ap + 8 * LDH + 8);
            }
            #pragma unroll
            for (int ni = 0; ni < 8; ++ni) {
                const __nv_bfloat16* bp = sm + SM_WB + (wc * 64 + ni * 8 + lr) * LDB + kl + lc * 2;
                b[ni][0] = *(const uint32_t*)bp;
                b[ni][1] = *(const uint32_t*)(bp + 8);
            }
            #pragma unroll
            for (int mi = 0; mi < 2; ++mi)
                #pragma unroll
                for (int ni = 0; ni < 8; ++ni)
                    mma_bf16(c2[mi][ni], a[mi][0], a[mi][1], a[mi][2], a[mi][3],
                             b[ni][0], b[ni][1]);
        }
        __syncthreads();
    }

    #pragma unroll
    for (int mi = 0; mi < 2; ++mi)
        #pragma unroll
        for (int ni = 0; ni < 8; ++ni) {
            int col = wc * 64 + ni * 8 + lc * 2;
            int r0g = row0 + wr * 32 + mi * 16 + lr;
            float bl = __ldg(&b2[col]), bh = __ldg(&b2[col + 1]);
            float2 v0 = make_float2(c2[mi][ni][0] + bl, c2[mi][ni][1] + bh);
            float2 v1 = make_float2(c2[mi][ni][2] + bl, c2[mi][ni][3] + bh);
            size_t o0 = (size_t)r0g * 256 + col;
            size_t o1 = (size_t)(r0g + 8) * 256 + col;
            if (KV) {
                float2 m0 = *(const float2*)(memory + o0);
                float2 m1 = *(const float2*)(memory + o1);
                v0.x += m0.x; v0.y += m0.y; v1.x += m1.x; v1.y += m1.y;
            }
            *(float2*)(dst + o0) = v0;
            *(float2*)(dst + o1) = v1;
        }
}

// ---------------------------------------------------------------------------
// Kernel 2: exact top-16 via warp-shared threshold + buffered consolidation.
// Warp per query. Gate: d2 < tau (tau = global 16th-best so far) — exact
// because scan order is index-ascending (ties with tau rank >= 17th).
// Accepted candidates -> per-warp u64 buffer (orderable-d2 ## index), merged
// by 16 rounds of warp-wide u64 extract-min on overflow / at the end.
// d2 rounding identical to R3-passing version.
// ---------------------------------------------------------------------------
__global__ void __launch_bounds__(256, 2) topk_kernel(
    const float* __restrict__ q_coor, const float* __restrict__ mem_coor)
{
    extern __shared__ char smraw[];
    float2* sxy = (float2*)smraw;                              // 64 KB
    float*  sm2 = (float*)(smraw + LM * 8);                    // 32 KB
    unsigned long long* sbuf =
        (unsigned long long*)(smraw + LM * 8 + LM * 4);        // 8 x 48 x 8B

    const int tid = threadIdx.x;
    const int b = blockIdx.y;
    const float2* mc = (const float2*)(mem_coor + (size_t)b * LM * 2);
    for (int i = tid; i < LM; i += 256) {
        float2 p = mc[i];
        sxy[i] = p;
        sm2[i] = __fadd_rn(__fmul_rn(p.x, p.x), __fmul_rn(p.y, p.y));
    }
    __syncthreads();

    const int wid = tid >> 5, lane = tid & 31;
    unsigned long long* buf = sbuf + wid * TK_BUFCAP;
    const int s = blockIdx.x * 8 + wid;
    const int qn = b * SQ + s;
    const float qx = q_coor[2 * qn], qy = q_coor[2 * qn + 1];
    const float q2 = __fadd_rn(__fmul_rn(qx, qx), __fmul_rn(qy, qy));

    const unsigned long long UMAX = 0xFFFFFFFFFFFFFFFFull;
    unsigned long long bestk = UMAX;  // lane r<16 holds rank-r best key
    float tau = __int_as_float(0x7f800000);  // +inf
    int cnt = 0;                      // buffer fill (warp-uniform)

    // warp-cooperative consolidation: best16 <- top16 of (best16 U buffer)
    auto consolidate = [&]() {
        unsigned long long k0 = (lane < cnt) ? buf[lane] : UMAX;
        unsigned long long k1 = (lane < 16 && lane + 32 < cnt) ? buf[lane + 32] : UMAX;
        unsigned long long k2 = bestk;
        unsigned long long nb = UMAX;
        #pragma unroll 1
        for (int r = 0; r < 16; ++r) {
            unsigned long long mk = k0; int src = 0;
            if (k1 < mk) { mk = k1; src = 1; }
            if (k2 < mk) { mk = k2; src = 2; }
            unsigned long long rk = mk; int rl = lane;
            #pragma unroll
            for (int off = 16; off; off >>= 1) {
                unsigned long long ok = __shfl_down_sync(0xffffffffu, rk, off);
                int ol = __shfl_down_sync(0xffffffffu, rl, off);
                if (ok < rk) { rk = ok; rl = ol; }
            }
            rk = __shfl_sync(0xffffffffu, rk, 0);
            rl = __shfl_sync(0xffffffffu, rl, 0);
            if (lane == r) nb = rk;
            if (lane == rl) {
                if (k0 == rk) k0 = UMAX;
                else if (k1 == rk) k1 = UMAX;
                else k2 = UMAX;
            }
        }
        bestk = nb;
        unsigned long long k15 = __shfl_sync(0xffffffffu, bestk, 15);
        tau = ord2f((uint32_t)(k15 >> 32));
        cnt = 0;
    };

    for (int t = 0; t < LM / 128; ++t) {
        const int c0 = t * 128 + lane;
        #pragma unroll
        for (int m = 0; m < 4; ++m) {
            const int c = c0 + m * 32;
            float2 pm = sxy[c];
            float m2 = sm2[c];
            float dt = __fmaf_rn(qy, pm.y, __fmul_rn(qx, pm.x));
            float d2 = __fsub_rn(__fadd_rn(q2, m2), __fmul_rn(2.0f, dt));
            bool acc = d2 < tau;
            unsigned mask = __ballot_sync(0xffffffffu, acc);
            if (mask) {
                int nacc = __popc(mask);
                if (cnt + nacc > TK_BUFCAP) {
                    consolidate();
                    acc = d2 < tau;
                    mask = __ballot_sync(0xffffffffu, acc);
                    nacc = __popc(mask);
                }
                if (acc) {
                    int pos = cnt + __popc(mask & ((1u << lane) - 1u));
                    buf[pos] = ((unsigned long long)f2ord(d2) << 32) | (uint32_t)c;
                }
                cnt += nacc;
            }
        }
    }
    if (cnt > 0) consolidate();

    if (lane < 16) g_idx[qn * 16 + lane] = (int)(uint32_t)bestk;
}

// ---------------------------------------------------------------------------
// Kernel 3: gather + softmax over D + multiply (unchanged from R3/R5 pass).
// ---------------------------------------------------------------------------
__global__ void __launch_bounds__(512, 1) attn_kernel(
    const float* __restrict__ memory, float* __restrict__ out)
{
    const int s = blockIdx.x, b = blockIdx.y;
    const int qn = b * SQ + s;
    const int w = threadIdx.x >> 5, lane = threadIdx.x & 31;

    const float4* qp = (const float4*)(g_q + (size_t)qn * 256);
    float4 q0 = qp[lane * 2], q1 = qp[lane * 2 + 1];

    const int idx = g_idx[qn * 16 + w];
    const float4* kvp = (const float4*)(g_kv + ((size_t)b * LM + idx) * 256);
    float4 k0 = kvp[lane * 2], k1 = kvp[lane * 2 + 1];

    float p[8];
    p[0] = q0.x * k0.x; p[1] = q0.y * k0.y; p[2] = q0.z * k0.z; p[3] = q0.w * k0.w;
    p[4] = q1.x * k1.x; p[5] = q1.y * k1.y; p[6] = q1.z * k1.z; p[7] = q1.w * k1.w;
    #pragma unroll
    for (int i = 0; i < 8; ++i) p[i] *= 0.0625f;

    float mx = p[0];
    #pragma unroll
    for (int i = 1; i < 8; ++i) mx = fmaxf(mx, p[i]);
    #pragma unroll
    for (int off = 16; off; off >>= 1)
        mx = fmaxf(mx, __shfl_xor_sync(0xffffffffu, mx, off));

    float sum = 0.0f;
    #pragma unroll
    for (int i = 0; i < 8; ++i) { p[i] = __expf(p[i] - mx); sum += p[i]; }
    #pragma unroll
    for (int off = 16; off; off >>= 1)
        sum += __shfl_xor_sync(0xffffffffu, sum, off);
    const float inv = __frcp_rn(sum);

    const float4* mp = (const float4*)(memory + ((size_t)b * LM + idx) * 256);
    float4 m0 = mp[lane * 2], m1 = mp[lane * 2 + 1];

    float4 r0, r1;
    r0.x = p[0] * inv * m0.x; r0.y = p[1] * inv * m0.y;
    r0.z = p[2] * inv * m0.z; r0.w = p[3] * inv * m0.w;
    r1.x = p[4] * inv * m1.x; r1.y = p[5] * inv * m1.y;
    r1.z = p[6] * inv * m1.z; r1.w = p[7] * inv * m1.w;

    float4* op = (float4*)(out + ((size_t)(qn * 16 + w)) * 256);
    op[lane * 2]     = r0;
    op[lane * 2 + 1] = r1;
}

// ---------------------------------------------------------------------------

extern "C" void kernel_launch(void* const* d_in, const int* in_sizes, int n_in,
                              void* d_out, int out_size)
{
    const float* memory   = (const float*)d_in[0];
    const float* mem_coor = (const float*)d_in[1];
    const float* q_coor   = (const float*)d_in[2];
    const float* Wq1 = (const float*)d_in[3];
    const float* bq1 = (const float*)d_in[4];
    const float* Wq2 = (const float*)d_in[5];
    const float* bq2 = (const float*)d_in[6];
    const float* Wk1 = (const float*)d_in[7];
    const float* bk1 = (const float*)d_in[8];
    const float* Wk2 = (const float*)d_in[9];
    const float* bk2 = (const float*)d_in[10];
    float* out = (float*)d_out;

    cudaFuncSetAttribute(mlp_mma_kernel,
        cudaFuncAttributeMaxDynamicSharedMemorySize, SMEM_MLP_BYTES);
    cudaFuncSetAttribute(topk_kernel,
        cudaFuncAttributeMaxDynamicSharedMemorySize, SMEM_TOPK);

    // K0: weight transpose + bf16
    prep_weights<<<256, 256>>>(Wq1, Wq2, Wk1, Wk2);

    // K1: fused query+KV MLP on mma.sync (CTAs 0..127 query, 128..383 KV)
    mlp_mma_kernel<<<384, 512, SMEM_MLP_BYTES>>>(
        q_coor, mem_coor, bq1, bq2, bk1, bk2, memory);

    // K2: top-16 neighbors (threshold-gated, buffered)
    topk_kernel<<<dim3(SQ / 8, BQ), 256, SMEM_TOPK>>>(q_coor, mem_coor);

    // K3: gather + softmax(D) + multiply
    attn_kernel<<<dim3(SQ, BQ), 512>>>(memory, out);
}

// round 7
// speedup vs baseline: 2.0089x; 1.0056x over previous
#include <cuda_runtime.h>
#include <cuda_bf16.h>
#include <cstdint>

#define BQ  4
#define SQ  4096
#define LM  8192
#define DD  256
#define KNN 16
#define NROW_Q (BQ*SQ)          /* 16384 */
#define NROW_T (BQ*(SQ+LM))     /* 49152 total MLP rows */

// Scratch (device globals: allocation-free, graph-capture safe)
__device__ __align__(16) float g_q [BQ*SQ*DD];         // 16 MB
__device__ __align__(16) float g_kv[(size_t)BQ*LM*DD]; // 32 MB
__device__ int   g_idx[BQ*SQ*KNN];                     // 1 MB
__device__ __align__(16) __nv_bfloat16 g_h[(size_t)NROW_T*DD];  // 24 MB hidden
// bf16 transposed weights: w1t[n*128+k] = W1[k][n]; w2t[n*256+k] = W2[k][n]
__device__ __align__(16) __nv_bfloat16 g_w1t_q[256*128];
__device__ __align__(16) __nv_bfloat16 g_w2t_q[256*256];
__device__ __align__(16) __nv_bfloat16 g_w1t_k[256*128];
__device__ __align__(16) __nv_bfloat16 g_w2t_k[256*256];

// ---------------------------------------------------------------------------
// smem layouts (bf16 elements; padded rows -> conflict-free fragment LDS)
// mlp1: A1 64x136 (17408B) + WB 256x136 (69632B)          = 87040B,  2 CTA/SM
// mlp2: AH 64x264 (33792B) + WB 256x136 (69632B)          = 103424B, 2 CTA/SM
// ---------------------------------------------------------------------------
#define LDA 136
#define LDB 136
#define LDH 264
#define M1_A  0
#define M1_WB (64 * LDA)
#define SMEM_MLP1 ((M1_WB + 256 * LDB) * 2)
#define M2_A  0
#define M2_WB (64 * LDH)
#define SMEM_MLP2 ((M2_WB + 256 * LDB) * 2)

// topk smem: float2 xy[8192] (64K) + float m2[8192] (32K) + u64 buf[8][48] (3K)
#define TK_BUFCAP 48
#define SMEM_TOPK (LM * 8 + LM * 4 + 8 * TK_BUFCAP * 8)

// bf16 mma.sync m16n8k16 (sm_80+ HMMA; legal at compute_103 base target)
__device__ __forceinline__ void mma_bf16(float c[4],
    uint32_t a0, uint32_t a1, uint32_t a2, uint32_t a3,
    uint32_t b0, uint32_t b1)
{
    asm volatile(
        "mma.sync.aligned.m16n8k16.row.col.f32.bf16.bf16.f32 "
        "{%0,%1,%2,%3}, {%4,%5,%6,%7}, {%8,%9}, {%0,%1,%2,%3};"
        : "+f"(c[0]), "+f"(c[1]), "+f"(c[2]), "+f"(c[3])
        : "r"(a0), "r"(a1), "r"(a2), "r"(a3), "r"(b0), "r"(b1));
}

// orderable-float transforms (total order matching float <)
__device__ __forceinline__ uint32_t f2ord(float f) {
    uint32_t u = __float_as_uint(f);
    return u ^ ((uint32_t)((int)u >> 31) | 0x80000000u);
}
__device__ __forceinline__ float ord2f(uint32_t o) {
    uint32_t u = o ^ ((uint32_t)((int)(~o) >> 31) | 0x80000000u);
    return __uint_as_float(u);
}

// ---------------------------------------------------------------------------
// Kernel 0: weight prep — transpose + bf16-convert both weight sets.
// ---------------------------------------------------------------------------
__global__ void prep_weights(const float* __restrict__ Wq1, const float* __restrict__ Wq2,
                             const float* __restrict__ Wk1, const float* __restrict__ Wk2)
{
    int idx = blockIdx.x * 256 + threadIdx.x;  // 65536 total
    {
        int n = idx >> 8, k = idx & 255;
        g_w2t_q[idx] = __float2bfloat16(Wq2[k * 256 + n]);
        g_w2t_k[idx] = __float2bfloat16(Wk2[k * 256 + n]);
    }
    if (idx < 32768) {
        int n = idx >> 7, k = idx & 127;
        g_w1t_q[idx] = __float2bfloat16(Wq1[k * 256 + n]);
        g_w1t_k[idx] = __float2bfloat16(Wk1[k * 256 + n]);
    }
}

// ---------------------------------------------------------------------------
// Kernel 1a: posemb + layer 1 (relu) -> g_h (bf16).
// Grid 768: CTAs [0,256) query rows (64 each), [256,768) memory rows.
// 256 threads = 8 warps as 2(row)x4(col); warp tile 32x64.
// ---------------------------------------------------------------------------
__global__ void __launch_bounds__(256, 2) mlp1_kernel(
    const float* __restrict__ q_coor, const float* __restrict__ mem_coor,
    const float* __restrict__ bq1, const float* __restrict__ bk1)
{
    extern __shared__ __nv_bfloat16 sm[];
    const int tid = threadIdx.x;
    const int w = tid >> 5, lane = tid & 31;
    const int wr = w >> 2, wc = w & 3;
    const int lr = lane >> 2, lc = lane & 3;

    const bool KV = blockIdx.x >= 256;
    const int lrow0 = (KV ? (blockIdx.x - 256) : blockIdx.x) * 64;  // local row
    const int grow0 = KV ? (NROW_Q + lrow0) : lrow0;                // g_h row
    const float* coor = KV ? mem_coor : q_coor;
    const __nv_bfloat16* w1t = KV ? g_w1t_k : g_w1t_q;
    const float* b1 = KV ? bk1 : bq1;

    // posemb -> A1 (64 rows x 128 cols)
    for (int p = tid; p < 64 * 64; p += 256) {
        int r = p >> 6, pp = p & 63;
        int half = pp >> 5, j = pp & 31;
        float coord = coor[2 * (lrow0 + r) + (half ? 0 : 1)];
        float freq = exp2f(-(float)j * 0.4152410118609203f);
        float v = coord * 6.283185307179586477f * freq;
        float sv, cv;
        sincosf(v, &sv, &cv);
        *(__nv_bfloat162*)(sm + M1_A + r * LDA + half * 64 + 2 * j) =
            __floats2bfloat162_rn(sv, cv);
    }
    // W1^T -> WB
    for (int p = tid; p < 256 * 16; p += 256) {
        int n = p >> 4, ch = p & 15;
        *(uint4*)(sm + M1_WB + n * LDB + ch * 8) = *(const uint4*)(w1t + n * 128 + ch * 8);
    }
    __syncthreads();

    float c1[2][8][4];
    #pragma unroll
    for (int mi = 0; mi < 2; ++mi)
        #pragma unroll
        for (int ni = 0; ni < 8; ++ni)
            #pragma unroll
            for (int q = 0; q < 4; ++q) c1[mi][ni][q] = 0.0f;

    #pragma unroll
    for (int ks = 0; ks < 8; ++ks) {
        const int k0 = ks * 16;
        uint32_t a[2][4], b[8][2];
        #pragma unroll
        for (int mi = 0; mi < 2; ++mi) {
            const __nv_bfloat16* ap = sm + M1_A + (wr * 32 + mi * 16 + lr) * LDA + k0 + lc * 2;
            a[mi][0] = *(const uint32_t*)ap;
            a[mi][1] = *(const uint32_t*)(ap + 8 * LDA);
            a[mi][2] = *(const uint32_t*)(ap + 8);
            a[mi][3] = *(const uint32_t*)(ap + 8 * LDA + 8);
        }
        #pragma unroll
        for (int ni = 0; ni < 8; ++ni) {
            const __nv_bfloat16* bp = sm + M1_WB + (wc * 64 + ni * 8 + lr) * LDB + k0 + lc * 2;
            b[ni][0] = *(const uint32_t*)bp;
            b[ni][1] = *(const uint32_t*)(bp + 8);
        }
        #pragma unroll
        for (int mi = 0; mi < 2; ++mi)
            #pragma unroll
            for (int ni = 0; ni < 8; ++ni)
                mma_bf16(c1[mi][ni], a[mi][0], a[mi][1], a[mi][2], a[mi][3],
                         b[ni][0], b[ni][1]);
    }

    // +b1, relu, bf16 -> g_h
    #pragma unroll
    for (int mi = 0; mi < 2; ++mi)
        #pragma unroll
        for (int ni = 0; ni < 8; ++ni) {
            int col = wc * 64 + ni * 8 + lc * 2;
            int row = grow0 + wr * 32 + mi * 16 + lr;
            float bl = __ldg(&b1[col]), bh = __ldg(&b1[col + 1]);
            float v0 = fmaxf(c1[mi][ni][0] + bl, 0.0f);
            float v1 = fmaxf(c1[mi][ni][1] + bh, 0.0f);
            float v2 = fmaxf(c1[mi][ni][2] + bl, 0.0f);
            float v3 = fmaxf(c1[mi][ni][3] + bh, 0.0f);
            *(__nv_bfloat162*)(g_h + (size_t)row * 256 + col) = __floats2bfloat162_rn(v0, v1);
            *(__nv_bfloat162*)(g_h + (size_t)(row + 8) * 256 + col) = __floats2bfloat162_rn(v2, v3);
        }
}

// ---------------------------------------------------------------------------
// Kernel 1b: layer 2: g_h @ W2^T + b2 (+memory for KV rows) -> g_q / g_kv.
// Grid 768 x 64-row tiles over all 49152 rows; K=256 in two 128-k chunks.
// ---------------------------------------------------------------------------
__global__ void __launch_bounds__(256, 2) mlp2_kernel(
    const float* __restrict__ bq2, const float* __restrict__ bk2,
    const float* __restrict__ memory)
{
    extern __shared__ __nv_bfloat16 sm[];
    const int tid = threadIdx.x;
    const int w = tid >> 5, lane = tid & 31;
    const int wr = w >> 2, wc = w & 3;
    const int lr = lane >> 2, lc = lane & 3;

    const int grow0 = blockIdx.x * 64;
    const bool KV = grow0 >= NROW_Q;
    const __nv_bfloat16* w2t = KV ? g_w2t_k : g_w2t_q;
    const float* b2 = KV ? bk2 : bq2;

    // h rows -> AH (64 x 256, LDH-padded)
    for (int p = tid; p < 64 * 32; p += 256) {
        int r = p >> 5, ch = p & 31;
        *(uint4*)(sm + M2_A + r * LDH + ch * 8) =
            *(const uint4*)(g_h + (size_t)(grow0 + r) * 256 + ch * 8);
    }

    float c2[2][8][4];
    #pragma unroll
    for (int mi = 0; mi < 2; ++mi)
        #pragma unroll
        for (int ni = 0; ni < 8; ++ni)
            #pragma unroll
            for (int q = 0; q < 4; ++q) c2[mi][ni][q] = 0.0f;

    #pragma unroll 1
    for (int chunk = 0; chunk < 2; ++chunk) {
        __syncthreads();   // AH ready (iter 0) / prior WB consumers done
        for (int p = tid; p < 256 * 16; p += 256) {
            int n = p >> 4, ch = p & 15;
            *(uint4*)(sm + M2_WB + n * LDB + ch * 8) =
                *(const uint4*)(w2t + n * 256 + chunk * 128 + ch * 8);
        }
        __syncthreads();
        #pragma unroll
        for (int ks = 0; ks < 8; ++ks) {
            const int kg = chunk * 128 + ks * 16;
            const int kl = ks * 16;
            uint32_t a[2][4], b[8][2];
            #pragma unroll
            for (int mi = 0; mi < 2; ++mi) {
                const __nv_bfloat16* ap = sm + M2_A + (wr * 32 + mi * 16 + lr) * LDH + kg + lc * 2;
                a[mi][0] = *(const uint32_t*)ap;
                a[mi][1] = *(const uint32_t*)(ap + 8 * LDH);
                a[mi][2] = *(const uint32_t*)(ap + 8);
                a[mi][3] = *(const uint32_t*)(ap + 8 * LDH + 8);
            }
            #pragma unroll
            for (int ni = 0; ni < 8; ++ni) {
                const __nv_bfloat16* bp = sm + M2_WB + (wc * 64 + ni * 8 + lr) * LDB + kl + lc * 2;
                b[ni][0] = *(const uint32_t*)bp;
                b[ni][1] = *(const uint32_t*)(bp + 8);
            }
            #pragma unroll
            for (int mi = 0; mi < 2; ++mi)
                #pragma unroll
                for (int ni = 0; ni < 8; ++ni)
                    mma_bf16(c2[mi][ni], a[mi][0], a[mi][1], a[mi][2], a[mi][3],
                             b[ni][0], b[ni][1]);
        }
    }

    // +b2 (+memory) -> fp32
    #pragma unroll
    for (int mi = 0; mi < 2; ++mi)
        #pragma unroll
        for (int ni = 0; ni < 8; ++ni) {
            int col = wc * 64 + ni * 8 + lc * 2;
            int g = grow0 + wr * 32 + mi * 16 + lr;
            float bl = __ldg(&b2[col]), bh = __ldg(&b2[col + 1]);
            float2 v0 = make_float2(c2[mi][ni][0] + bl, c2[mi][ni][1] + bh);
            float2 v1 = make_float2(c2[mi][ni][2] + bl, c2[mi][ni][3] + bh);
            if (KV) {
                size_t l0 = (size_t)(g - NROW_Q) * 256 + col;
                size_t l1 = (size_t)(g + 8 - NROW_Q) * 256 + col;
                float2 m0 = *(const float2*)(memory + l0);
                float2 m1 = *(const float2*)(memory + l1);
                v0.x += m0.x; v0.y += m0.y; v1.x += m1.x; v1.y += m1.y;
                *(float2*)(g_kv + l0) = v0;
                *(float2*)(g_kv + l1) = v1;
            } else {
                *(float2*)(g_q + (size_t)g * 256 + col) = v0;
                *(float2*)(g_q + (size_t)(g + 8) * 256 + col) = v1;
            }
        }
}

// ---------------------------------------------------------------------------
// Kernel 2: exact top-16 via warp-shared threshold (unchanged from R6 pass).
// ---------------------------------------------------------------------------
__global__ void __launch_bounds__(256, 2) topk_kernel(
    const float* __restrict__ q_coor, const float* __restrict__ mem_coor)
{
    extern __shared__ char smraw[];
    float2* sxy = (float2*)smraw;
    float*  sm2 = (float*)(smraw + LM * 8);
    unsigned long long* sbuf =
        (unsigned long long*)(smraw + LM * 8 + LM * 4);

    const int tid = threadIdx.x;
    const int b = blockIdx.y;
    const float2* mc = (const float2*)(mem_coor + (size_t)b * LM * 2);
    for (int i = tid; i < LM; i += 256) {
        float2 p = mc[i];
        sxy[i] = p;
        sm2[i] = __fadd_rn(__fmul_rn(p.x, p.x), __fmul_rn(p.y, p.y));
    }
    __syncthreads();

    const int wid = tid >> 5, lane = tid & 31;
    unsigned long long* buf = sbuf + wid * TK_BUFCAP;
    const int s = blockIdx.x * 8 + wid;
    const int qn = b * SQ + s;
    const float qx = q_coor[2 * qn], qy = q_coor[2 * qn + 1];
    const float q2 = __fadd_rn(__fmul_rn(qx, qx), __fmul_rn(qy, qy));

    const unsigned long long UMAX = 0xFFFFFFFFFFFFFFFFull;
    unsigned long long bestk = UMAX;
    float tau = __int_as_float(0x7f800000);
    int cnt = 0;

    auto consolidate = [&]() {
        unsigned long long k0 = (lane < cnt) ? buf[lane] : UMAX;
        unsigned long long k1 = (lane < 16 && lane + 32 < cnt) ? buf[lane + 32] : UMAX;
        unsigned long long k2 = bestk;
        unsigned long long nb = UMAX;
        #pragma unroll 1
        for (int r = 0; r < 16; ++r) {
            unsigned long long mk = k0;
            if (k1 < mk) mk = k1;
            if (k2 < mk) mk = k2;
            unsigned long long rk = mk; int rl = lane;
            #pragma unroll
            for (int off = 16; off; off >>= 1) {
                unsigned long long ok = __shfl_down_sync(0xffffffffu, rk, off);
                int ol = __shfl_down_sync(0xffffffffu, rl, off);
                if (ok < rk) { rk = ok; rl = ol; }
            }
            rk = __shfl_sync(0xffffffffu, rk, 0);
            rl = __shfl_sync(0xffffffffu, rl, 0);
            if (lane == r) nb = rk;
            if (lane == rl) {
                if (k0 == rk) k0 = UMAX;
                else if (k1 == rk) k1 = UMAX;
                else k2 = UMAX;
            }
        }
        bestk = nb;
        unsigned long long k15 = __shfl_sync(0xffffffffu, bestk, 15);
        tau = ord2f((uint32_t)(k15 >> 32));
        cnt = 0;
    };

    for (int t = 0; t < LM / 128; ++t) {
        const int c0 = t * 128 + lane;
        #pragma unroll
        for (int m = 0; m < 4; ++m) {
            const int c = c0 + m * 32;
            float2 pm = sxy[c];
            float m2 = sm2[c];
            float dt = __fmaf_rn(qy, pm.y, __fmul_rn(qx, pm.x));
            float d2 = __fsub_rn(__fadd_rn(q2, m2), __fmul_rn(2.0f, dt));
            bool acc = d2 < tau;
            unsigned mask = __ballot_sync(0xffffffffu, acc);
            if (mask) {
                int nacc = __popc(mask);
                if (cnt + nacc > TK_BUFCAP) {
                    consolidate();
                    acc = d2 < tau;
                    mask = __ballot_sync(0xffffffffu, acc);
                    nacc = __popc(mask);
                }
                if (acc) {
                    int pos = cnt + __popc(mask & ((1u << lane) - 1u));
                    buf[pos] = ((unsigned long long)f2ord(d2) << 32) | (uint32_t)c;
                }
                cnt += nacc;
            }
        }
    }
    if (cnt > 0) consolidate();

    if (lane < 16) g_idx[qn * 16 + lane] = (int)(uint32_t)bestk;
}

// ---------------------------------------------------------------------------
// Kernel 3: gather + softmax over D + multiply.
// Block 128 thr = 4 warps; warp w handles neighbors w*4..w*4+3 sequentially
// (q loaded once per warp -> 4x less redundant q traffic than warp-per-nbr).
// ---------------------------------------------------------------------------
__global__ void __launch_bounds__(128, 1) attn_kernel(
    const float* __restrict__ memory, float* __restrict__ out)
{
    const int s = blockIdx.x, b = blockIdx.y;
    const int qn = b * SQ + s;
    const int w = threadIdx.x >> 5, lane = threadIdx.x & 31;

    const float4* qp = (const float4*)(g_q + (size_t)qn * 256);
    const float4 q0 = qp[lane * 2], q1 = qp[lane * 2 + 1];

    #pragma unroll
    for (int jj = 0; jj < 4; ++jj) {
        const int j = w * 4 + jj;
        const int idx = __ldg(&g_idx[qn * 16 + j]);

        const float4* kvp = (const float4*)(g_kv + ((size_t)b * LM + idx) * 256);
        float4 k0 = kvp[lane * 2], k1 = kvp[lane * 2 + 1];

        float p[8];
        p[0] = q0.x * k0.x; p[1] = q0.y * k0.y; p[2] = q0.z * k0.z; p[3] = q0.w * k0.w;
        p[4] = q1.x * k1.x; p[5] = q1.y * k1.y; p[6] = q1.z * k1.z; p[7] = q1.w * k1.w;
        #pragma unroll
        for (int i = 0; i < 8; ++i) p[i] *= 0.0625f;

        float mx = p[0];
        #pragma unroll
        for (int i = 1; i < 8; ++i) mx = fmaxf(mx, p[i]);
        #pragma unroll
        for (int off = 16; off; off >>= 1)
            mx = fmaxf(mx, __shfl_xor_sync(0xffffffffu, mx, off));

        float sum = 0.0f;
        #pragma unroll
        for (int i = 0; i < 8; ++i) { p[i] = __expf(p[i] - mx); sum += p[i]; }
        #pragma unroll
        for (int off = 16; off; off >>= 1)
            sum += __shfl_xor_sync(0xffffffffu, sum, off);
        const float inv = __frcp_rn(sum);

        const float4* mp = (const float4*)(memory + ((size_t)b * LM + idx) * 256);
        float4 m0 = mp[lane * 2], m1 = mp[lane * 2 + 1];

        float4 r0, r1;
        r0.x = p[0] * inv * m0.x; r0.y = p[1] * inv * m0.y;
        r0.z = p[2] * inv * m0.z; r0.w = p[3] * inv * m0.w;
        r1.x = p[4] * inv * m1.x; r1.y = p[5] * inv * m1.y;
        r1.z = p[6] * inv * m1.z; r1.w = p[7] * inv * m1.w;

        float4* op = (float4*)(out + ((size_t)(qn * 16 + j)) * 256);
        op[lane * 2]     = r0;
        op[lane * 2 + 1] = r1;
    }
}

// ---------------------------------------------------------------------------

extern "C" void kernel_launch(void* const* d_in, const int* in_sizes, int n_in,
                              void* d_out, int out_size)
{
    const float* memory   = (const float*)d_in[0];
    const float* mem_coor = (const float*)d_in[1];
    const float* q_coor   = (const float*)d_in[2];
    const float* Wq1 = (const float*)d_in[3];
    const float* bq1 = (const float*)d_in[4];
    const float* Wq2 = (const float*)d_in[5];
    const float* bq2 = (const float*)d_in[6];
    const float* Wk1 = (const float*)d_in[7];
    const float* bk1 = (const float*)d_in[8];
    const float* Wk2 = (const float*)d_in[9];
    const float* bk2 = (const float*)d_in[10];
    float* out = (float*)d_out;

    cudaFuncSetAttribute(mlp1_kernel,
        cudaFuncAttributeMaxDynamicSharedMemorySize, SMEM_MLP1);
    cudaFuncSetAttribute(mlp2_kernel,
        cudaFuncAttributeMaxDynamicSharedMemorySize, SMEM_MLP2);
    cudaFuncSetAttribute(topk_kernel,
        cudaFuncAttributeMaxDynamicSharedMemorySize, SMEM_TOPK);

    // K0: weight transpose + bf16
    prep_weights<<<256, 256>>>(Wq1, Wq2, Wk1, Wk2);

    // K1a: posemb + layer1 -> g_h  (256 query CTAs + 512 KV CTAs)
    mlp1_kernel<<<768, 256, SMEM_MLP1>>>(q_coor, mem_coor, bq1, bk1);

    // K1b: layer2 -> g_q / g_kv
    mlp2_kernel<<<NROW_T / 64, 256, SMEM_MLP2>>>(bq2, bk2, memory);

    // K2: top-16 neighbors (threshold-gated, buffered)
    topk_kernel<<<dim3(SQ / 8, BQ), 256, SMEM_TOPK>>>(q_coor, mem_coor);

    // K3: gather + softmax(D) + multiply
    attn_kernel<<<dim3(SQ, BQ), 128>>>(memory, out);
}

// round 8
// speedup vs baseline: 2.1405x; 1.0655x over previous
#include <cuda_runtime.h>
#include <cuda_bf16.h>
#include <cstdint>

#define BQ  4
#define SQ  4096
#define LM  8192
#define DD  256
#define KNN 16
#define NROW_Q (BQ*SQ)          /* 16384 */
#define NROW_T (BQ*(SQ+LM))     /* 49152 total MLP rows */

// Scratch (device globals: allocation-free, graph-capture safe)
__device__ __align__(16) float g_q [BQ*SQ*DD];         // 16 MB
__device__ __align__(16) float g_kv[(size_t)BQ*LM*DD]; // 32 MB
__device__ int   g_idx[BQ*SQ*KNN];                     // 1 MB
__device__ __align__(16) __nv_bfloat16 g_h[(size_t)NROW_T*DD];  // 24 MB hidden
// bf16 transposed weights: w1t[n*128+k] = W1[k][n]; w2t[n*256+k] = W2[k][n]
__device__ __align__(16) __nv_bfloat16 g_w1t_q[256*128];
__device__ __align__(16) __nv_bfloat16 g_w2t_q[256*256];
__device__ __align__(16) __nv_bfloat16 g_w1t_k[256*128];
__device__ __align__(16) __nv_bfloat16 g_w2t_k[256*256];

// ---------------------------------------------------------------------------
// smem layouts (bf16 elements; padded rows -> conflict-free fragment LDS)
// ---------------------------------------------------------------------------
#define LDA 136
#define LDB 136
#define LDH 264
#define M1_A  0
#define M1_WB (64 * LDA)
#define SMEM_MLP1 ((M1_WB + 256 * LDB) * 2)
#define M2_A  0
#define M2_WB (64 * LDH)
#define SMEM_MLP2 ((M2_WB + 256 * LDB) * 2)

// topk smem: float2 xy[8192] (64K) + u64 buf[8][48] (3K)  -> 3 CTA/SM
#define TK_BUFCAP 48
#define SMEM_TOPK (LM * 8 + 8 * TK_BUFCAP * 8)

// bf16 mma.sync m16n8k16 (sm_80+ HMMA; legal at compute_103 base target)
__device__ __forceinline__ void mma_bf16(float c[4],
    uint32_t a0, uint32_t a1, uint32_t a2, uint32_t a3,
    uint32_t b0, uint32_t b1)
{
    asm volatile(
        "mma.sync.aligned.m16n8k16.row.col.f32.bf16.bf16.f32 "
        "{%0,%1,%2,%3}, {%4,%5,%6,%7}, {%8,%9}, {%0,%1,%2,%3};"
        : "+f"(c[0]), "+f"(c[1]), "+f"(c[2]), "+f"(c[3])
        : "r"(a0), "r"(a1), "r"(a2), "r"(a3), "r"(b0), "r"(b1));
}

// orderable-float transforms (total order matching float <)
__device__ __forceinline__ uint32_t f2ord(float f) {
    uint32_t u = __float_as_uint(f);
    return u ^ ((uint32_t)((int)u >> 31) | 0x80000000u);
}
__device__ __forceinline__ float ord2f(uint32_t o) {
    uint32_t u = o ^ ((uint32_t)((int)(~o) >> 31) | 0x80000000u);
    return __uint_as_float(u);
}

// ---------------------------------------------------------------------------
// Kernel 0: weight prep — transpose + bf16-convert both weight sets.
// ---------------------------------------------------------------------------
__global__ void prep_weights(const float* __restrict__ Wq1, const float* __restrict__ Wq2,
                             const float* __restrict__ Wk1, const float* __restrict__ Wk2)
{
    int idx = blockIdx.x * 256 + threadIdx.x;  // 65536 total
    {
        int n = idx >> 8, k = idx & 255;
        g_w2t_q[idx] = __float2bfloat16(Wq2[k * 256 + n]);
        g_w2t_k[idx] = __float2bfloat16(Wk2[k * 256 + n]);
    }
    if (idx < 32768) {
        int n = idx >> 7, k = idx & 127;
        g_w1t_q[idx] = __float2bfloat16(Wq1[k * 256 + n]);
        g_w1t_k[idx] = __float2bfloat16(Wk1[k * 256 + n]);
    }
}

// ---------------------------------------------------------------------------
// Kernel 1a: posemb + layer 1 (relu) -> g_h (bf16).  (unchanged, R7 pass)
// ---------------------------------------------------------------------------
__global__ void __launch_bounds__(256, 2) mlp1_kernel(
    const float* __restrict__ q_coor, const float* __restrict__ mem_coor,
    const float* __restrict__ bq1, const float* __restrict__ bk1)
{
    extern __shared__ __nv_bfloat16 sm[];
    const int tid = threadIdx.x;
    const int w = tid >> 5, lane = tid & 31;
    const int wr = w >> 2, wc = w & 3;
    const int lr = lane >> 2, lc = lane & 3;

    const bool KV = blockIdx.x >= 256;
    const int lrow0 = (KV ? (blockIdx.x - 256) : blockIdx.x) * 64;
    const int grow0 = KV ? (NROW_Q + lrow0) : lrow0;
    const float* coor = KV ? mem_coor : q_coor;
    const __nv_bfloat16* w1t = KV ? g_w1t_k : g_w1t_q;
    const float* b1 = KV ? bk1 : bq1;

    for (int p = tid; p < 64 * 64; p += 256) {
        int r = p >> 6, pp = p & 63;
        int half = pp >> 5, j = pp & 31;
        float coord = coor[2 * (lrow0 + r) + (half ? 0 : 1)];
        float freq = exp2f(-(float)j * 0.4152410118609203f);
        float v = coord * 6.283185307179586477f * freq;
        float sv, cv;
        sincosf(v, &sv, &cv);
        *(__nv_bfloat162*)(sm + M1_A + r * LDA + half * 64 + 2 * j) =
            __floats2bfloat162_rn(sv, cv);
    }
    for (int p = tid; p < 256 * 16; p += 256) {
        int n = p >> 4, ch = p & 15;
        *(uint4*)(sm + M1_WB + n * LDB + ch * 8) = *(const uint4*)(w1t + n * 128 + ch * 8);
    }
    __syncthreads();

    float c1[2][8][4];
    #pragma unroll
    for (int mi = 0; mi < 2; ++mi)
        #pragma unroll
        for (int ni = 0; ni < 8; ++ni)
            #pragma unroll
            for (int q = 0; q < 4; ++q) c1[mi][ni][q] = 0.0f;

    #pragma unroll
    for (int ks = 0; ks < 8; ++ks) {
        const int k0 = ks * 16;
        uint32_t a[2][4], b[8][2];
        #pragma unroll
        for (int mi = 0; mi < 2; ++mi) {
            const __nv_bfloat16* ap = sm + M1_A + (wr * 32 + mi * 16 + lr) * LDA + k0 + lc * 2;
            a[mi][0] = *(const uint32_t*)ap;
            a[mi][1] = *(const uint32_t*)(ap + 8 * LDA);
            a[mi][2] = *(const uint32_t*)(ap + 8);
            a[mi][3] = *(const uint32_t*)(ap + 8 * LDA + 8);
        }
        #pragma unroll
        for (int ni = 0; ni < 8; ++ni) {
            const __nv_bfloat16* bp = sm + M1_WB + (wc * 64 + ni * 8 + lr) * LDB + k0 + lc * 2;
            b[ni][0] = *(const uint32_t*)bp;
            b[ni][1] = *(const uint32_t*)(bp + 8);
        }
        #pragma unroll
        for (int mi = 0; mi < 2; ++mi)
            #pragma unroll
            for (int ni = 0; ni < 8; ++ni)
                mma_bf16(c1[mi][ni], a[mi][0], a[mi][1], a[mi][2], a[mi][3],
                         b[ni][0], b[ni][1]);
    }

    #pragma unroll
    for (int mi = 0; mi < 2; ++mi)
        #pragma unroll
        for (int ni = 0; ni < 8; ++ni) {
            int col = wc * 64 + ni * 8 + lc * 2;
            int row = grow0 + wr * 32 + mi * 16 + lr;
            float bl = __ldg(&b1[col]), bh = __ldg(&b1[col + 1]);
            float v0 = fmaxf(c1[mi][ni][0] + bl, 0.0f);
            float v1 = fmaxf(c1[mi][ni][1] + bh, 0.0f);
            float v2 = fmaxf(c1[mi][ni][2] + bl, 0.0f);
            float v3 = fmaxf(c1[mi][ni][3] + bh, 0.0f);
            *(__nv_bfloat162*)(g_h + (size_t)row * 256 + col) = __floats2bfloat162_rn(v0, v1);
            *(__nv_bfloat162*)(g_h + (size_t)(row + 8) * 256 + col) = __floats2bfloat162_rn(v2, v3);
        }
}

// ---------------------------------------------------------------------------
// Kernel 1b: layer 2 (unchanged, R7 pass).
// ---------------------------------------------------------------------------
__global__ void __launch_bounds__(256, 2) mlp2_kernel(
    const float* __restrict__ bq2, const float* __restrict__ bk2,
    const float* __restrict__ memory)
{
    extern __shared__ __nv_bfloat16 sm[];
    const int tid = threadIdx.x;
    const int w = tid >> 5, lane = tid & 31;
    const int wr = w >> 2, wc = w & 3;
    const int lr = lane >> 2, lc = lane & 3;

    const int grow0 = blockIdx.x * 64;
    const bool KV = grow0 >= NROW_Q;
    const __nv_bfloat16* w2t = KV ? g_w2t_k : g_w2t_q;
    const float* b2 = KV ? bk2 : bq2;

    for (int p = tid; p < 64 * 32; p += 256) {
        int r = p >> 5, ch = p & 31;
        *(uint4*)(sm + M2_A + r * LDH + ch * 8) =
            *(const uint4*)(g_h + (size_t)(grow0 + r) * 256 + ch * 8);
    }

    float c2[2][8][4];
    #pragma unroll
    for (int mi = 0; mi < 2; ++mi)
        #pragma unroll
        for (int ni = 0; ni < 8; ++ni)
            #pragma unroll
            for (int q = 0; q < 4; ++q) c2[mi][ni][q] = 0.0f;

    #pragma unroll 1
    for (int chunk = 0; chunk < 2; ++chunk) {
        __syncthreads();
        for (int p = tid; p < 256 * 16; p += 256) {
            int n = p >> 4, ch = p & 15;
            *(uint4*)(sm + M2_WB + n * LDB + ch * 8) =
                *(const uint4*)(w2t + n * 256 + chunk * 128 + ch * 8);
        }
        __syncthreads();
        #pragma unroll
        for (int ks = 0; ks < 8; ++ks) {
            const int kg = chunk * 128 + ks * 16;
            const int kl = ks * 16;
            uint32_t a[2][4], b[8][2];
            #pragma unroll
            for (int mi = 0; mi < 2; ++mi) {
                const __nv_bfloat16* ap = sm + M2_A + (wr * 32 + mi * 16 + lr) * LDH + kg + lc * 2;
                a[mi][0] = *(const uint32_t*)ap;
                a[mi][1] = *(const uint32_t*)(ap + 8 * LDH);
                a[mi][2] = *(const uint32_t*)(ap + 8);
                a[mi][3] = *(const uint32_t*)(ap + 8 * LDH + 8);
            }
            #pragma unroll
            for (int ni = 0; ni < 8; ++ni) {
                const __nv_bfloat16* bp = sm + M2_WB + (wc * 64 + ni * 8 + lr) * LDB + kl + lc * 2;
                b[ni][0] = *(const uint32_t*)bp;
                b[ni][1] = *(const uint32_t*)(bp + 8);
            }
            #pragma unroll
            for (int mi = 0; mi < 2; ++mi)
                #pragma unroll
                for (int ni = 0; ni < 8; ++ni)
                    mma_bf16(c2[mi][ni], a[mi][0], a[mi][1], a[mi][2], a[mi][3],
                             b[ni][0], b[ni][1]);
        }
    }

    #pragma unroll
    for (int mi = 0; mi < 2; ++mi)
        #pragma unroll
        for (int ni = 0; ni < 8; ++ni) {
            int col = wc * 64 + ni * 8 + lc * 2;
            int g = grow0 + wr * 32 + mi * 16 + lr;
            float bl = __ldg(&b2[col]), bh = __ldg(&b2[col + 1]);
            float2 v0 = make_float2(c2[mi][ni][0] + bl, c2[mi][ni][1] + bh);
            float2 v1 = make_float2(c2[mi][ni][2] + bl, c2[mi][ni][3] + bh);
            if (KV) {
                size_t l0 = (size_t)(g - NROW_Q) * 256 + col;
                size_t l1 = (size_t)(g + 8 - NROW_Q) * 256 + col;
                float2 m0 = *(const float2*)(memory + l0);
                float2 m1 = *(const float2*)(memory + l1);
                v0.x += m0.x; v0.y += m0.y; v1.x += m1.x; v1.y += m1.y;
                *(float2*)(g_kv + l0) = v0;
                *(float2*)(g_kv + l1) = v1;
            } else {
                *(float2*)(g_q + (size_t)g * 256 + col) = v0;
                *(float2*)(g_q + (size_t)(g + 8) * 256 + col) = v1;
            }
        }
}

// ---------------------------------------------------------------------------
// Kernel 2: exact top-16, threshold-gated.
// Lane owns 4 CONSECUTIVE candidates (2x LDS.128); ONE ballot per 128-tile on
// (min4 < tau); slow path only on tiles with accepts. m2 recomputed inline
// (identical rounding to stored version). 3 CTA/SM (67KB smem).
// ---------------------------------------------------------------------------
__global__ void __launch_bounds__(256, 3) topk_kernel(
    const float* __restrict__ q_coor, const float* __restrict__ mem_coor)
{
    extern __shared__ char smraw[];
    float2* sxy = (float2*)smraw;                              // 64 KB
    unsigned long long* sbuf = (unsigned long long*)(smraw + LM * 8);

    const int tid = threadIdx.x;
    const int b = blockIdx.y;
    const float2* mc = (const float2*)(mem_coor + (size_t)b * LM * 2);
    for (int i = tid; i < LM; i += 256) sxy[i] = mc[i];
    __syncthreads();

    const int wid = tid >> 5, lane = tid & 31;
    unsigned long long* buf = sbuf + wid * TK_BUFCAP;
    const int s = blockIdx.x * 8 + wid;
    const int qn = b * SQ + s;
    const float qx = q_coor[2 * qn], qy = q_coor[2 * qn + 1];
    const float q2 = __fadd_rn(__fmul_rn(qx, qx), __fmul_rn(qy, qy));

    const unsigned long long UMAX = 0xFFFFFFFFFFFFFFFFull;
    unsigned long long bestk = UMAX;
    float tau = __int_as_float(0x7f800000);
    int cnt = 0;

    auto consolidate = [&]() {
        unsigned long long k0 = (lane < cnt) ? buf[lane] : UMAX;
        unsigned long long k1 = (lane < 16 && lane + 32 < cnt) ? buf[lane + 32] : UMAX;
        unsigned long long k2 = bestk;
        unsigned long long nb = UMAX;
        #pragma unroll 1
        for (int r = 0; r < 16; ++r) {
            unsigned long long mk = k0;
            if (k1 < mk) mk = k1;
            if (k2 < mk) mk = k2;
            unsigned long long rk = mk; int rl = lane;
            #pragma unroll
            for (int off = 16; off; off >>= 1) {
                unsigned long long ok = __shfl_down_sync(0xffffffffu, rk, off);
                int ol = __shfl_down_sync(0xffffffffu, rl, off);
                if (ok < rk) { rk = ok; rl = ol; }
            }
            rk = __shfl_sync(0xffffffffu, rk, 0);
            rl = __shfl_sync(0xffffffffu, rl, 0);
            if (lane == r) nb = rk;
            if (lane == rl) {
                if (k0 == rk) k0 = UMAX;
                else if (k1 == rk) k1 = UMAX;
                else k2 = UMAX;
            }
        }
        bestk = nb;
        unsigned long long k15 = __shfl_sync(0xffffffffu, bestk, 15);
        tau = ord2f((uint32_t)(k15 >> 32));
        cnt = 0;
    };

    #pragma unroll 1
    for (int t = 0; t < LM / 128; ++t) {
        const int c0 = t * 128 + lane * 4;
        float4 u = *(const float4*)(sxy + c0);       // cands c0, c0+1
        float4 v = *(const float4*)(sxy + c0 + 2);   // cands c0+2, c0+3
        float d2[4];
        {
            float m2, dt;
            m2 = __fadd_rn(__fmul_rn(u.x, u.x), __fmul_rn(u.y, u.y));
            dt = __fmaf_rn(qy, u.y, __fmul_rn(qx, u.x));
            d2[0] = __fsub_rn(__fadd_rn(q2, m2), __fmul_rn(2.0f, dt));
            m2 = __fadd_rn(__fmul_rn(u.z, u.z), __fmul_rn(u.w, u.w));
            dt = __fmaf_rn(qy, u.w, __fmul_rn(qx, u.z));
            d2[1] = __fsub_rn(__fadd_rn(q2, m2), __fmul_rn(2.0f, dt));
            m2 = __fadd_rn(__fmul_rn(v.x, v.x), __fmul_rn(v.y, v.y));
            dt = __fmaf_rn(qy, v.y, __fmul_rn(qx, v.x));
            d2[2] = __fsub_rn(__fadd_rn(q2, m2), __fmul_rn(2.0f, dt));
            m2 = __fadd_rn(__fmul_rn(v.z, v.z), __fmul_rn(v.w, v.w));
            dt = __fmaf_rn(qy, v.w, __fmul_rn(qx, v.z));
            d2[3] = __fsub_rn(__fadd_rn(q2, m2), __fmul_rn(2.0f, dt));
        }
        float mn = fminf(fminf(d2[0], d2[1]), fminf(d2[2], d2[3]));
        if (!__ballot_sync(0xffffffffu, mn < tau)) continue;

        // slow path: per-candidate append with overflow consolidation
        #pragma unroll
        for (int m = 0; m < 4; ++m) {
            bool acc = d2[m] < tau;
            unsigned mask = __ballot_sync(0xffffffffu, acc);
            if (!mask) continue;
            int nacc = __popc(mask);
            if (cnt + nacc > TK_BUFCAP) {
                consolidate();
                acc = d2[m] < tau;
                mask = __ballot_sync(0xffffffffu, acc);
                nacc = __popc(mask);
            }
            if (acc) {
                int pos = cnt + __popc(mask & ((1u << lane) - 1u));
                buf[pos] = ((unsigned long long)f2ord(d2[m]) << 32) | (uint32_t)(c0 + m);
            }
            cnt += nacc;
        }
    }
    if (cnt > 0) consolidate();

    if (lane < 16) g_idx[qn * 16 + lane] = (int)(uint32_t)bestk;
}

// ---------------------------------------------------------------------------
// Kernel 3: gather + softmax over D + multiply (unchanged, R7 pass).
// ---------------------------------------------------------------------------
__global__ void __launch_bounds__(128, 1) attn_kernel(
    const float* __restrict__ memory, float* __restrict__ out)
{
    const int s = blockIdx.x, b = blockIdx.y;
    const int qn = b * SQ + s;
    const int w = threadIdx.x >> 5, lane = threadIdx.x & 31;

    const float4* qp = (const float4*)(g_q + (size_t)qn * 256);
    const float4 q0 = qp[lane * 2], q1 = qp[lane * 2 + 1];

    #pragma unroll
    for (int jj = 0; jj < 4; ++jj) {
        const int j = w * 4 + jj;
        const int idx = __ldg(&g_idx[qn * 16 + j]);

        const float4* kvp = (const float4*)(g_kv + ((size_t)b * LM + idx) * 256);
        float4 k0 = kvp[lane * 2], k1 = kvp[lane * 2 + 1];

        float p[8];
        p[0] = q0.x * k0.x; p[1] = q0.y * k0.y; p[2] = q0.z * k0.z; p[3] = q0.w * k0.w;
        p[4] = q1.x * k1.x; p[5] = q1.y * k1.y; p[6] = q1.z * k1.z; p[7] = q1.w * k1.w;
        #pragma unroll
        for (int i = 0; i < 8; ++i) p[i] *= 0.0625f;

        float mx = p[0];
        #pragma unroll
        for (int i = 1; i < 8; ++i) mx = fmaxf(mx, p[i]);
        #pragma unroll
        for (int off = 16; off; off >>= 1)
            mx = fmaxf(mx, __shfl_xor_sync(0xffffffffu, mx, off));

        float sum = 0.0f;
        #pragma unroll
        for (int i = 0; i < 8; ++i) { p[i] = __expf(p[i] - mx); sum += p[i]; }
        #pragma unroll
        for (int off = 16; off; off >>= 1)
            sum += __shfl_xor_sync(0xffffffffu, sum, off);
        const float inv = __frcp_rn(sum);

        const float4* mp = (const float4*)(memory + ((size_t)b * LM + idx) * 256);
        float4 m0 = mp[lane * 2], m1 = mp[lane * 2 + 1];

        float4 r0, r1;
        r0.x = p[0] * inv * m0.x; r0.y = p[1] * inv * m0.y;
        r0.z = p[2] * inv * m0.z; r0.w = p[3] * inv * m0.w;
        r1.x = p[4] * inv * m1.x; r1.y = p[5] * inv * m1.y;
        r1.z = p[6] * inv * m1.z; r1.w = p[7] * inv * m1.w;

        float4* op = (float4*)(out + ((size_t)(qn * 16 + j)) * 256);
        op[lane * 2]     = r0;
        op[lane * 2 + 1] = r1;
    }
}

// ---------------------------------------------------------------------------

extern "C" void kernel_launch(void* const* d_in, const int* in_sizes, int n_in,
                              void* d_out, int out_size)
{
    const float* memory   = (const float*)d_in[0];
    const float* mem_coor = (const float*)d_in[1];
    const float* q_coor   = (const float*)d_in[2];
    const float* Wq1 = (const float*)d_in[3];
    const float* bq1 = (const float*)d_in[4];
    const float* Wq2 = (const float*)d_in[5];
    const float* bq2 = (const float*)d_in[6];
    const float* Wk1 = (const float*)d_in[7];
    const float* bk1 = (const float*)d_in[8];
    const float* Wk2 = (const float*)d_in[9];
    const float* bk2 = (const float*)d_in[10];
    float* out = (float*)d_out;

    cudaFuncSetAttribute(mlp1_kernel,
        cudaFuncAttributeMaxDynamicSharedMemorySize, SMEM_MLP1);
    cudaFuncSetAttribute(mlp2_kernel,
        cudaFuncAttributeMaxDynamicSharedMemorySize, SMEM_MLP2);
    cudaFuncSetAttribute(topk_kernel,
        cudaFuncAttributeMaxDynamicSharedMemorySize, SMEM_TOPK);

    // K0: weight transpose + bf16
    prep_weights<<<256, 256>>>(Wq1, Wq2, Wk1, Wk2);

    // K1a: posemb + layer1 -> g_h
    mlp1_kernel<<<768, 256, SMEM_MLP1>>>(q_coor, mem_coor, bq1, bk1);

    // K1b: layer2 -> g_q / g_kv
    mlp2_kernel<<<NROW_T / 64, 256, SMEM_MLP2>>>(bq2, bk2, memory);

    // K2: top-16 neighbors (tile-gated threshold scan)
    topk_kernel<<<dim3(SQ / 8, BQ), 256, SMEM_TOPK>>>(q_coor, mem_coor);

    // K3: gather + softmax(D) + multiply
    attn_kernel<<<dim3(SQ, BQ), 128>>>(memory, out);
}

// round 9
// speedup vs baseline: 4.2777x; 1.9984x over previous
#include <cuda_runtime.h>
#include <cuda_bf16.h>
#include <cstdint>

#define BQ  4
#define SQ  4096
#define LM  8192
#define DD  256
#define KNN 16
#define NROW_Q (BQ*SQ)          /* 16384 */
#define NROW_T (BQ*(SQ+LM))     /* 49152 total MLP rows */

// Scratch (device globals: allocation-free, graph-capture safe)
__device__ __align__(16) float g_q [BQ*SQ*DD];         // 16 MB
__device__ __align__(16) float g_kv[(size_t)BQ*LM*DD]; // 32 MB
__device__ int   g_idx[BQ*SQ*KNN];                     // 1 MB
__device__ __align__(16) __nv_bfloat16 g_h[(size_t)NROW_T*DD];  // 24 MB hidden
// bf16 transposed weights
__device__ __align__(16) __nv_bfloat16 g_w1t_q[256*128];
__device__ __align__(16) __nv_bfloat16 g_w2t_q[256*256];
__device__ __align__(16) __nv_bfloat16 g_w1t_k[256*128];
__device__ __align__(16) __nv_bfloat16 g_w2t_k[256*256];
// spatial grid (32x32 cells per batch)
#define GC 32
#define GCELLS (GC*GC)
#define GH 0.03125f
__device__ int g_cellstart[BQ][GCELLS + 1];
__device__ __align__(16) float4 g_spt[BQ][LM];   // sorted {x, y, bits(idx), 0}

// ---------------------------------------------------------------------------
#define LDA 136
#define LDB 136
#define LDH 264
#define M1_A  0
#define M1_WB (64 * LDA)
#define SMEM_MLP1 ((M1_WB + 256 * LDB) * 2)
#define M2_A  0
#define M2_WB (64 * LDH)
#define SMEM_MLP2 ((M2_WB + 256 * LDB) * 2)

__device__ __forceinline__ void mma_bf16(float c[4],
    uint32_t a0, uint32_t a1, uint32_t a2, uint32_t a3,
    uint32_t b0, uint32_t b1)
{
    asm volatile(
        "mma.sync.aligned.m16n8k16.row.col.f32.bf16.bf16.f32 "
        "{%0,%1,%2,%3}, {%4,%5,%6,%7}, {%8,%9}, {%0,%1,%2,%3};"
        : "+f"(c[0]), "+f"(c[1]), "+f"(c[2]), "+f"(c[3])
        : "r"(a0), "r"(a1), "r"(a2), "r"(a3), "r"(b0), "r"(b1));
}

__device__ __forceinline__ uint32_t f2ord(float f) {
    uint32_t u = __float_as_uint(f);
    return u ^ ((uint32_t)((int)u >> 31) | 0x80000000u);
}
__device__ __forceinline__ float ord2f(uint32_t o) {
    uint32_t u = o ^ ((uint32_t)((int)(~o) >> 31) | 0x80000000u);
    return __uint_as_float(u);
}

// ---------------------------------------------------------------------------
// Kernel 0: weight prep (unchanged, R8 pass)
// ---------------------------------------------------------------------------
__global__ void prep_weights(const float* __restrict__ Wq1, const float* __restrict__ Wq2,
                             const float* __restrict__ Wk1, const float* __restrict__ Wk2)
{
    int idx = blockIdx.x * 256 + threadIdx.x;
    {
        int n = idx >> 8, k = idx & 255;
        g_w2t_q[idx] = __float2bfloat16(Wq2[k * 256 + n]);
        g_w2t_k[idx] = __float2bfloat16(Wk2[k * 256 + n]);
    }
    if (idx < 32768) {
        int n = idx >> 7, k = idx & 127;
        g_w1t_q[idx] = __float2bfloat16(Wq1[k * 256 + n]);
        g_w1t_k[idx] = __float2bfloat16(Wk1[k * 256 + n]);
    }
}

// ---------------------------------------------------------------------------
// Kernel 0b: spatial grid build. One block per batch, 1024 threads.
// ---------------------------------------------------------------------------
__global__ void __launch_bounds__(1024, 1) grid_build(const float* __restrict__ mem_coor)
{
    __shared__ int hist[GCELLS];
    __shared__ int scn[GCELLS];
    const int b = blockIdx.x, tid = threadIdx.x;
    hist[tid] = 0;
    __syncthreads();

    const float2* mc = (const float2*)(mem_coor + (size_t)b * LM * 2);
    int cellid[8]; float2 pt[8];
    #pragma unroll
    for (int i = 0; i < 8; ++i) {
        int p = tid + i * 1024;
        float2 c = mc[p];
        int cx = min(GC - 1, (int)(c.x * (float)GC));
        int cy = min(GC - 1, (int)(c.y * (float)GC));
        cellid[i] = cy * GC + cx; pt[i] = c;
        atomicAdd(&hist[cellid[i]], 1);
    }
    __syncthreads();

    int v = hist[tid];
    scn[tid] = v;
    __syncthreads();
    for (int off = 1; off < GCELLS; off <<= 1) {
        int t = (tid >= off) ? scn[tid - off] : 0;
        __syncthreads();
        scn[tid] += t;
        __syncthreads();
    }
    int excl = scn[tid] - v;
    g_cellstart[b][tid] = excl;
    if (tid == GCELLS - 1) g_cellstart[b][GCELLS] = LM;
    hist[tid] = excl;    // running scatter offsets
    __syncthreads();

    #pragma unroll
    for (int i = 0; i < 8; ++i) {
        int p = tid + i * 1024;
        int pos = atomicAdd(&hist[cellid[i]], 1);
        g_spt[b][pos] = make_float4(pt[i].x, pt[i].y, __int_as_float(p), 0.0f);
    }
}

// ---------------------------------------------------------------------------
// Kernel 1a: posemb + layer 1 (unchanged, R8 pass)
// ---------------------------------------------------------------------------
__global__ void __launch_bounds__(256, 2) mlp1_kernel(
    const float* __restrict__ q_coor, const float* __restrict__ mem_coor,
    const float* __restrict__ bq1, const float* __restrict__ bk1)
{
    extern __shared__ __nv_bfloat16 sm[];
    const int tid = threadIdx.x;
    const int w = tid >> 5, lane = tid & 31;
    const int wr = w >> 2, wc = w & 3;
    const int lr = lane >> 2, lc = lane & 3;

    const bool KV = blockIdx.x >= 256;
    const int lrow0 = (KV ? (blockIdx.x - 256) : blockIdx.x) * 64;
    const int grow0 = KV ? (NROW_Q + lrow0) : lrow0;
    const float* coor = KV ? mem_coor : q_coor;
    const __nv_bfloat16* w1t = KV ? g_w1t_k : g_w1t_q;
    const float* b1 = KV ? bk1 : bq1;

    for (int p = tid; p < 64 * 64; p += 256) {
        int r = p >> 6, pp = p & 63;
        int half = pp >> 5, j = pp & 31;
        float coord = coor[2 * (lrow0 + r) + (half ? 0 : 1)];
        float freq = exp2f(-(float)j * 0.4152410118609203f);
        float v = coord * 6.283185307179586477f * freq;
        float sv, cv;
        sincosf(v, &sv, &cv);
        *(__nv_bfloat162*)(sm + M1_A + r * LDA + half * 64 + 2 * j) =
            __floats2bfloat162_rn(sv, cv);
    }
    for (int p = tid; p < 256 * 16; p += 256) {
        int n = p >> 4, ch = p & 15;
        *(uint4*)(sm + M1_WB + n * LDB + ch * 8) = *(const uint4*)(w1t + n * 128 + ch * 8);
    }
    __syncthreads();

    float c1[2][8][4];
    #pragma unroll
    for (int mi = 0; mi < 2; ++mi)
        #pragma unroll
        for (int ni = 0; ni < 8; ++ni)
            #pragma unroll
            for (int q = 0; q < 4; ++q) c1[mi][ni][q] = 0.0f;

    #pragma unroll
    for (int ks = 0; ks < 8; ++ks) {
        const int k0 = ks * 16;
        uint32_t a[2][4], b[8][2];
        #pragma unroll
        for (int mi = 0; mi < 2; ++mi) {
            const __nv_bfloat16* ap = sm + M1_A + (wr * 32 + mi * 16 + lr) * LDA + k0 + lc * 2;
            a[mi][0] = *(const uint32_t*)ap;
            a[mi][1] = *(const uint32_t*)(ap + 8 * LDA);
            a[mi][2] = *(const uint32_t*)(ap + 8);
            a[mi][3] = *(const uint32_t*)(ap + 8 * LDA + 8);
        }
        #pragma unroll
        for (int ni = 0; ni < 8; ++ni) {
            const __nv_bfloat16* bp = sm + M1_WB + (wc * 64 + ni * 8 + lr) * LDB + k0 + lc * 2;
            b[ni][0] = *(const uint32_t*)bp;
            b[ni][1] = *(const uint32_t*)(bp + 8);
        }
        #pragma unroll
        for (int mi = 0; mi < 2; ++mi)
            #pragma unroll
            for (int ni = 0; ni < 8; ++ni)
                mma_bf16(c1[mi][ni], a[mi][0], a[mi][1], a[mi][2], a[mi][3],
                         b[ni][0], b[ni][1]);
    }

    #pragma unroll
    for (int mi = 0; mi < 2; ++mi)
        #pragma unroll
        for (int ni = 0; ni < 8; ++ni) {
            int col = wc * 64 + ni * 8 + lc * 2;
            int row = grow0 + wr * 32 + mi * 16 + lr;
            float bl = __ldg(&b1[col]), bh = __ldg(&b1[col + 1]);
            float v0 = fmaxf(c1[mi][ni][0] + bl, 0.0f);
            float v1 = fmaxf(c1[mi][ni][1] + bh, 0.0f);
            float v2 = fmaxf(c1[mi][ni][2] + bl, 0.0f);
            float v3 = fmaxf(c1[mi][ni][3] + bh, 0.0f);
            *(__nv_bfloat162*)(g_h + (size_t)row * 256 + col) = __floats2bfloat162_rn(v0, v1);
            *(__nv_bfloat162*)(g_h + (size_t)(row + 8) * 256 + col) = __floats2bfloat162_rn(v2, v3);
        }
}

// ---------------------------------------------------------------------------
// Kernel 1b: layer 2 (unchanged, R8 pass)
// ---------------------------------------------------------------------------
__global__ void __launch_bounds__(256, 2) mlp2_kernel(
    const float* __restrict__ bq2, const float* __restrict__ bk2,
    const float* __restrict__ memory)
{
    extern __shared__ __nv_bfloat16 sm[];
    const int tid = threadIdx.x;
    const int w = tid >> 5, lane = tid & 31;
    const int wr = w >> 2, wc = w & 3;
    const int lr = lane >> 2, lc = lane & 3;

    const int grow0 = blockIdx.x * 64;
    const bool KV = grow0 >= NROW_Q;
    const __nv_bfloat16* w2t = KV ? g_w2t_k : g_w2t_q;
    const float* b2 = KV ? bk2 : bq2;

    for (int p = tid; p < 64 * 32; p += 256) {
        int r = p >> 5, ch = p & 31;
        *(uint4*)(sm + M2_A + r * LDH + ch * 8) =
            *(const uint4*)(g_h + (size_t)(grow0 + r) * 256 + ch * 8);
    }

    float c2[2][8][4];
    #pragma unroll
    for (int mi = 0; mi < 2; ++mi)
        #pragma unroll
        for (int ni = 0; ni < 8; ++ni)
            #pragma unroll
            for (int q = 0; q < 4; ++q) c2[mi][ni][q] = 0.0f;

    #pragma unroll 1
    for (int chunk = 0; chunk < 2; ++chunk) {
        __syncthreads();
        for (int p = tid; p < 256 * 16; p += 256) {
            int n = p >> 4, ch = p & 15;
            *(uint4*)(sm + M2_WB + n * LDB + ch * 8) =
                *(const uint4*)(w2t + n * 256 + chunk * 128 + ch * 8);
        }
        __syncthreads();
        #pragma unroll
        for (int ks = 0; ks < 8; ++ks) {
            const int kg = chunk * 128 + ks * 16;
            const int kl = ks * 16;
            uint32_t a[2][4], b[8][2];
            #pragma unroll
            for (int mi = 0; mi < 2; ++mi) {
                const __nv_bfloat16* ap = sm + M2_A + (wr * 32 + mi * 16 + lr) * LDH + kg + lc * 2;
                a[mi][0] = *(const uint32_t*)ap;
                a[mi][1] = *(const uint32_t*)(ap + 8 * LDH);
                a[mi][2] = *(const uint32_t*)(ap + 8);
                a[mi][3] = *(const uint32_t*)(ap + 8 * LDH + 8);
            }
            #pragma unroll
            for (int ni = 0; ni < 8; ++ni) {
                const __nv_bfloat16* bp = sm + M2_WB + (wc * 64 + ni * 8 + lr) * LDB + kl + lc * 2;
                b[ni][0] = *(const uint32_t*)bp;
                b[ni][1] = *(const uint32_t*)(bp + 8);
            }
            #pragma unroll
            for (int mi = 0; mi < 2; ++mi)
                #pragma unroll
                for (int ni = 0; ni < 8; ++ni)
                    mma_bf16(c2[mi][ni], a[mi][0], a[mi][1], a[mi][2], a[mi][3],
                             b[ni][0], b[ni][1]);
        }
    }

    #pragma unroll
    for (int mi = 0; mi < 2; ++mi)
        #pragma unroll
        for (int ni = 0; ni < 8; ++ni) {
            int col = wc * 64 + ni * 8 + lc * 2;
            int g = grow0 + wr * 32 + mi * 16 + lr;
            float bl = __ldg(&b2[col]), bh = __ldg(&b2[col + 1]);
            float2 v0 = make_float2(c2[mi][ni][0] + bl, c2[mi][ni][1] + bh);
            float2 v1 = make_float2(c2[mi][ni][2] + bl, c2[mi][ni][3] + bh);
            if (KV) {
                size_t l0 = (size_t)(g - NROW_Q) * 256 + col;
                size_t l1 = (size_t)(g + 8 - NROW_Q) * 256 + col;
                float2 m0 = *(const float2*)(memory + l0);
                float2 m1 = *(const float2*)(memory + l1);
                v0.x += m0.x; v0.y += m0.y; v1.x += m1.x; v1.y += m1.y;
                *(float2*)(g_kv + l0) = v0;
                *(float2*)(g_kv + l1) = v1;
            } else {
                *(float2*)(g_q + (size_t)g * 256 + col) = v0;
                *(float2*)(g_q + (size_t)(g + 8) * 256 + col) = v1;
            }
        }
}

// ---------------------------------------------------------------------------
// Kernel 2: exact top-16 via spatial grid. Warp per query.
// Collect 3x3 cell box (contiguous spans per row) into per-warp u64 key
// buffer; warp-cooperative 16-round extract-min; expand by perimeter rings
// until d16 < (R*h)^2 - margin (unexamined points are >= R*h away).
// d2 rounding identical to the brute-force passing versions.
// ---------------------------------------------------------------------------
#define TKCAP 320
__global__ void __launch_bounds__(256) topk_kernel(
    const float* __restrict__ q_coor)
{
    __shared__ unsigned long long sbuf[8][TKCAP + 16];

    const int wid = threadIdx.x >> 5, lane = threadIdx.x & 31;
    const int b = blockIdx.y;
    const int s = blockIdx.x * 8 + wid;
    const int qn = b * SQ + s;
    const float qx = q_coor[2 * qn], qy = q_coor[2 * qn + 1];
    const float q2 = __fadd_rn(__fmul_rn(qx, qx), __fmul_rn(qy, qy));
    const int cx = min(GC - 1, (int)(qx * (float)GC));
    const int cy = min(GC - 1, (int)(qy * (float)GC));
    const int* cs = g_cellstart[b];
    const float4* spt = g_spt[b];
    unsigned long long* buf = sbuf[wid];

    const unsigned long long UMAX = 0xFFFFFFFFFFFFFFFFull;
    unsigned long long bestk = UMAX;   // lane r<16 holds rank-r key after select
    float tau = __int_as_float(0x7f800000);   // +inf
    int cnt = 0;

    // merge buf[0..cnt) + bestk -> new bestk; update tau; reset cnt
    auto select16 = [&]() {
        // inject current bestk into buffer (ranks are dense from lane 0)
        unsigned valid = __ballot_sync(0xffffffffu, lane < 16 && bestk != UMAX);
        if (lane < 16 && bestk != UMAX) buf[cnt + lane] = bestk;
        cnt += __popc(valid);
        const int nper = (cnt + 31) >> 5;
        unsigned long long nb = UMAX;
        #pragma unroll 1
        for (int r = 0; r < 16; ++r) {
            unsigned long long mk = UMAX; int mj = 0;
            for (int i = 0; i < nper; ++i) {
                int j = lane + i * 32;
                if (j < cnt) {
                    unsigned long long v = buf[j];
                    if (v < mk) { mk = v; mj = j; }
                }
            }
            unsigned long long rk = mk; int rl = lane;
            #pragma unroll
            for (int off = 16; off; off >>= 1) {
                unsigned long long ok = __shfl_down_sync(0xffffffffu, rk, off);
                int ol = __shfl_down_sync(0xffffffffu, rl, off);
                if (ok < rk) { rk = ok; rl = ol; }
            }
            rk = __shfl_sync(0xffffffffu, rk, 0);
            rl = __shfl_sync(0xffffffffu, rl, 0);
            if (rk == UMAX) break;            // fewer than 16 total (uniform)
            if (lane == r) nb = rk;
            if (lane == rl) buf[mj] = UMAX;   // consume
        }
        bestk = nb;
        unsigned long long k15 = __shfl_sync(0xffffffffu, bestk, 15);
        tau = (k15 == UMAX) ? __int_as_float(0x7f800000)
                            : ord2f((uint32_t)(k15 >> 32));
        cnt = 0;
    };

    // scan a contiguous sorted-point range with tau gating
    auto scan_range = [&](int s0, int e0) {
        for (int j0 = s0; j0 < e0; j0 += 32) {
            const int j = j0 + lane;
            const bool valid = j < e0;
            float d2 = 0.0f; int oi = 0;
            if (valid) {
                float4 p = __ldg(&spt[j]);
                float m2 = __fadd_rn(__fmul_rn(p.x, p.x), __fmul_rn(p.y, p.y));
                float dt = __fmaf_rn(qy, p.y, __fmul_rn(qx, p.x));
                d2 = __fsub_rn(__fadd_rn(q2, m2), __fmul_rn(2.0f, dt));
                oi = __float_as_int(p.z);
            }
            bool acc = valid && (d2 < tau);
            unsigned mask = __ballot_sync(0xffffffffu, acc);
            if (!mask) continue;
            int nacc = __popc(mask);
            if (cnt + nacc > TKCAP) {
                select16();
                acc = valid && (d2 < tau);
                mask = __ballot_sync(0xffffffffu, acc);
                nacc = __popc(mask);
            }
            if (acc) {
                int pos = cnt + __popc(mask & ((1u << lane) - 1u));
                buf[pos] = ((unsigned long long)f2ord(d2) << 32) | (uint32_t)oi;
            }
            cnt += nacc;
        }
    };

    // initial 3x3 box (Chebyshev radius 1)
    {
        int x0 = max(0, cx - 1), x1 = min(GC - 1, cx + 1);
        int y0 = max(0, cy - 1), y1 = min(GC - 1, cy + 1);
        for (int y = y0; y <= y1; ++y)
            scan_range(__ldg(&cs[y * GC + x0]), __ldg(&cs[y * GC + x1 + 1]));
        select16();
    }

    int R = 1;
    while (true) {
        float bound = (float)R * GH;
        bool full = (cx - R <= 0) && (cx + R >= GC - 1) &&
                    (cy - R <= 0) && (cy + R >= GC - 1);
        if (full || tau < bound * bound - 2e-6f) break;
        ++R;
        const int nx0 = max(0, cx - R), nx1 = min(GC - 1, cx + R);
        if (cy - R >= 0)
            scan_range(__ldg(&cs[(cy - R) * GC + nx0]), __ldg(&cs[(cy - R) * GC + nx1 + 1]));
        if (cy + R <= GC - 1)
            scan_range(__ldg(&cs[(cy + R) * GC + nx0]), __ldg(&cs[(cy + R) * GC + nx1 + 1]));
        const int my0 = max(0, cy - R + 1), my1 = min(GC - 1, cy + R - 1);
        for (int y = my0; y <= my1; ++y) {
            if (cx - R >= 0)
                scan_range(__ldg(&cs[y * GC + cx - R]), __ldg(&cs[y * GC + cx - R + 1]));
            if (cx + R <= GC - 1)
                scan_range(__ldg(&cs[y * GC + cx + R]), __ldg(&cs[y * GC + cx + R + 1]));
        }
        if (cnt > 0) select16();
    }

    if (lane < 16) g_idx[qn * 16 + lane] = (int)(uint32_t)bestk;
}

// ---------------------------------------------------------------------------
// Kernel 3: gather + softmax over D + multiply (unchanged, R8 pass)
// ---------------------------------------------------------------------------
__global__ void __launch_bounds__(128, 1) attn_kernel(
    const float* __restrict__ memory, float* __restrict__ out)
{
    const int s = blockIdx.x, b = blockIdx.y;
    const int qn = b * SQ + s;
    const int w = threadIdx.x >> 5, lane = threadIdx.x & 31;

    const float4* qp = (const float4*)(g_q + (size_t)qn * 256);
    const float4 q0 = qp[lane * 2], q1 = qp[lane * 2 + 1];

    #pragma unroll
    for (int jj = 0; jj < 4; ++jj) {
        const int j = w * 4 + jj;
        const int idx = __ldg(&g_idx[qn * 16 + j]);

        const float4* kvp = (const float4*)(g_kv + ((size_t)b * LM + idx) * 256);
        float4 k0 = kvp[lane * 2], k1 = kvp[lane * 2 + 1];

        float p[8];
        p[0] = q0.x * k0.x; p[1] = q0.y * k0.y; p[2] = q0.z * k0.z; p[3] = q0.w * k0.w;
        p[4] = q1.x * k1.x; p[5] = q1.y * k1.y; p[6] = q1.z * k1.z; p[7] = q1.w * k1.w;
        #pragma unroll
        for (int i = 0; i < 8; ++i) p[i] *= 0.0625f;

        float mx = p[0];
        #pragma unroll
        for (int i = 1; i < 8; ++i) mx = fmaxf(mx, p[i]);
        #pragma unroll
        for (int off = 16; off; off >>= 1)
            mx = fmaxf(mx, __shfl_xor_sync(0xffffffffu, mx, off));

        float sum = 0.0f;
        #pragma unroll
        for (int i = 0; i < 8; ++i) { p[i] = __expf(p[i] - mx); sum += p[i]; }
        #pragma unroll
        for (int off = 16; off; off >>= 1)
            sum += __shfl_xor_sync(0xffffffffu, sum, off);
        const float inv = __frcp_rn(sum);

        const float4* mp = (const float4*)(memory + ((size_t)b * LM + idx) * 256);
        float4 m0 = mp[lane * 2], m1 = mp[lane * 2 + 1];

        float4 r0, r1;
        r0.x = p[0] * inv * m0.x; r0.y = p[1] * inv * m0.y;
        r0.z = p[2] * inv * m0.z; r0.w = p[3] * inv * m0.w;
        r1.x = p[4] * inv * m1.x; r1.y = p[5] * inv * m1.y;
        r1.z = p[6] * inv * m1.z; r1.w = p[7] * inv * m1.w;

        float4* op = (float4*)(out + ((size_t)(qn * 16 + j)) * 256);
        op[lane * 2]     = r0;
        op[lane * 2 + 1] = r1;
    }
}

// ---------------------------------------------------------------------------

extern "C" void kernel_launch(void* const* d_in, const int* in_sizes, int n_in,
                              void* d_out, int out_size)
{
    const float* memory   = (const float*)d_in[0];
    const float* mem_coor = (const float*)d_in[1];
    const float* q_coor   = (const float*)d_in[2];
    const float* Wq1 = (const float*)d_in[3];
    const float* bq1 = (const float*)d_in[4];
    const float* Wq2 = (const float*)d_in[5];
    const float* bq2 = (const float*)d_in[6];
    const float* Wk1 = (const float*)d_in[7];
    const float* bk1 = (const float*)d_in[8];
    const float* Wk2 = (const float*)d_in[9];
    const float* bk2 = (const float*)d_in[10];
    float* out = (float*)d_out;

    cudaFuncSetAttribute(mlp1_kernel,
        cudaFuncAttributeMaxDynamicSharedMemorySize, SMEM_MLP1);
    cudaFuncSetAttribute(mlp2_kernel,
        cudaFuncAttributeMaxDynamicSharedMemorySize, SMEM_MLP2);

    // K0: weight transpose + bf16; spatial grid build
    prep_weights<<<256, 256>>>(Wq1, Wq2, Wk1, Wk2);
    grid_build<<<BQ, 1024>>>(mem_coor);

    // K1: MLP layers
    mlp1_kernel<<<768, 256, SMEM_MLP1>>>(q_coor, mem_coor, bq1, bk1);
    mlp2_kernel<<<NROW_T / 64, 256, SMEM_MLP2>>>(bq2, bk2, memory);

    // K2: top-16 neighbors via spatial grid
    topk_kernel<<<dim3(SQ / 8, BQ), 256>>>(q_coor);

    // K3: gather + softmax(D) + multiply
    attn_kernel<<<dim3(SQ, BQ), 128>>>(memory, out);
}

// round 12
// speedup vs baseline: 4.3856x; 1.0252x over previous
#include <cuda_runtime.h>
#include <cuda_bf16.h>
#include <cstdint>

#define BQ  4
#define SQ  4096
#define LM  8192
#define DD  256
#define KNN 16
#define NROW_Q (BQ*SQ)          /* 16384 */
#define NROW_T (BQ*(SQ+LM))     /* 49152 total MLP rows */

// Scratch (device globals: allocation-free, graph-capture safe)
__device__ __align__(16) float g_q [BQ*SQ*DD];         // 16 MB
__device__ __align__(16) float g_kv[(size_t)BQ*LM*DD]; // 32 MB
__device__ int   g_idx[BQ*SQ*KNN];                     // 1 MB
__device__ __align__(16) __nv_bfloat16 g_h[(size_t)NROW_T*DD];  // 24 MB hidden
// bf16 transposed weights
__device__ __align__(16) __nv_bfloat16 g_w1t_q[256*128];
__device__ __align__(16) __nv_bfloat16 g_w2t_q[256*256];
__device__ __align__(16) __nv_bfloat16 g_w1t_k[256*128];
__device__ __align__(16) __nv_bfloat16 g_w2t_k[256*256];
// spatial grid (32x32 cells per batch)
#define GC 32
#define GCELLS (GC*GC)
#define GH 0.03125f
__device__ int g_cellstart[BQ][GCELLS + 1];
__device__ __align__(16) float4 g_spt[BQ][LM];   // sorted {x, y, bits(idx), 0}

// ---------------------------------------------------------------------------
#define LDA 136
#define LDB 136
#define LDH 264
#define M1_A  0
#define M1_WB (64 * LDA)
#define SMEM_MLP1 ((M1_WB + 256 * LDB) * 2)
// mlp2: AH 128xLDH (67584B) + WB0 256xLDB (69632B) + WB1 (69632B) = 206848B
#define M2_A   0
#define M2_WB0 (128 * LDH)
#define M2_WB1 (M2_WB0 + 256 * LDB)
#define SMEM_MLP2 ((M2_WB1 + 256 * LDB) * 2)

__device__ __forceinline__ void mma_bf16(float c[4],
    uint32_t a0, uint32_t a1, uint32_t a2, uint32_t a3,
    uint32_t b0, uint32_t b1)
{
    asm volatile(
        "mma.sync.aligned.m16n8k16.row.col.f32.bf16.bf16.f32 "
        "{%0,%1,%2,%3}, {%4,%5,%6,%7}, {%8,%9}, {%0,%1,%2,%3};"
        : "+f"(c[0]), "+f"(c[1]), "+f"(c[2]), "+f"(c[3])
        : "r"(a0), "r"(a1), "r"(a2), "r"(a3), "r"(b0), "r"(b1));
}

__device__ __forceinline__ void cp16(uint32_t smem, const void* g) {
    asm volatile("cp.async.cg.shared.global [%0], [%1], 16;" :: "r"(smem), "l"(g));
}
#define CP_COMMIT() asm volatile("cp.async.commit_group;" ::: "memory")
#define CP_WAIT(n)  asm volatile("cp.async.wait_group %0;" :: "n"(n) : "memory")

__device__ __forceinline__ uint32_t f2ord(float f) {
    uint32_t u = __float_as_uint(f);
    return u ^ ((uint32_t)((int)u >> 31) | 0x80000000u);
}
__device__ __forceinline__ float ord2f(uint32_t o) {
    uint32_t u = o ^ ((uint32_t)((int)(~o) >> 31) | 0x80000000u);
    return __uint_as_float(u);
}

// ---------------------------------------------------------------------------
// Kernel 0: weight prep (unchanged, R9 pass)
// ---------------------------------------------------------------------------
__global__ void prep_weights(const float* __restrict__ Wq1, const float* __restrict__ Wq2,
                             const float* __restrict__ Wk1, const float* __restrict__ Wk2)
{
    int idx = blockIdx.x * 256 + threadIdx.x;
    {
        int n = idx >> 8, k = idx & 255;
        g_w2t_q[idx] = __float2bfloat16(Wq2[k * 256 + n]);
        g_w2t_k[idx] = __float2bfloat16(Wk2[k * 256 + n]);
    }
    if (idx < 32768) {
        int n = idx >> 7, k = idx & 127;
        g_w1t_q[idx] = __float2bfloat16(Wq1[k * 256 + n]);
        g_w1t_k[idx] = __float2bfloat16(Wk1[k * 256 + n]);
    }
}

// ---------------------------------------------------------------------------
// Kernel 0b: spatial grid build (unchanged, R9 pass)
// ---------------------------------------------------------------------------
__global__ void __launch_bounds__(1024, 1) grid_build(const float* __restrict__ mem_coor)
{
    __shared__ int hist[GCELLS];
    __shared__ int scn[GCELLS];
    const int b = blockIdx.x, tid = threadIdx.x;
    hist[tid] = 0;
    __syncthreads();

    const float2* mc = (const float2*)(mem_coor + (size_t)b * LM * 2);
    int cellid[8]; float2 pt[8];
    #pragma unroll
    for (int i = 0; i < 8; ++i) {
        int p = tid + i * 1024;
        float2 c = mc[p];
        int cx = min(GC - 1, (int)(c.x * (float)GC));
        int cy = min(GC - 1, (int)(c.y * (float)GC));
        cellid[i] = cy * GC + cx; pt[i] = c;
        atomicAdd(&hist[cellid[i]], 1);
    }
    __syncthreads();

    int v = hist[tid];
    scn[tid] = v;
    __syncthreads();
    for (int off = 1; off < GCELLS; off <<= 1) {
        int t = (tid >= off) ? scn[tid - off] : 0;
        __syncthreads();
        scn[tid] += t;
        __syncthreads();
    }
    int excl = scn[tid] - v;
    g_cellstart[b][tid] = excl;
    if (tid == GCELLS - 1) g_cellstart[b][GCELLS] = LM;
    hist[tid] = excl;
    __syncthreads();

    #pragma unroll
    for (int i = 0; i < 8; ++i) {
        int p = tid + i * 1024;
        int pos = atomicAdd(&hist[cellid[i]], 1);
        g_spt[b][pos] = make_float4(pt[i].x, pt[i].y, __int_as_float(p), 0.0f);
    }
}

// ---------------------------------------------------------------------------
// Kernel 1a: posemb + layer 1 (unchanged, R9 pass)
// ---------------------------------------------------------------------------
__global__ void __launch_bounds__(256, 2) mlp1_kernel(
    const float* __restrict__ q_coor, const float* __restrict__ mem_coor,
    const float* __restrict__ bq1, const float* __restrict__ bk1)
{
    extern __shared__ __nv_bfloat16 sm[];
    const int tid = threadIdx.x;
    const int w = tid >> 5, lane = tid & 31;
    const int wr = w >> 2, wc = w & 3;
    const int lr = lane >> 2, lc = lane & 3;

    const bool KV = blockIdx.x >= 256;
    const int lrow0 = (KV ? (blockIdx.x - 256) : blockIdx.x) * 64;
    const int grow0 = KV ? (NROW_Q + lrow0) : lrow0;
    const float* coor = KV ? mem_coor : q_coor;
    const __nv_bfloat16* w1t = KV ? g_w1t_k : g_w1t_q;
    const float* b1 = KV ? bk1 : bq1;

    for (int p = tid; p < 64 * 64; p += 256) {
        int r = p >> 6, pp = p & 63;
        int half = pp >> 5, j = pp & 31;
        float coord = coor[2 * (lrow0 + r) + (half ? 0 : 1)];
        float freq = exp2f(-(float)j * 0.4152410118609203f);
        float v = coord * 6.283185307179586477f * freq;
        float sv, cv;
        sincosf(v, &sv, &cv);
        *(__nv_bfloat162*)(sm + M1_A + r * LDA + half * 64 + 2 * j) =
            __floats2bfloat162_rn(sv, cv);
    }
    for (int p = tid; p < 256 * 16; p += 256) {
        int n = p >> 4, ch = p & 15;
        *(uint4*)(sm + M1_WB + n * LDB + ch * 8) = *(const uint4*)(w1t + n * 128 + ch * 8);
    }
    __syncthreads();

    float c1[2][8][4];
    #pragma unroll
    for (int mi = 0; mi < 2; ++mi)
        #pragma unroll
        for (int ni = 0; ni < 8; ++ni)
            #pragma unroll
            for (int q = 0; q < 4; ++q) c1[mi][ni][q] = 0.0f;

    #pragma unroll
    for (int ks = 0; ks < 8; ++ks) {
        const int k0 = ks * 16;
        uint32_t a[2][4], b[8][2];
        #pragma unroll
        for (int mi = 0; mi < 2; ++mi) {
            const __nv_bfloat16* ap = sm + M1_A + (wr * 32 + mi * 16 + lr) * LDA + k0 + lc * 2;
            a[mi][0] = *(const uint32_t*)ap;
            a[mi][1] = *(const uint32_t*)(ap + 8 * LDA);
            a[mi][2] = *(const uint32_t*)(ap + 8);
            a[mi][3] = *(const uint32_t*)(ap + 8 * LDA + 8);
        }
        #pragma unroll
        for (int ni = 0; ni < 8; ++ni) {
            const __nv_bfloat16* bp = sm + M1_WB + (wc * 64 + ni * 8 + lr) * LDB + k0 + lc * 2;
            b[ni][0] = *(const uint32_t*)bp;
            b[ni][1] = *(const uint32_t*)(bp + 8);
        }
        #pragma unroll
        for (int mi = 0; mi < 2; ++mi)
            #pragma unroll
            for (int ni = 0; ni < 8; ++ni)
                mma_bf16(c1[mi][ni], a[mi][0], a[mi][1], a[mi][2], a[mi][3],
                         b[ni][0], b[ni][1]);
    }

    #pragma unroll
    for (int mi = 0; mi < 2; ++mi)
        #pragma unroll
        for (int ni = 0; ni < 8; ++ni) {
            int col = wc * 64 + ni * 8 + lc * 2;
            int row = grow0 + wr * 32 + mi * 16 + lr;
            float bl = __ldg(&b1[col]), bh = __ldg(&b1[col + 1]);
            float v0 = fmaxf(c1[mi][ni][0] + bl, 0.0f);
            float v1 = fmaxf(c1[mi][ni][1] + bh, 0.0f);
            float v2 = fmaxf(c1[mi][ni][2] + bl, 0.0f);
            float v3 = fmaxf(c1[mi][ni][3] + bh, 0.0f);
            *(__nv_bfloat162*)(g_h + (size_t)row * 256 + col) = __floats2bfloat162_rn(v0, v1);
            *(__nv_bfloat162*)(g_h + (size_t)(row + 8) * 256 + col) = __floats2bfloat162_rn(v2, v3);
        }
}

// ---------------------------------------------------------------------------
// Kernel 1b: layer 2, cp.async double-buffered weights, M-tile 128.
// Grid 384 x 128-row tiles; 512 threads = 16 warps as 4x4; warp tile 32x64.
// Both W2 chunks prefetched at kernel start; chunk1 loads overlap chunk0 mma.
// ---------------------------------------------------------------------------
__global__ void __launch_bounds__(512, 1) mlp2_kernel(
    const float* __restrict__ bq2, const float* __restrict__ bk2,
    const float* __restrict__ memory)
{
    extern __shared__ __nv_bfloat16 sm[];
    const uint32_t smb = (uint32_t)__cvta_generic_to_shared(sm);
    const int tid = threadIdx.x;
    const int w = tid >> 5, lane = tid & 31;
    const int wr = w >> 2, wc = w & 3;
    const int lr = lane >> 2, lc = lane & 3;

    const int grow0 = blockIdx.x * 128;
    const bool KV = grow0 >= NROW_Q;
    const __nv_bfloat16* w2t = KV ? g_w2t_k : g_w2t_q;
    const float* b2 = KV ? bk2 : bq2;

    // async stage: AH (128x256) + WB0 -> group0 ; WB1 -> group1
    for (int p = tid; p < 128 * 32; p += 512) {
        int r = p >> 5, ch = p & 31;
        cp16(smb + (M2_A + r * LDH + ch * 8) * 2,
             g_h + (size_t)(grow0 + r) * 256 + ch * 8);
    }
    for (int p = tid; p < 256 * 16; p += 512) {
        int n = p >> 4, ch = p & 15;
        cp16(smb + (M2_WB0 + n * LDB + ch * 8) * 2, w2t + n * 256 + ch * 8);
    }
    CP_COMMIT();
    for (int p = tid; p < 256 * 16; p += 512) {
        int n = p >> 4, ch = p & 15;
        cp16(smb + (M2_WB1 + n * LDB + ch * 8) * 2, w2t + n * 256 + 128 + ch * 8);
    }
    CP_COMMIT();

    float c2[2][8][4];
    #pragma unroll
    for (int mi = 0; mi < 2; ++mi)
        #pragma unroll
        for (int ni = 0; ni < 8; ++ni)
            #pragma unroll
            for (int q = 0; q < 4; ++q) c2[mi][ni][q] = 0.0f;

    CP_WAIT(1);          // AH + WB0 resident
    __syncthreads();

    #pragma unroll 1
    for (int chunk = 0; chunk < 2; ++chunk) {
        const int wb = chunk ? M2_WB1 : M2_WB0;
        #pragma unroll
        for (int ks = 0; ks < 8; ++ks) {
            const int kg = chunk * 128 + ks * 16;
            const int kl = ks * 16;
            uint32_t a[2][4], b[8][2];
            #pragma unroll
            for (int mi = 0; mi < 2; ++mi) {
                const __nv_bfloat16* ap = sm + M2_A + (wr * 32 + mi * 16 + lr) * LDH + kg + lc * 2;
                a[mi][0] = *(const uint32_t*)ap;
                a[mi][1] = *(const uint32_t*)(ap + 8 * LDH);
                a[mi][2] = *(const uint32_t*)(ap + 8);
                a[mi][3] = *(const uint32_t*)(ap + 8 * LDH + 8);
            }
            #pragma unroll
            for (int ni = 0; ni < 8; ++ni) {
                const __nv_bfloat16* bp = sm + wb + (wc * 64 + ni * 8 + lr) * LDB + kl + lc * 2;
                b[ni][0] = *(const uint32_t*)bp;
                b[ni][1] = *(const uint32_t*)(bp + 8);
            }
            #pragma unroll
            for (int mi = 0; mi < 2; ++mi)
                #pragma unroll
                for (int ni = 0; ni < 8; ++ni)
                    mma_bf16(c2[mi][ni], a[mi][0], a[mi][1], a[mi][2], a[mi][3],
                             b[ni][0], b[ni][1]);
        }
        if (chunk == 0) { CP_WAIT(0); __syncthreads(); }
    }

    #pragma unroll
    for (int mi = 0; mi < 2; ++mi)
        #pragma unroll
        for (int ni = 0; ni < 8; ++ni) {
            int col = wc * 64 + ni * 8 + lc * 2;
            int g = grow0 + wr * 32 + mi * 16 + lr;
            float bl = __ldg(&b2[col]), bh = __ldg(&b2[col + 1]);
            float2 v0 = make_float2(c2[mi][ni][0] + bl, c2[mi][ni][1] + bh);
            float2 v1 = make_float2(c2[mi][ni][2] + bl, c2[mi][ni][3] + bh);
            if (KV) {
                size_t l0 = (size_t)(g - NROW_Q) * 256 + col;
                size_t l1 = (size_t)(g + 8 - NROW_Q) * 256 + col;
                float2 m0 = *(const float2*)(memory + l0);
                float2 m1 = *(const float2*)(memory + l1);
                v0.x += m0.x; v0.y += m0.y; v1.x += m1.x; v1.y += m1.y;
                *(float2*)(g_kv + l0) = v0;
                *(float2*)(g_kv + l1) = v1;
            } else {
                *(float2*)(g_q + (size_t)g * 256 + col) = v0;
                *(float2*)(g_q + (size_t)(g + 8) * 256 + col) = v1;
            }
        }
}

// ---------------------------------------------------------------------------
// Kernel 2: exact top-16 via spatial grid (unchanged, R9 pass)
// ---------------------------------------------------------------------------
#define TKCAP 320
__global__ void __launch_bounds__(256) topk_kernel(
    const float* __restrict__ q_coor)
{
    __shared__ unsigned long long sbuf[8][TKCAP + 16];

    const int wid = threadIdx.x >> 5, lane = threadIdx.x & 31;
    const int b = blockIdx.y;
    const int s = blockIdx.x * 8 + wid;
    const int qn = b * SQ + s;
    const float qx = q_coor[2 * qn], qy = q_coor[2 * qn + 1];
    const float q2 = __fadd_rn(__fmul_rn(qx, qx), __fmul_rn(qy, qy));
    const int cx = min(GC - 1, (int)(qx * (float)GC));
    const int cy = min(GC - 1, (int)(qy * (float)GC));
    const int* cs = g_cellstart[b];
    const float4* spt = g_spt[b];
    unsigned long long* buf = sbuf[wid];

    const unsigned long long UMAX = 0xFFFFFFFFFFFFFFFFull;
    unsigned long long bestk = UMAX;
    float tau = __int_as_float(0x7f800000);
    int cnt = 0;

    auto select16 = [&]() {
        unsigned valid = __ballot_sync(0xffffffffu, lane < 16 && bestk != UMAX);
        if (lane < 16 && bestk != UMAX) buf[cnt + lane] = bestk;
        cnt += __popc(valid);
        const int nper = (cnt + 31) >> 5;
        unsigned long long nb = UMAX;
        #pragma unroll 1
        for (int r = 0; r < 16; ++r) {
            unsigned long long mk = UMAX; int mj = 0;
            for (int i = 0; i < nper; ++i) {
                int j = lane + i * 32;
                if (j < cnt) {
                    unsigned long long v = buf[j];
                    if (v < mk) { mk = v; mj = j; }
                }
            }
            unsigned long long rk = mk; int rl = lane;
            #pragma unroll
            for (int off = 16; off; off >>= 1) {
                unsigned long long ok = __shfl_down_sync(0xffffffffu, rk, off);
                int ol = __shfl_down_sync(0xffffffffu, rl, off);
                if (ok < rk) { rk = ok; rl = ol; }
            }
            rk = __shfl_sync(0xffffffffu, rk, 0);
            rl = __shfl_sync(0xffffffffu, rl, 0);
            if (rk == UMAX) break;
            if (lane == r) nb = rk;
            if (lane == rl) buf[mj] = UMAX;
        }
        bestk = nb;
        unsigned long long k15 = __shfl_sync(0xffffffffu, bestk, 15);
        tau = (k15 == UMAX) ? __int_as_float(0x7f800000)
                            : ord2f((uint32_t)(k15 >> 32));
        cnt = 0;
    };

    auto scan_range = [&](int s0, int e0) {
        for (int j0 = s0; j0 < e0; j0 += 32) {
            const int j = j0 + lane;
            const bool valid = j < e0;
            float d2 = 0.0f; int oi = 0;
            if (valid) {
                float4 p = __ldg(&spt[j]);
                float m2 = __fadd_rn(__fmul_rn(p.x, p.x), __fmul_rn(p.y, p.y));
                float dt = __fmaf_rn(qy, p.y, __fmul_rn(qx, p.x));
                d2 = __fsub_rn(__fadd_rn(q2, m2), __fmul_rn(2.0f, dt));
                oi = __float_as_int(p.z);
            }
            bool acc = valid && (d2 < tau);
            unsigned mask = __ballot_sync(0xffffffffu, acc);
            if (!mask) continue;
            int nacc = __popc(mask);
            if (cnt + nacc > TKCAP) {
                select16();
                acc = valid && (d2 < tau);
                mask = __ballot_sync(0xffffffffu, acc);
                nacc = __popc(mask);
            }
            if (acc) {
                int pos = cnt + __popc(mask & ((1u << lane) - 1u));
                buf[pos] = ((unsigned long long)f2ord(d2) << 32) | (uint32_t)oi;
            }
            cnt += nacc;
        }
    };

    {
        int x0 = max(0, cx - 1), x1 = min(GC - 1, cx + 1);
        int y0 = max(0, cy - 1), y1 = min(GC - 1, cy + 1);
        for (int y = y0; y <= y1; ++y)
            scan_range(__ldg(&cs[y * GC + x0]), __ldg(&cs[y * GC + x1 + 1]));
        select16();
    }

    int R = 1;
    while (true) {
        float bound = (float)R * GH;
        bool full = (cx - R <= 0) && (cx + R >= GC - 1) &&
                    (cy - R <= 0) && (cy + R >= GC - 1);
        if (full || tau < bound * bound - 2e-6f) break;
        ++R;
        const int nx0 = max(0, cx - R), nx1 = min(GC - 1, cx + R);
        if (cy - R >= 0)
            scan_range(__ldg(&cs[(cy - R) * GC + nx0]), __ldg(&cs[(cy - R) * GC + nx1 + 1]));
        if (cy + R <= GC - 1)
            scan_range(__ldg(&cs[(cy + R) * GC + nx0]), __ldg(&cs[(cy + R) * GC + nx1 + 1]));
        const int my0 = max(0, cy - R + 1), my1 = min(GC - 1, cy + R - 1);
        for (int y = my0; y <= my1; ++y) {
            if (cx - R >= 0)
                scan_range(__ldg(&cs[y * GC + cx - R]), __ldg(&cs[y * GC + cx - R + 1]));
            if (cx + R <= GC - 1)
                scan_range(__ldg(&cs[y * GC + cx + R]), __ldg(&cs[y * GC + cx + R + 1]));
        }
        if (cnt > 0) select16();
    }

    if (lane < 16) g_idx[qn * 16 + lane] = (int)(uint32_t)bestk;
}

// ---------------------------------------------------------------------------
// Kernel 3: gather + softmax over D + multiply. 2 neighbors per iteration
// (independent shfl/load chains interleave -> halved exposed latency).
// ---------------------------------------------------------------------------
__global__ void __launch_bounds__(128, 1) attn_kernel(
    const float* __restrict__ memory, float* __restrict__ out)
{
    const int s = blockIdx.x, b = blockIdx.y;
    const int qn = b * SQ + s;
    const int w = threadIdx.x >> 5, lane = threadIdx.x & 31;

    const float4* qp = (const float4*)(g_q + (size_t)qn * 256);
    const float4 q0 = qp[lane * 2], q1 = qp[lane * 2 + 1];

    #pragma unroll
    for (int jj = 0; jj < 4; jj += 2) {
        const int j0 = w * 4 + jj;
        const int idx0 = __ldg(&g_idx[qn * 16 + j0]);
        const int idx1 = __ldg(&g_idx[qn * 16 + j0 + 1]);

        const float4* kvp0 = (const float4*)(g_kv + ((size_t)b * LM + idx0) * 256);
        const float4* kvp1 = (const float4*)(g_kv + ((size_t)b * LM + idx1) * 256);
        float4 ka0 = kvp0[lane * 2], ka1 = kvp0[lane * 2 + 1];
        float4 kb0 = kvp1[lane * 2], kb1 = kvp1[lane * 2 + 1];

        float pa[8], pb[8];
        pa[0] = q0.x * ka0.x; pa[1] = q0.y * ka0.y; pa[2] = q0.z * ka0.z; pa[3] = q0.w * ka0.w;
        pa[4] = q1.x * ka1.x; pa[5] = q1.y * ka1.y; pa[6] = q1.z * ka1.z; pa[7] = q1.w * ka1.w;
        pb[0] = q0.x * kb0.x; pb[1] = q0.y * kb0.y; pb[2] = q0.z * kb0.z; pb[3] = q0.w * kb0.w;
        pb[4] = q1.x * kb1.x; pb[5] = q1.y * kb1.y; pb[6] = q1.z * kb1.z; pb[7] = q1.w * kb1.w;
        #pragma unroll
        for (int i = 0; i < 8; ++i) { pa[i] *= 0.0625f; pb[i] *= 0.0625f; }

        float mxa = pa[0], mxb = pb[0];
        #pragma unroll
        for (int i = 1; i < 8; ++i) { mxa = fmaxf(mxa, pa[i]); mxb = fmaxf(mxb, pb[i]); }
        #pragma unroll
        for (int off = 16; off; off >>= 1) {
            mxa = fmaxf(mxa, __shfl_xor_sync(0xffffffffu, mxa, off));
            mxb = fmaxf(mxb, __shfl_xor_sync(0xffffffffu, mxb, off));
        }

        float sa = 0.0f, sb = 0.0f;
        #pragma unroll
        for (int i = 0; i < 8; ++i) {
            pa[i] = __expf(pa[i] - mxa); sa += pa[i];
            pb[i] = __expf(pb[i] - mxb); sb += pb[i];
        }
        #pragma unroll
        for (int off = 16; off; off >>= 1) {
            sa += __shfl_xor_sync(0xffffffffu, sa, off);
            sb += __shfl_xor_sync(0xffffffffu, sb, off);
        }
        const float ia = __frcp_rn(sa), ib = __frcp_rn(sb);

        const float4* mp0 = (const float4*)(memory + ((size_t)b * LM + idx0) * 256);
        const float4* mp1 = (const float4*)(memory + ((size_t)b * LM + idx1) * 256);
        float4 ma0 = mp0[lane * 2], ma1 = mp0[lane * 2 + 1];
        float4 mb0 = mp1[lane * 2], mb1 = mp1[lane * 2 + 1];

        float4 r;
        float4* op0 = (float4*)(out + ((size_t)(qn * 16 + j0)) * 256);
        float4* op1 = (float4*)(out + ((size_t)(qn * 16 + j0 + 1)) * 256);
        r.x = pa[0] * ia * ma0.x; r.y = pa[1] * ia * ma0.y;
        r.z = pa[2] * ia * ma0.z; r.w = pa[3] * ia * ma0.w;
        op0[lane * 2] = r;
        r.x = pa[4] * ia * ma1.x; r.y = pa[5] * ia * ma1.y;
        r.z = pa[6] * ia * ma1.z; r.w = pa[7] * ia * ma1.w;
        op0[lane * 2 + 1] = r;
        r.x = pb[0] * ib * mb0.x; r.y = pb[1] * ib * mb0.y;
        r.z = pb[2] * ib * mb0.z; r.w = pb[3] * ib * mb0.w;
        op1[lane * 2] = r;
        r.x = pb[4] * ib * mb1.x; r.y = pb[5] * ib * mb1.y;
        r.z = pb[6] * ib * mb1.z; r.w = pb[7] * ib * mb1.w;
        op1[lane * 2 + 1] = r;
    }
}

// ---------------------------------------------------------------------------

extern "C" void kernel_launch(void* const* d_in, const int* in_sizes, int n_in,
                              void* d_out, int out_size)
{
    const float* memory   = (const float*)d_in[0];
    const float* mem_coor = (const float*)d_in[1];
    const float* q_coor   = (const float*)d_in[2];
    const float* Wq1 = (const float*)d_in[3];
    const float* bq1 = (const float*)d_in[4];
    const float* Wq2 = (const float*)d_in[5];
    const float* bq2 = (const float*)d_in[6];
    const float* Wk1 = (const float*)d_in[7];
    const float* bk1 = (const float*)d_in[8];
    const float* Wk2 = (const float*)d_in[9];
    const float* bk2 = (const float*)d_in[10];
    float* out = (float*)d_out;

    cudaFuncSetAttribute(mlp1_kernel,
        cudaFuncAttributeMaxDynamicSharedMemorySize, SMEM_MLP1);
    cudaFuncSetAttribute(mlp2_kernel,
        cudaFuncAttributeMaxDynamicSharedMemorySize, SMEM_MLP2);

    // K0: weight transpose + bf16; spatial grid build
    prep_weights<<<256, 256>>>(Wq1, Wq2, Wk1, Wk2);
    grid_build<<<BQ, 1024>>>(mem_coor);

    // K1: MLP layers
    mlp1_kernel<<<768, 256, SMEM_MLP1>>>(q_coor, mem_coor, bq1, bk1);
    mlp2_kernel<<<NROW_T / 128, 512, SMEM_MLP2>>>(bq2, bk2, memory);

    // K2: top-16 neighbors via spatial grid
    topk_kernel<<<dim3(SQ / 8, BQ), 256>>>(q_coor);

    // K3: gather + softmax(D) + multiply
    attn_kernel<<<dim3(SQ, BQ), 128>>>(memory, out);
}

// round 14
// speedup vs baseline: 4.4063x; 1.0047x over previous
#include <cuda_runtime.h>
#include <cuda_bf16.h>
#include <cstdint>

#define BQ  4
#define SQ  4096
#define LM  8192
#define DD  256
#define KNN 16
#define NROW_Q (BQ*SQ)          /* 16384 */
#define NROW_T (BQ*(SQ+LM))     /* 49152 total MLP rows */

// Scratch (device globals: allocation-free, graph-capture safe)
__device__ __align__(16) float g_q [BQ*SQ*DD];         // 16 MB
__device__ __align__(16) float g_kv[(size_t)BQ*LM*DD]; // 32 MB
__device__ int   g_idx[BQ*SQ*KNN];                     // 1 MB
__device__ __align__(16) __nv_bfloat16 g_h[(size_t)NROW_T*DD];  // 24 MB hidden
// bf16 transposed weights
__device__ __align__(16) __nv_bfloat16 g_w1t_q[256*128];
__device__ __align__(16) __nv_bfloat16 g_w2t_q[256*256];
__device__ __align__(16) __nv_bfloat16 g_w1t_k[256*128];
__device__ __align__(16) __nv_bfloat16 g_w2t_k[256*256];
// spatial grid (32x32 cells per batch)
#define GC 32
#define GCELLS (GC*GC)
#define GH 0.03125f
__device__ int g_cellstart[BQ][GCELLS + 1];
__device__ __align__(16) float4 g_spt[BQ][LM];   // sorted {x, y, bits(idx), 0}

// ---------------------------------------------------------------------------
#define LDA 136
#define LDB 136
#define LDH 264
#define M1_A  0
#define M1_WB (64 * LDA)
#define SMEM_MLP1 ((M1_WB + 256 * LDB) * 2)
// mlp2: AH 128xLDH (67584B) + WB0 256xLDB (69632B) + WB1 (69632B) = 206848B
#define M2_A   0
#define M2_WB0 (128 * LDH)
#define M2_WB1 (M2_WB0 + 256 * LDB)
#define SMEM_MLP2 ((M2_WB1 + 256 * LDB) * 2)

__device__ __forceinline__ void mma_bf16(float c[4],
    uint32_t a0, uint32_t a1, uint32_t a2, uint32_t a3,
    uint32_t b0, uint32_t b1)
{
    asm volatile(
        "mma.sync.aligned.m16n8k16.row.col.f32.bf16.bf16.f32 "
        "{%0,%1,%2,%3}, {%4,%5,%6,%7}, {%8,%9}, {%0,%1,%2,%3};"
        : "+f"(c[0]), "+f"(c[1]), "+f"(c[2]), "+f"(c[3])
        : "r"(a0), "r"(a1), "r"(a2), "r"(a3), "r"(b0), "r"(b1));
}

__device__ __forceinline__ void cp16(uint32_t smem, const void* g) {
    asm volatile("cp.async.cg.shared.global [%0], [%1], 16;" :: "r"(smem), "l"(g));
}
#define CP_COMMIT() asm volatile("cp.async.commit_group;" ::: "memory")
#define CP_WAIT(n)  asm volatile("cp.async.wait_group %0;" :: "n"(n) : "memory")

__device__ __forceinline__ uint32_t f2ord(float f) {
    uint32_t u = __float_as_uint(f);
    return u ^ ((uint32_t)((int)u >> 31) | 0x80000000u);
}
__device__ __forceinline__ float ord2f(uint32_t o) {
    uint32_t u = o ^ ((uint32_t)((int)(~o) >> 31) | 0x80000000u);
    return __uint_as_float(u);
}

// ---------------------------------------------------------------------------
// Kernel 0: weight prep (unchanged)
// ---------------------------------------------------------------------------
__global__ void prep_weights(const float* __restrict__ Wq1, const float* __restrict__ Wq2,
                             const float* __restrict__ Wk1, const float* __restrict__ Wk2)
{
    int idx = blockIdx.x * 256 + threadIdx.x;
    {
        int n = idx >> 8, k = idx & 255;
        g_w2t_q[idx] = __float2bfloat16(Wq2[k * 256 + n]);
        g_w2t_k[idx] = __float2bfloat16(Wk2[k * 256 + n]);
    }
    if (idx < 32768) {
        int n = idx >> 7, k = idx & 127;
        g_w1t_q[idx] = __float2bfloat16(Wq1[k * 256 + n]);
        g_w1t_k[idx] = __float2bfloat16(Wk1[k * 256 + n]);
    }
}

// ---------------------------------------------------------------------------
// Kernel 0b: spatial grid build (unchanged)
// ---------------------------------------------------------------------------
__global__ void __launch_bounds__(1024, 1) grid_build(const float* __restrict__ mem_coor)
{
    __shared__ int hist[GCELLS];
    __shared__ int scn[GCELLS];
    const int b = blockIdx.x, tid = threadIdx.x;
    hist[tid] = 0;
    __syncthreads();

    const float2* mc = (const float2*)(mem_coor + (size_t)b * LM * 2);
    int cellid[8]; float2 pt[8];
    #pragma unroll
    for (int i = 0; i < 8; ++i) {
        int p = tid + i * 1024;
        float2 c = mc[p];
        int cx = min(GC - 1, (int)(c.x * (float)GC));
        int cy = min(GC - 1, (int)(c.y * (float)GC));
        cellid[i] = cy * GC + cx; pt[i] = c;
        atomicAdd(&hist[cellid[i]], 1);
    }
    __syncthreads();

    int v = hist[tid];
    scn[tid] = v;
    __syncthreads();
    for (int off = 1; off < GCELLS; off <<= 1) {
        int t = (tid >= off) ? scn[tid - off] : 0;
        __syncthreads();
        scn[tid] += t;
        __syncthreads();
    }
    int excl = scn[tid] - v;
    g_cellstart[b][tid] = excl;
    if (tid == GCELLS - 1) g_cellstart[b][GCELLS] = LM;
    hist[tid] = excl;
    __syncthreads();

    #pragma unroll
    for (int i = 0; i < 8; ++i) {
        int p = tid + i * 1024;
        int pos = atomicAdd(&hist[cellid[i]], 1);
        g_spt[b][pos] = make_float4(pt[i].x, pt[i].y, __int_as_float(p), 0.0f);
    }
}

// ---------------------------------------------------------------------------
// Kernel 1a: posemb + layer 1 (unchanged)
// ---------------------------------------------------------------------------
__global__ void __launch_bounds__(256, 2) mlp1_kernel(
    const float* __restrict__ q_coor, const float* __restrict__ mem_coor,
    const float* __restrict__ bq1, const float* __restrict__ bk1)
{
    extern __shared__ __nv_bfloat16 sm[];
    const int tid = threadIdx.x;
    const int w = tid >> 5, lane = tid & 31;
    const int wr = w >> 2, wc = w & 3;
    const int lr = lane >> 2, lc = lane & 3;

    const bool KV = blockIdx.x >= 256;
    const int lrow0 = (KV ? (blockIdx.x - 256) : blockIdx.x) * 64;
    const int grow0 = KV ? (NROW_Q + lrow0) : lrow0;
    const float* coor = KV ? mem_coor : q_coor;
    const __nv_bfloat16* w1t = KV ? g_w1t_k : g_w1t_q;
    const float* b1 = KV ? bk1 : bq1;

    for (int p = tid; p < 64 * 64; p += 256) {
        int r = p >> 6, pp = p & 63;
        int half = pp >> 5, j = pp & 31;
        float coord = coor[2 * (lrow0 + r) + (half ? 0 : 1)];
        float freq = exp2f(-(float)j * 0.4152410118609203f);
        float v = coord * 6.283185307179586477f * freq;
        float sv, cv;
        sincosf(v, &sv, &cv);
        *(__nv_bfloat162*)(sm + M1_A + r * LDA + half * 64 + 2 * j) =
            __floats2bfloat162_rn(sv, cv);
    }
    for (int p = tid; p < 256 * 16; p += 256) {
        int n = p >> 4, ch = p & 15;
        *(uint4*)(sm + M1_WB + n * LDB + ch * 8) = *(const uint4*)(w1t + n * 128 + ch * 8);
    }
    __syncthreads();

    float c1[2][8][4];
    #pragma unroll
    for (int mi = 0; mi < 2; ++mi)
        #pragma unroll
        for (int ni = 0; ni < 8; ++ni)
            #pragma unroll
            for (int q = 0; q < 4; ++q) c1[mi][ni][q] = 0.0f;

    #pragma unroll
    for (int ks = 0; ks < 8; ++ks) {
        const int k0 = ks * 16;
        uint32_t a[2][4], b[8][2];
        #pragma unroll
        for (int mi = 0; mi < 2; ++mi) {
            const __nv_bfloat16* ap = sm + M1_A + (wr * 32 + mi * 16 + lr) * LDA + k0 + lc * 2;
            a[mi][0] = *(const uint32_t*)ap;
            a[mi][1] = *(const uint32_t*)(ap + 8 * LDA);
            a[mi][2] = *(const uint32_t*)(ap + 8);
            a[mi][3] = *(const uint32_t*)(ap + 8 * LDA + 8);
        }
        #pragma unroll
        for (int ni = 0; ni < 8; ++ni) {
            const __nv_bfloat16* bp = sm + M1_WB + (wc * 64 + ni * 8 + lr) * LDB + k0 + lc * 2;
            b[ni][0] = *(const uint32_t*)bp;
            b[ni][1] = *(const uint32_t*)(bp + 8);
        }
        #pragma unroll
        for (int mi = 0; mi < 2; ++mi)
            #pragma unroll
            for (int ni = 0; ni < 8; ++ni)
                mma_bf16(c1[mi][ni], a[mi][0], a[mi][1], a[mi][2], a[mi][3],
                         b[ni][0], b[ni][1]);
    }

    #pragma unroll
    for (int mi = 0; mi < 2; ++mi)
        #pragma unroll
        for (int ni = 0; ni < 8; ++ni) {
            int col = wc * 64 + ni * 8 + lc * 2;
            int row = grow0 + wr * 32 + mi * 16 + lr;
            float bl = __ldg(&b1[col]), bh = __ldg(&b1[col + 1]);
            float v0 = fmaxf(c1[mi][ni][0] + bl, 0.0f);
            float v1 = fmaxf(c1[mi][ni][1] + bh, 0.0f);
            float v2 = fmaxf(c1[mi][ni][2] + bl, 0.0f);
            float v3 = fmaxf(c1[mi][ni][3] + bh, 0.0f);
            *(__nv_bfloat162*)(g_h + (size_t)row * 256 + col) = __floats2bfloat162_rn(v0, v1);
            *(__nv_bfloat162*)(g_h + (size_t)(row + 8) * 256 + col) = __floats2bfloat162_rn(v2, v3);
        }
}

// ---------------------------------------------------------------------------
// Kernel 1b: layer 2, cp.async double-buffered weights, M-tile 128.
// AH staged in K-halves: chunk-0 compute starts after AHlo+WB0 only.
// ---------------------------------------------------------------------------
__global__ void __launch_bounds__(512, 1) mlp2_kernel(
    const float* __restrict__ bq2, const float* __restrict__ bk2,
    const float* __restrict__ memory)
{
    extern __shared__ __nv_bfloat16 sm[];
    const uint32_t smb = (uint32_t)__cvta_generic_to_shared(sm);
    const int tid = threadIdx.x;
    const int w = tid >> 5, lane = tid & 31;
    const int wr = w >> 2, wc = w & 3;
    const int lr = lane >> 2, lc = lane & 3;

    const int grow0 = blockIdx.x * 128;
    const bool KV = grow0 >= NROW_Q;
    const __nv_bfloat16* w2t = KV ? g_w2t_k : g_w2t_q;
    const float* b2 = KV ? bk2 : bq2;

    // group0: AH lo-half (cols 0..127) + WB0 ; group1: AH hi-half + WB1
    for (int p = tid; p < 128 * 16; p += 512) {
        int r = p >> 4, ch = p & 15;
        cp16(smb + (M2_A + r * LDH + ch * 8) * 2,
             g_h + (size_t)(grow0 + r) * 256 + ch * 8);
    }
    for (int p = tid; p < 256 * 16; p += 512) {
        int n = p >> 4, ch = p & 15;
        cp16(smb + (M2_WB0 + n * LDB + ch * 8) * 2, w2t + n * 256 + ch * 8);
    }
    CP_COMMIT();
    for (int p = tid; p < 128 * 16; p += 512) {
        int r = p >> 4, ch = (p & 15) + 16;
        cp16(smb + (M2_A + r * LDH + ch * 8) * 2,
             g_h + (size_t)(grow0 + r) * 256 + ch * 8);
    }
    for (int p = tid; p < 256 * 16; p += 512) {
        int n = p >> 4, ch = p & 15;
        cp16(smb + (M2_WB1 + n * LDB + ch * 8) * 2, w2t + n * 256 + 128 + ch * 8);
    }
    CP_COMMIT();

    float c2[2][8][4];
    #pragma unroll
    for (int mi = 0; mi < 2; ++mi)
        #pragma unroll
        for (int ni = 0; ni < 8; ++ni)
            #pragma unroll
            for (int q = 0; q < 4; ++q) c2[mi][ni][q] = 0.0f;

    CP_WAIT(1);          // AHlo + WB0 resident
    __syncthreads();

    #pragma unroll 1
    for (int chunk = 0; chunk < 2; ++chunk) {
        const int wb = chunk ? M2_WB1 : M2_WB0;
        #pragma unroll
        for (int ks = 0; ks < 8; ++ks) {
            const int kg = chunk * 128 + ks * 16;
            const int kl = ks * 16;
            uint32_t a[2][4], b[8][2];
            #pragma unroll
            for (int mi = 0; mi < 2; ++mi) {
                const __nv_bfloat16* ap = sm + M2_A + (wr * 32 + mi * 16 + lr) * LDH + kg + lc * 2;
                a[mi][0] = *(const uint32_t*)ap;
                a[mi][1] = *(const uint32_t*)(ap + 8 * LDH);
                a[mi][2] = *(const uint32_t*)(ap + 8);
                a[mi][3] = *(const uint32_t*)(ap + 8 * LDH + 8);
            }
            #pragma unroll
            for (int ni = 0; ni < 8; ++ni) {
                const __nv_bfloat16* bp = sm + wb + (wc * 64 + ni * 8 + lr) * LDB + kl + lc * 2;
                b[ni][0] = *(const uint32_t*)bp;
                b[ni][1] = *(const uint32_t*)(bp + 8);
            }
            #pragma unroll
            for (int mi = 0; mi < 2; ++mi)
                #pragma unroll
                for (int ni = 0; ni < 8; ++ni)
                    mma_bf16(c2[mi][ni], a[mi][0], a[mi][1], a[mi][2], a[mi][3],
                             b[ni][0], b[ni][1]);
        }
        if (chunk == 0) { CP_WAIT(0); __syncthreads(); }
    }

    #pragma unroll
    for (int mi = 0; mi < 2; ++mi)
        #pragma unroll
        for (int ni = 0; ni < 8; ++ni) {
            int col = wc * 64 + ni * 8 + lc * 2;
            int g = grow0 + wr * 32 + mi * 16 + lr;
            float bl = __ldg(&b2[col]), bh = __ldg(&b2[col + 1]);
            float2 v0 = make_float2(c2[mi][ni][0] + bl, c2[mi][ni][1] + bh);
            float2 v1 = make_float2(c2[mi][ni][2] + bl, c2[mi][ni][3] + bh);
            if (KV) {
                size_t l0 = (size_t)(g - NROW_Q) * 256 + col;
                size_t l1 = (size_t)(g + 8 - NROW_Q) * 256 + col;
                float2 m0 = *(const float2*)(memory + l0);
                float2 m1 = *(const float2*)(memory + l1);
                v0.x += m0.x; v0.y += m0.y; v1.x += m1.x; v1.y += m1.y;
                *(float2*)(g_kv + l0) = v0;
                *(float2*)(g_kv + l1) = v1;
            } else {
                *(float2*)(g_q + (size_t)g * 256 + col) = v0;
                *(float2*)(g_q + (size_t)(g + 8) * 256 + col) = v1;
            }
        }
}

// ---------------------------------------------------------------------------
// Kernel 2: exact top-16 via spatial grid (unchanged)
// ---------------------------------------------------------------------------
#define TKCAP 320
__global__ void __launch_bounds__(256) topk_kernel(
    const float* __restrict__ q_coor)
{
    __shared__ unsigned long long sbuf[8][TKCAP + 16];

    const int wid = threadIdx.x >> 5, lane = threadIdx.x & 31;
    const int b = blockIdx.y;
    const int s = blockIdx.x * 8 + wid;
    const int qn = b * SQ + s;
    const float qx = q_coor[2 * qn], qy = q_coor[2 * qn + 1];
    const float q2 = __fadd_rn(__fmul_rn(qx, qx), __fmul_rn(qy, qy));
    const int cx = min(GC - 1, (int)(qx * (float)GC));
    const int cy = min(GC - 1, (int)(qy * (float)GC));
    const int* cs = g_cellstart[b];
    const float4* spt = g_spt[b];
    unsigned long long* buf = sbuf[wid];

    const unsigned long long UMAX = 0xFFFFFFFFFFFFFFFFull;
    unsigned long long bestk = UMAX;
    float tau = __int_as_float(0x7f800000);
    int cnt = 0;

    auto select16 = [&]() {
        unsigned valid = __ballot_sync(0xffffffffu, lane < 16 && bestk != UMAX);
        if (lane < 16 && bestk != UMAX) buf[cnt + lane] = bestk;
        cnt += __popc(valid);
        const int nper = (cnt + 31) >> 5;
        unsigned long long nb = UMAX;
        #pragma unroll 1
        for (int r = 0; r < 16; ++r) {
            unsigned long long mk = UMAX; int mj = 0;
            for (int i = 0; i < nper; ++i) {
                int j = lane + i * 32;
                if (j < cnt) {
                    unsigned long long v = buf[j];
                    if (v < mk) { mk = v; mj = j; }
                }
            }
            unsigned long long rk = mk; int rl = lane;
            #pragma unroll
            for (int off = 16; off; off >>= 1) {
                unsigned long long ok = __shfl_down_sync(0xffffffffu, rk, off);
                int ol = __shfl_down_sync(0xffffffffu, rl, off);
                if (ok < rk) { rk = ok; rl = ol; }
            }
            rk = __shfl_sync(0xffffffffu, rk, 0);
            rl = __shfl_sync(0xffffffffu, rl, 0);
            if (rk == UMAX) break;
            if (lane == r) nb = rk;
            if (lane == rl) buf[mj] = UMAX;
        }
        bestk = nb;
        unsigned long long k15 = __shfl_sync(0xffffffffu, bestk, 15);
        tau = (k15 == UMAX) ? __int_as_float(0x7f800000)
                            : ord2f((uint32_t)(k15 >> 32));
        cnt = 0;
    };

    auto scan_range = [&](int s0, int e0) {
        for (int j0 = s0; j0 < e0; j0 += 32) {
            const int j = j0 + lane;
            const bool valid = j < e0;
            float d2 = 0.0f; int oi = 0;
            if (valid) {
                float4 p = __ldg(&spt[j]);
                float m2 = __fadd_rn(__fmul_rn(p.x, p.x), __fmul_rn(p.y, p.y));
                float dt = __fmaf_rn(qy, p.y, __fmul_rn(qx, p.x));
                d2 = __fsub_rn(__fadd_rn(q2, m2), __fmul_rn(2.0f, dt));
                oi = __float_as_int(p.z);
            }
            bool acc = valid && (d2 < tau);
            unsigned mask = __ballot_sync(0xffffffffu, acc);
            if (!mask) continue;
            int nacc = __popc(mask);
            if (cnt + nacc > TKCAP) {
                select16();
                acc = valid && (d2 < tau);
                mask = __ballot_sync(0xffffffffu, acc);
                nacc = __popc(mask);
            }
            if (acc) {
                int pos = cnt + __popc(mask & ((1u << lane) - 1u));
                buf[pos] = ((unsigned long long)f2ord(d2) << 32) | (uint32_t)oi;
            }
            cnt += nacc;
        }
    };

    {
        int x0 = max(0, cx - 1), x1 = min(GC - 1, cx + 1);
        int y0 = max(0, cy - 1), y1 = min(GC - 1, cy + 1);
        for (int y = y0; y <= y1; ++y)
            scan_range(__ldg(&cs[y * GC + x0]), __ldg(&cs[y * GC + x1 + 1]));
        select16();
    }

    int R = 1;
    while (true) {
        float bound = (float)R * GH;
        bool full = (cx - R <= 0) && (cx + R >= GC - 1) &&
                    (cy - R <= 0) && (cy + R >= GC - 1);
        if (full || tau < bound * bound - 2e-6f) break;
        ++R;
        const int nx0 = max(0, cx - R), nx1 = min(GC - 1, cx + R);
        if (cy - R >= 0)
            scan_range(__ldg(&cs[(cy - R) * GC + nx0]), __ldg(&cs[(cy - R) * GC + nx1 + 1]));
        if (cy + R <= GC - 1)
            scan_range(__ldg(&cs[(cy + R) * GC + nx0]), __ldg(&cs[(cy + R) * GC + nx1 + 1]));
        const int my0 = max(0, cy - R + 1), my1 = min(GC - 1, cy + R - 1);
        for (int y = my0; y <= my1; ++y) {
            if (cx - R >= 0)
                scan_range(__ldg(&cs[y * GC + cx - R]), __ldg(&cs[y * GC + cx - R + 1]));
            if (cx + R <= GC - 1)
                scan_range(__ldg(&cs[y * GC + cx + R]), __ldg(&cs[y * GC + cx + R + 1]));
        }
        if (cnt > 0) select16();
    }

    if (lane < 16) g_idx[qn * 16 + lane] = (int)(uint32_t)bestk;
}

// ---------------------------------------------------------------------------
// Kernel 3: gather + softmax over D + multiply.
// No max-subtraction (logits are O(0.3): exp(p)/sum(exp(p)) is overflow-safe
// and equals the max-subtracted form to ~1ulp). Streaming stores (__stcs)
// keep the 268MB output from evicting hot kv/memory rows out of L2.
// ---------------------------------------------------------------------------
__global__ void __launch_bounds__(128, 1) attn_kernel(
    const float* __restrict__ memory, float* __restrict__ out)
{
    const int s = blockIdx.x, b = blockIdx.y;
    const int qn = b * SQ + s;
    const int w = threadIdx.x >> 5, lane = threadIdx.x & 31;

    const float4* qp = (const float4*)(g_q + (size_t)qn * 256);
    const float4 q0 = qp[lane * 2], q1 = qp[lane * 2 + 1];

    #pragma unroll
    for (int jj = 0; jj < 4; jj += 2) {
        const int j0 = w * 4 + jj;
        const int idx0 = __ldg(&g_idx[qn * 16 + j0]);
        const int idx1 = __ldg(&g_idx[qn * 16 + j0 + 1]);

        const float4* kvp0 = (const float4*)(g_kv + ((size_t)b * LM + idx0) * 256);
        const float4* kvp1 = (const float4*)(g_kv + ((size_t)b * LM + idx1) * 256);
        float4 ka0 = kvp0[lane * 2], ka1 = kvp0[lane * 2 + 1];
        float4 kb0 = kvp1[lane * 2], kb1 = kvp1[lane * 2 + 1];

        float pa[8], pb[8];
        pa[0] = q0.x * ka0.x; pa[1] = q0.y * ka0.y; pa[2] = q0.z * ka0.z; pa[3] = q0.w * ka0.w;
        pa[4] = q1.x * ka1.x; pa[5] = q1.y * ka1.y; pa[6] = q1.z * ka1.z; pa[7] = q1.w * ka1.w;
        pb[0] = q0.x * kb0.x; pb[1] = q0.y * kb0.y; pb[2] = q0.z * kb0.z; pb[3] = q0.w * kb0.w;
        pb[4] = q1.x * kb1.x; pb[5] = q1.y * kb1.y; pb[6] = q1.z * kb1.z; pb[7] = q1.w * kb1.w;

        float sa = 0.0f, sb = 0.0f;
        #pragma unroll
        for (int i = 0; i < 8; ++i) {
            pa[i] = __expf(pa[i] * 0.0625f); sa += pa[i];
            pb[i] = __expf(pb[i] * 0.0625f); sb += pb[i];
        }
        #pragma unroll
        for (int off = 16; off; off >>= 1) {
            sa += __shfl_xor_sync(0xffffffffu, sa, off);
            sb += __shfl_xor_sync(0xffffffffu, sb, off);
        }
        const float ia = __frcp_rn(sa), ib = __frcp_rn(sb);

        const float4* mp0 = (const float4*)(memory + ((size_t)b * LM + idx0) * 256);
        const float4* mp1 = (const float4*)(memory + ((size_t)b * LM + idx1) * 256);
        float4 ma0 = mp0[lane * 2], ma1 = mp0[lane * 2 + 1];
        float4 mb0 = mp1[lane * 2], mb1 = mp1[lane * 2 + 1];

        float4 r;
        float4* op0 = (float4*)(out + ((size_t)(qn * 16 + j0)) * 256);
        float4* op1 = (float4*)(out + ((size_t)(qn * 16 + j0 + 1)) * 256);
        r.x = pa[0] * ia * ma0.x; r.y = pa[1] * ia * ma0.y;
        r.z = pa[2] * ia * ma0.z; r.w = pa[3] * ia * ma0.w;
        __stcs(&op0[lane * 2], r);
        r.x = pa[4] * ia * ma1.x; r.y = pa[5] * ia * ma1.y;
        r.z = pa[6] * ia * ma1.z; r.w = pa[7] * ia * ma1.w;
        __stcs(&op0[lane * 2 + 1], r);
        r.x = pb[0] * ib * mb0.x; r.y = pb[1] * ib * mb0.y;
        r.z = pb[2] * ib * mb0.z; r.w = pb[3] * ib * mb0.w;
        __stcs(&op1[lane * 2], r);
        r.x = pb[4] * ib * mb1.x; r.y = pb[5] * ib * mb1.y;
        r.z = pb[6] * ib * mb1.z; r.w = pb[7] * ib * mb1.w;
        __stcs(&op1[lane * 2 + 1], r);
    }
}

// ---------------------------------------------------------------------------

extern "C" void kernel_launch(void* const* d_in, const int* in_sizes, int n_in,
                              void* d_out, int out_size)
{
    const float* memory   = (const float*)d_in[0];
    const float* mem_coor = (const float*)d_in[1];
    const float* q_coor   = (const float*)d_in[2];
    const float* Wq1 = (const float*)d_in[3];
    const float* bq1 = (const float*)d_in[4];
    const float* Wq2 = (const float*)d_in[5];
    const float* bq2 = (const float*)d_in[6];
    const float* Wk1 = (const float*)d_in[7];
    const float* bk1 = (const float*)d_in[8];
    const float* Wk2 = (const float*)d_in[9];
    const float* bk2 = (const float*)d_in[10];
    float* out = (float*)d_out;

    cudaFuncSetAttribute(mlp1_kernel,
        cudaFuncAttributeMaxDynamicSharedMemorySize, SMEM_MLP1);
    cudaFuncSetAttribute(mlp2_kernel,
        cudaFuncAttributeMaxDynamicSharedMemorySize, SMEM_MLP2);

    // K0: weight transpose + bf16; spatial grid build
    prep_weights<<<256, 256>>>(Wq1, Wq2, Wk1, Wk2);
    grid_build<<<BQ, 1024>>>(mem_coor);

    // K1: MLP layers
    mlp1_kernel<<<768, 256, SMEM_MLP1>>>(q_coor, mem_coor, bq1, bk1);
    mlp2_kernel<<<NROW_T / 128, 512, SMEM_MLP2>>>(bq2, bk2, memory);

    // K2: top-16 neighbors via spatial grid
    topk_kernel<<<dim3(SQ / 8, BQ), 256>>>(q_coor);

    // K3: gather + softmax(D) + multiply
    attn_kernel<<<dim3(SQ, BQ), 128>>>(memory, out);
}

// round 16
// speedup vs baseline: 4.6243x; 1.0495x over previous
#include <cuda_runtime.h>
#include <cuda_bf16.h>
#include <cstdint>

#define BQ  4
#define SQ  4096
#define LM  8192
#define DD  256
#define KNN 16
#define NROW_Q (BQ*SQ)          /* 16384 */
#define NROW_T (BQ*(SQ+LM))     /* 49152 total MLP rows */

// Scratch (device globals: allocation-free, graph-capture safe)
__device__ __align__(16) __nv_bfloat16 g_q [(size_t)BQ*SQ*DD];  // 8 MB  (bf16)
__device__ __align__(16) __nv_bfloat16 g_kv[(size_t)BQ*LM*DD];  // 16 MB (bf16)
__device__ int   g_idx[BQ*SQ*KNN];                              // 1 MB
__device__ __align__(16) __nv_bfloat16 g_h[(size_t)NROW_T*DD];  // 24 MB hidden
// bf16 transposed weights
__device__ __align__(16) __nv_bfloat16 g_w1t_q[256*128];
__device__ __align__(16) __nv_bfloat16 g_w2t_q[256*256];
__device__ __align__(16) __nv_bfloat16 g_w1t_k[256*128];
__device__ __align__(16) __nv_bfloat16 g_w2t_k[256*256];
// spatial grid (32x32 cells per batch)
#define GC 32
#define GCELLS (GC*GC)
#define GH 0.03125f
__device__ int g_cellstart[BQ][GCELLS + 1];
__device__ __align__(16) float4 g_spt[BQ][LM];   // sorted {x, y, bits(idx), 0}

// ---------------------------------------------------------------------------
#define LDA 136
#define LDB 136
#define LDH 264
#define LDW 264
#define M1_A  0
#define M1_WB (64 * LDA)
#define SMEM_MLP1 ((M1_WB + 256 * LDB) * 2)
// mlp2: AH 64xLDH (33792B) + W 128xLDW (67584B) = 101376B -> 2 CTA/SM
#define M2_A 0
#define M2_W (64 * LDH)
#define SMEM_MLP2 ((M2_W + 128 * LDW) * 2)

__device__ __forceinline__ void mma_bf16(float c[4],
    uint32_t a0, uint32_t a1, uint32_t a2, uint32_t a3,
    uint32_t b0, uint32_t b1)
{
    asm volatile(
        "mma.sync.aligned.m16n8k16.row.col.f32.bf16.bf16.f32 "
        "{%0,%1,%2,%3}, {%4,%5,%6,%7}, {%8,%9}, {%0,%1,%2,%3};"
        : "+f"(c[0]), "+f"(c[1]), "+f"(c[2]), "+f"(c[3])
        : "r"(a0), "r"(a1), "r"(a2), "r"(a3), "r"(b0), "r"(b1));
}

__device__ __forceinline__ void cp16(uint32_t smem, const void* g) {
    asm volatile("cp.async.cg.shared.global [%0], [%1], 16;" :: "r"(smem), "l"(g));
}
#define CP_COMMIT() asm volatile("cp.async.commit_group;" ::: "memory")
#define CP_WAIT(n)  asm volatile("cp.async.wait_group %0;" :: "n"(n) : "memory")

__device__ __forceinline__ uint32_t f2ord(float f) {
    uint32_t u = __float_as_uint(f);
    return u ^ ((uint32_t)((int)u >> 31) | 0x80000000u);
}
__device__ __forceinline__ float ord2f(uint32_t o) {
    uint32_t u = o ^ ((uint32_t)((int)(~o) >> 31) | 0x80000000u);
    return __uint_as_float(u);
}
__device__ __forceinline__ void bf2x(float& lo, float& hi, uint32_t u) {
    float2 f = __bfloat1622float2(*(__nv_bfloat162*)&u);
    lo = f.x; hi = f.y;
}

// ---------------------------------------------------------------------------
// Kernel 0: weight prep (unchanged)
// ---------------------------------------------------------------------------
__global__ void prep_weights(const float* __restrict__ Wq1, const float* __restrict__ Wq2,
                             const float* __restrict__ Wk1, const float* __restrict__ Wk2)
{
    int idx = blockIdx.x * 256 + threadIdx.x;
    {
        int n = idx >> 8, k = idx & 255;
        g_w2t_q[idx] = __float2bfloat16(Wq2[k * 256 + n]);
        g_w2t_k[idx] = __float2bfloat16(Wk2[k * 256 + n]);
    }
    if (idx < 32768) {
        int n = idx >> 7, k = idx & 127;
        g_w1t_q[idx] = __float2bfloat16(Wq1[k * 256 + n]);
        g_w1t_k[idx] = __float2bfloat16(Wk1[k * 256 + n]);
    }
}

// ---------------------------------------------------------------------------
// Kernel 0b: spatial grid build (unchanged)
// ---------------------------------------------------------------------------
__global__ void __launch_bounds__(1024, 1) grid_build(const float* __restrict__ mem_coor)
{
    __shared__ int hist[GCELLS];
    __shared__ int scn[GCELLS];
    const int b = blockIdx.x, tid = threadIdx.x;
    hist[tid] = 0;
    __syncthreads();

    const float2* mc = (const float2*)(mem_coor + (size_t)b * LM * 2);
    int cellid[8]; float2 pt[8];
    #pragma unroll
    for (int i = 0; i < 8; ++i) {
        int p = tid + i * 1024;
        float2 c = mc[p];
        int cx = min(GC - 1, (int)(c.x * (float)GC));
        int cy = min(GC - 1, (int)(c.y * (float)GC));
        cellid[i] = cy * GC + cx; pt[i] = c;
        atomicAdd(&hist[cellid[i]], 1);
    }
    __syncthreads();

    int v = hist[tid];
    scn[tid] = v;
    __syncthreads();
    for (int off = 1; off < GCELLS; off <<= 1) {
        int t = (tid >= off) ? scn[tid - off] : 0;
        __syncthreads();
        scn[tid] += t;
        __syncthreads();
    }
    int excl = scn[tid] - v;
    g_cellstart[b][tid] = excl;
    if (tid == GCELLS - 1) g_cellstart[b][GCELLS] = LM;
    hist[tid] = excl;
    __syncthreads();

    #pragma unroll
    for (int i = 0; i < 8; ++i) {
        int p = tid + i * 1024;
        int pos = atomicAdd(&hist[cellid[i]], 1);
        g_spt[b][pos] = make_float4(pt[i].x, pt[i].y, __int_as_float(p), 0.0f);
    }
}

// ---------------------------------------------------------------------------
// Kernel 1a: posemb + layer 1 (unchanged)
// ---------------------------------------------------------------------------
__global__ void __launch_bounds__(256, 2) mlp1_kernel(
    const float* __restrict__ q_coor, const float* __restrict__ mem_coor,
    const float* __restrict__ bq1, const float* __restrict__ bk1)
{
    extern __shared__ __nv_bfloat16 sm[];
    const int tid = threadIdx.x;
    const int w = tid >> 5, lane = tid & 31;
    const int wr = w >> 2, wc = w & 3;
    const int lr = lane >> 2, lc = lane & 3;

    const bool KV = blockIdx.x >= 256;
    const int lrow0 = (KV ? (blockIdx.x - 256) : blockIdx.x) * 64;
    const int grow0 = KV ? (NROW_Q + lrow0) : lrow0;
    const float* coor = KV ? mem_coor : q_coor;
    const __nv_bfloat16* w1t = KV ? g_w1t_k : g_w1t_q;
    const float* b1 = KV ? bk1 : bq1;

    for (int p = tid; p < 64 * 64; p += 256) {
        int r = p >> 6, pp = p & 63;
        int half = pp >> 5, j = pp & 31;
        float coord = coor[2 * (lrow0 + r) + (half ? 0 : 1)];
        float freq = exp2f(-(float)j * 0.4152410118609203f);
        float v = coord * 6.283185307179586477f * freq;
        float sv, cv;
        sincosf(v, &sv, &cv);
        *(__nv_bfloat162*)(sm + M1_A + r * LDA + half * 64 + 2 * j) =
            __floats2bfloat162_rn(sv, cv);
    }
    for (int p = tid; p < 256 * 16; p += 256) {
        int n = p >> 4, ch = p & 15;
        *(uint4*)(sm + M1_WB + n * LDB + ch * 8) = *(const uint4*)(w1t + n * 128 + ch * 8);
    }
    __syncthreads();

    float c1[2][8][4];
    #pragma unroll
    for (int mi = 0; mi < 2; ++mi)
        #pragma unroll
        for (int ni = 0; ni < 8; ++ni)
            #pragma unroll
            for (int q = 0; q < 4; ++q) c1[mi][ni][q] = 0.0f;

    #pragma unroll
    for (int ks = 0; ks < 8; ++ks) {
        const int k0 = ks * 16;
        uint32_t a[2][4], b[8][2];
        #pragma unroll
        for (int mi = 0; mi < 2; ++mi) {
            const __nv_bfloat16* ap = sm + M1_A + (wr * 32 + mi * 16 + lr) * LDA + k0 + lc * 2;
            a[mi][0] = *(const uint32_t*)ap;
            a[mi][1] = *(const uint32_t*)(ap + 8 * LDA);
            a[mi][2] = *(const uint32_t*)(ap + 8);
            a[mi][3] = *(const uint32_t*)(ap + 8 * LDA + 8);
        }
        #pragma unroll
        for (int ni = 0; ni < 8; ++ni) {
            const __nv_bfloat16* bp = sm + M1_WB + (wc * 64 + ni * 8 + lr) * LDB + k0 + lc * 2;
            b[ni][0] = *(const uint32_t*)bp;
            b[ni][1] = *(const uint32_t*)(bp + 8);
        }
        #pragma unroll
        for (int mi = 0; mi < 2; ++mi)
            #pragma unroll
            for (int ni = 0; ni < 8; ++ni)
                mma_bf16(c1[mi][ni], a[mi][0], a[mi][1], a[mi][2], a[mi][3],
                         b[ni][0], b[ni][1]);
    }

    #pragma unroll
    for (int mi = 0; mi < 2; ++mi)
        #pragma unroll
        for (int ni = 0; ni < 8; ++ni) {
            int col = wc * 64 + ni * 8 + lc * 2;
            int row = grow0 + wr * 32 + mi * 16 + lr;
            float bl = __ldg(&b1[col]), bh = __ldg(&b1[col + 1]);
            float v0 = fmaxf(c1[mi][ni][0] + bl, 0.0f);
            float v1 = fmaxf(c1[mi][ni][1] + bh, 0.0f);
            float v2 = fmaxf(c1[mi][ni][2] + bl, 0.0f);
            float v3 = fmaxf(c1[mi][ni][3] + bh, 0.0f);
            *(__nv_bfloat162*)(g_h + (size_t)row * 256 + col) = __floats2bfloat162_rn(v0, v1);
            *(__nv_bfloat162*)(g_h + (size_t)(row + 8) * 256 + col) = __floats2bfloat162_rn(v2, v3);
        }
}

// ---------------------------------------------------------------------------
// Kernel 1b: layer 2. M64 x N128 tiles, 256 threads, 99KB smem -> 2 CTA/SM.
// Grid (768 row-tiles, 2 N-halves). 8 warps as 2(wr)x4(wc); warp tile 32x32.
// Outputs bf16 to g_q / g_kv (kv = mlp + memory added in fp32, then bf16).
// ---------------------------------------------------------------------------
__global__ void __launch_bounds__(256, 2) mlp2_kernel(
    const float* __restrict__ bq2, const float* __restrict__ bk2,
    const float* __restrict__ memory)
{
    extern __shared__ __nv_bfloat16 sm[];
    const uint32_t smb = (uint32_t)__cvta_generic_to_shared(sm);
    const int tid = threadIdx.x;
    const int w = tid >> 5, lane = tid & 31;
    const int wr = w >> 2, wc = w & 3;
    const int lr = lane >> 2, lc = lane & 3;

    const int grow0 = blockIdx.x * 64;
    const int nh = blockIdx.y;       // N half: cols [nh*128, nh*128+128)
    const bool KV = grow0 >= NROW_Q;
    const __nv_bfloat16* w2t = (KV ? g_w2t_k : g_w2t_q) + (size_t)nh * 128 * 256;
    const float* b2 = (KV ? bk2 : bq2) + nh * 128;

    // prologue: AH (64x256) + W (128x256) via cp.async, one group
    for (int p = tid; p < 64 * 32; p += 256) {
        int r = p >> 5, ch = p & 31;
        cp16(smb + (M2_A + r * LDH + ch * 8) * 2,
             g_h + (size_t)(grow0 + r) * 256 + ch * 8);
    }
    for (int p = tid; p < 128 * 32; p += 256) {
        int n = p >> 5, ch = p & 31;
        cp16(smb + (M2_W + n * LDW + ch * 8) * 2, w2t + n * 256 + ch * 8);
    }
    CP_COMMIT();

    float c2[2][4][4];
    #pragma unroll
    for (int mi = 0; mi < 2; ++mi)
        #pragma unroll
        for (int ni = 0; ni < 4; ++ni)
            #pragma unroll
            for (int q = 0; q < 4; ++q) c2[mi][ni][q] = 0.0f;

    CP_WAIT(0);
    __syncthreads();

    #pragma unroll
    for (int ks = 0; ks < 16; ++ks) {
        const int k0 = ks * 16;
        uint32_t a[2][4], b[4][2];
        #pragma unroll
        for (int mi = 0; mi < 2; ++mi) {
            const __nv_bfloat16* ap = sm + M2_A + (wr * 32 + mi * 16 + lr) * LDH + k0 + lc * 2;
            a[mi][0] = *(const uint32_t*)ap;
            a[mi][1] = *(const uint32_t*)(ap + 8 * LDH);
            a[mi][2] = *(const uint32_t*)(ap + 8);
            a[mi][3] = *(const uint32_t*)(ap + 8 * LDH + 8);
        }
        #pragma unroll
        for (int ni = 0; ni < 4; ++ni) {
            const __nv_bfloat16* bp = sm + M2_W + (wc * 32 + ni * 8 + lr) * LDW + k0 + lc * 2;
            b[ni][0] = *(const uint32_t*)bp;
            b[ni][1] = *(const uint32_t*)(bp + 8);
        }
        #pragma unroll
        for (int mi = 0; mi < 2; ++mi)
            #pragma unroll
            for (int ni = 0; ni < 4; ++ni)
                mma_bf16(c2[mi][ni], a[mi][0], a[mi][1], a[mi][2], a[mi][3],
                         b[ni][0], b[ni][1]);
    }

    // epilogue: +b2 (+memory for KV), store bf16
    #pragma unroll
    for (int mi = 0; mi < 2; ++mi)
        #pragma unroll
        for (int ni = 0; ni < 4; ++ni) {
            int cl = wc * 32 + ni * 8 + lc * 2;          // local col in half
            int col = nh * 128 + cl;
            int g = grow0 + wr * 32 + mi * 16 + lr;
            float bl = __ldg(&b2[cl]), bh = __ldg(&b2[cl + 1]);
            float v0 = c2[mi][ni][0] + bl, v1 = c2[mi][ni][1] + bh;
            float v2 = c2[mi][ni][2] + bl, v3 = c2[mi][ni][3] + bh;
            if (KV) {
                size_t l0 = (size_t)(g - NROW_Q) * 256 + col;
                size_t l1 = (size_t)(g + 8 - NROW_Q) * 256 + col;
                float2 m0 = *(const float2*)(memory + l0);
                float2 m1 = *(const float2*)(memory + l1);
                *(__nv_bfloat162*)(g_kv + l0) = __floats2bfloat162_rn(v0 + m0.x, v1 + m0.y);
                *(__nv_bfloat162*)(g_kv + l1) = __floats2bfloat162_rn(v2 + m1.x, v3 + m1.y);
            } else {
                *(__nv_bfloat162*)(g_q + (size_t)g * 256 + col) = __floats2bfloat162_rn(v0, v1);
                *(__nv_bfloat162*)(g_q + (size_t)(g + 8) * 256 + col) = __floats2bfloat162_rn(v2, v3);
            }
        }
}

// ---------------------------------------------------------------------------
// Kernel 2: exact top-16 via spatial grid (unchanged)
// ---------------------------------------------------------------------------
#define TKCAP 320
__global__ void __launch_bounds__(256) topk_kernel(
    const float* __restrict__ q_coor)
{
    __shared__ unsigned long long sbuf[8][TKCAP + 16];

    const int wid = threadIdx.x >> 5, lane = threadIdx.x & 31;
    const int b = blockIdx.y;
    const int s = blockIdx.x * 8 + wid;
    const int qn = b * SQ + s;
    const float qx = q_coor[2 * qn], qy = q_coor[2 * qn + 1];
    const float q2 = __fadd_rn(__fmul_rn(qx, qx), __fmul_rn(qy, qy));
    const int cx = min(GC - 1, (int)(qx * (float)GC));
    const int cy = min(GC - 1, (int)(qy * (float)GC));
    const int* cs = g_cellstart[b];
    const float4* spt = g_spt[b];
    unsigned long long* buf = sbuf[wid];

    const unsigned long long UMAX = 0xFFFFFFFFFFFFFFFFull;
    unsigned long long bestk = UMAX;
    float tau = __int_as_float(0x7f800000);
    int cnt = 0;

    auto select16 = [&]() {
        unsigned valid = __ballot_sync(0xffffffffu, lane < 16 && bestk != UMAX);
        if (lane < 16 && bestk != UMAX) buf[cnt + lane] = bestk;
        cnt += __popc(valid);
        const int nper = (cnt + 31) >> 5;
        unsigned long long nb = UMAX;
        #pragma unroll 1
        for (int r = 0; r < 16; ++r) {
            unsigned long long mk = UMAX; int mj = 0;
            for (int i = 0; i < nper; ++i) {
                int j = lane + i * 32;
                if (j < cnt) {
                    unsigned long long v = buf[j];
                    if (v < mk) { mk = v; mj = j; }
                }
            }
            unsigned long long rk = mk; int rl = lane;
            #pragma unroll
            for (int off = 16; off; off >>= 1) {
                unsigned long long ok = __shfl_down_sync(0xffffffffu, rk, off);
                int ol = __shfl_down_sync(0xffffffffu, rl, off);
                if (ok < rk) { rk = ok; rl = ol; }
            }
            rk = __shfl_sync(0xffffffffu, rk, 0);
            rl = __shfl_sync(0xffffffffu, rl, 0);
            if (rk == UMAX) break;
            if (lane == r) nb = rk;
            if (lane == rl) buf[mj] = UMAX;
        }
        bestk = nb;
        unsigned long long k15 = __shfl_sync(0xffffffffu, bestk, 15);
        tau = (k15 == UMAX) ? __int_as_float(0x7f800000)
                            : ord2f((uint32_t)(k15 >> 32));
        cnt = 0;
    };

    auto scan_range = [&](int s0, int e0) {
        for (int j0 = s0; j0 < e0; j0 += 32) {
            const int j = j0 + lane;
            const bool valid = j < e0;
            float d2 = 0.0f; int oi = 0;
            if (valid) {
                float4 p = __ldg(&spt[j]);
                float m2 = __fadd_rn(__fmul_rn(p.x, p.x), __fmul_rn(p.y, p.y));
                float dt = __fmaf_rn(qy, p.y, __fmul_rn(qx, p.x));
                d2 = __fsub_rn(__fadd_rn(q2, m2), __fmul_rn(2.0f, dt));
                oi = __float_as_int(p.z);
            }
            bool acc = valid && (d2 < tau);
            unsigned mask = __ballot_sync(0xffffffffu, acc);
            if (!mask) continue;
            int nacc = __popc(mask);
            if (cnt + nacc > TKCAP) {
                select16();
                acc = valid && (d2 < tau);
                mask = __ballot_sync(0xffffffffu, acc);
                nacc = __popc(mask);
            }
            if (acc) {
                int pos = cnt + __popc(mask & ((1u << lane) - 1u));
                buf[pos] = ((unsigned long long)f2ord(d2) << 32) | (uint32_t)oi;
            }
            cnt += nacc;
        }
    };

    {
        int x0 = max(0, cx - 1), x1 = min(GC - 1, cx + 1);
        int y0 = max(0, cy - 1), y1 = min(GC - 1, cy + 1);
        for (int y = y0; y <= y1; ++y)
            scan_range(__ldg(&cs[y * GC + x0]), __ldg(&cs[y * GC + x1 + 1]));
        select16();
    }

    int R = 1;
    while (true) {
        float bound = (float)R * GH;
        bool full = (cx - R <= 0) && (cx + R >= GC - 1) &&
                    (cy - R <= 0) && (cy + R >= GC - 1);
        if (full || tau < bound * bound - 2e-6f) break;
        ++R;
        const int nx0 = max(0, cx - R), nx1 = min(GC - 1, cx + R);
        if (cy - R >= 0)
            scan_range(__ldg(&cs[(cy - R) * GC + nx0]), __ldg(&cs[(cy - R) * GC + nx1 + 1]));
        if (cy + R <= GC - 1)
            scan_range(__ldg(&cs[(cy + R) * GC + nx0]), __ldg(&cs[(cy + R) * GC + nx1 + 1]));
        const int my0 = max(0, cy - R + 1), my1 = min(GC - 1, cy + R - 1);
        for (int y = my0; y <= my1; ++y) {
            if (cx - R >= 0)
                scan_range(__ldg(&cs[y * GC + cx - R]), __ldg(&cs[y * GC + cx - R + 1]));
            if (cx + R <= GC - 1)
                scan_range(__ldg(&cs[y * GC + cx + R]), __ldg(&cs[y * GC + cx + R + 1]));
        }
        if (cnt > 0) select16();
    }

    if (lane < 16) g_idx[qn * 16 + lane] = (int)(uint32_t)bestk;
}

// ---------------------------------------------------------------------------
// Kernel 3: gather + softmax over D + multiply. q/kv read as bf16 (half the
// gather traffic); memory fp32; no-max softmax; streaming output stores.
// ---------------------------------------------------------------------------
__global__ void __launch_bounds__(128, 1) attn_kernel(
    const float* __restrict__ memory, float* __restrict__ out)
{
    const int s = blockIdx.x, b = blockIdx.y;
    const int qn = b * SQ + s;
    const int w = threadIdx.x >> 5, lane = threadIdx.x & 31;

    float qv[8];
    {
        uint4 u = ((const uint4*)(g_q + (size_t)qn * 256))[lane];
        bf2x(qv[0], qv[1], u.x); bf2x(qv[2], qv[3], u.y);
        bf2x(qv[4], qv[5], u.z); bf2x(qv[6], qv[7], u.w);
    }

    #pragma unroll
    for (int jj = 0; jj < 4; jj += 2) {
        const int j0 = w * 4 + jj;
        const int idx0 = __ldg(&g_idx[qn * 16 + j0]);
        const int idx1 = __ldg(&g_idx[qn * 16 + j0 + 1]);

        float ka[8], kb[8];
        {
            uint4 u = ((const uint4*)(g_kv + ((size_t)b * LM + idx0) * 256))[lane];
            bf2x(ka[0], ka[1], u.x); bf2x(ka[2], ka[3], u.y);
            bf2x(ka[4], ka[5], u.z); bf2x(ka[6], ka[7], u.w);
        }
        {
            uint4 u = ((const uint4*)(g_kv + ((size_t)b * LM + idx1) * 256))[lane];
            bf2x(kb[0], kb[1], u.x); bf2x(kb[2], kb[3], u.y);
            bf2x(kb[4], kb[5], u.z); bf2x(kb[6], kb[7], u.w);
        }

        float pa[8], pb[8];
        float sa = 0.0f, sb = 0.0f;
        #pragma unroll
        for (int i = 0; i < 8; ++i) {
            pa[i] = __expf(qv[i] * ka[i] * 0.0625f); sa += pa[i];
            pb[i] = __expf(qv[i] * kb[i] * 0.0625f); sb += pb[i];
        }
        #pragma unroll
        for (int off = 16; off; off >>= 1) {
            sa += __shfl_xor_sync(0xffffffffu, sa, off);
            sb += __shfl_xor_sync(0xffffffffu, sb, off);
        }
        const float ia = __frcp_rn(sa), ib = __frcp_rn(sb);

        const float4* mp0 = (const float4*)(memory + ((size_t)b * LM + idx0) * 256);
        const float4* mp1 = (const float4*)(memory + ((size_t)b * LM + idx1) * 256);
        float4 ma0 = mp0[lane * 2], ma1 = mp0[lane * 2 + 1];
        float4 mb0 = mp1[lane * 2], mb1 = mp1[lane * 2 + 1];

        float4 r;
        float4* op0 = (float4*)(out + ((size_t)(qn * 16 + j0)) * 256);
        float4* op1 = (float4*)(out + ((size_t)(qn * 16 + j0 + 1)) * 256);
        r.x = pa[0] * ia * ma0.x; r.y = pa[1] * ia * ma0.y;
        r.z = pa[2] * ia * ma0.z; r.w = pa[3] * ia * ma0.w;
        __stcs(&op0[lane * 2], r);
        r.x = pa[4] * ia * ma1.x; r.y = pa[5] * ia * ma1.y;
        r.z = pa[6] * ia * ma1.z; r.w = pa[7] * ia * ma1.w;
        __stcs(&op0[lane * 2 + 1], r);
        r.x = pb[0] * ib * mb0.x; r.y = pb[1] * ib * mb0.y;
        r.z = pb[2] * ib * mb0.z; r.w = pb[3] * ib * mb0.w;
        __stcs(&op1[lane * 2], r);
        r.x = pb[4] * ib * mb1.x; r.y = pb[5] * ib * mb1.y;
        r.z = pb[6] * ib * mb1.z; r.w = pb[7] * ib * mb1.w;
        __stcs(&op1[lane * 2 + 1], r);
    }
}

// ---------------------------------------------------------------------------

extern "C" void kernel_launch(void* const* d_in, const int* in_sizes, int n_in,
                              void* d_out, int out_size)
{
    const float* memory   = (const float*)d_in[0];
    const float* mem_coor = (const float*)d_in[1];
    const float* q_coor   = (const float*)d_in[2];
    const float* Wq1 = (const float*)d_in[3];
    const float* bq1 = (const float*)d_in[4];
    const float* Wq2 = (const float*)d_in[5];
    const float* bq2 = (const float*)d_in[6];
    const float* Wk1 = (const float*)d_in[7];
    const float* bk1 = (const float*)d_in[8];
    const float* Wk2 = (const float*)d_in[9];
    const float* bk2 = (const float*)d_in[10];
    float* out = (float*)d_out;

    cudaFuncSetAttribute(mlp1_kernel,
        cudaFuncAttributeMaxDynamicSharedMemorySize, SMEM_MLP1);
    cudaFuncSetAttribute(mlp2_kernel,
        cudaFuncAttributeMaxDynamicSharedMemorySize, SMEM_MLP2);

    // K0: weight transpose + bf16; spatial grid build
    prep_weights<<<256, 256>>>(Wq1, Wq2, Wk1, Wk2);
    grid_build<<<BQ, 1024>>>(mem_coor);

    // K1: MLP layers
    mlp1_kernel<<<768, 256, SMEM_MLP1>>>(q_coor, mem_coor, bq1, bk1);
    mlp2_kernel<<<dim3(NROW_T / 64, 2), 256, SMEM_MLP2>>>(bq2, bk2, memory);

    // K2: top-16 neighbors via spatial grid
    topk_kernel<<<dim3(SQ / 8, BQ), 256>>>(q_coor);

    // K3: gather + softmax(D) + multiply
    attn_kernel<<<dim3(SQ, BQ), 128>>>(memory, out);
}

// round 17
// speedup vs baseline: 4.6852x; 1.0132x over previous
#include <cuda_runtime.h>
#include <cuda_bf16.h>
#include <cstdint>

#define BQ  4
#define SQ  4096
#define LM  8192
#define DD  256
#define KNN 16
#define NROW_Q (BQ*SQ)          /* 16384 */
#define NROW_T (BQ*(SQ+LM))     /* 49152 total MLP rows */

// Scratch (device globals: allocation-free, graph-capture safe)
__device__ __align__(16) __nv_bfloat16 g_q [(size_t)BQ*SQ*DD];  // 8 MB  (bf16)
__device__ __align__(16) __nv_bfloat16 g_kv[(size_t)BQ*LM*DD];  // 16 MB (bf16)
__device__ int   g_idx[BQ*SQ*KNN];                              // 1 MB
__device__ __align__(16) __nv_bfloat16 g_h[(size_t)NROW_T*DD];  // 24 MB hidden
// bf16 transposed weights
__device__ __align__(16) __nv_bfloat16 g_w1t_q[256*128];
__device__ __align__(16) __nv_bfloat16 g_w2t_q[256*256];
__device__ __align__(16) __nv_bfloat16 g_w1t_k[256*128];
__device__ __align__(16) __nv_bfloat16 g_w2t_k[256*256];
// spatial grid (32x32 cells per batch)
#define GC 32
#define GCELLS (GC*GC)
#define GH 0.03125f
__device__ int g_cellstart[BQ][GCELLS + 1];
__device__ __align__(16) float4 g_spt[BQ][LM];   // sorted {x, y, bits(idx), 0}

// ---------------------------------------------------------------------------
#define LDA 136
#define LDB 136
#define LDH 264
#define LDW 264
#define M1_A  0
#define M1_WB (64 * LDA)
#define SMEM_MLP1 ((M1_WB + 256 * LDB) * 2)
// mlp2: AH 64xLDH (33792B) + W 128xLDW (67584B) = 101376B -> 2 CTA/SM
#define M2_A 0
#define M2_W (64 * LDH)
#define SMEM_MLP2 ((M2_W + 128 * LDW) * 2)

__device__ __forceinline__ void mma_bf16(float c[4],
    uint32_t a0, uint32_t a1, uint32_t a2, uint32_t a3,
    uint32_t b0, uint32_t b1)
{
    asm volatile(
        "mma.sync.aligned.m16n8k16.row.col.f32.bf16.bf16.f32 "
        "{%0,%1,%2,%3}, {%4,%5,%6,%7}, {%8,%9}, {%0,%1,%2,%3};"
        : "+f"(c[0]), "+f"(c[1]), "+f"(c[2]), "+f"(c[3])
        : "r"(a0), "r"(a1), "r"(a2), "r"(a3), "r"(b0), "r"(b1));
}

__device__ __forceinline__ void cp16(uint32_t smem, const void* g) {
    asm volatile("cp.async.cg.shared.global [%0], [%1], 16;" :: "r"(smem), "l"(g));
}
#define CP_COMMIT() asm volatile("cp.async.commit_group;" ::: "memory")
#define CP_WAIT(n)  asm volatile("cp.async.wait_group %0;" :: "n"(n) : "memory")

__device__ __forceinline__ uint32_t f2ord(float f) {
    uint32_t u = __float_as_uint(f);
    return u ^ ((uint32_t)((int)u >> 31) | 0x80000000u);
}
__device__ __forceinline__ float ord2f(uint32_t o) {
    uint32_t u = o ^ ((uint32_t)((int)(~o) >> 31) | 0x80000000u);
    return __uint_as_float(u);
}
__device__ __forceinline__ void bf2x(float& lo, float& hi, uint32_t u) {
    float2 f = __bfloat1622float2(*(__nv_bfloat162*)&u);
    lo = f.x; hi = f.y;
}

// Fast exp on FMA/ALU pipes (no MUFU). 2^t split: n = rne(t) via magic
// constant; 2^f (f in [-0.5,0.5]) by degree-5 Taylor (rel err ~3e-6);
// exponent applied by integer add on float bits. Valid for |x| < ~80.
__device__ __forceinline__ float fexp(float x) {
    float t = x * 1.4426950408889634f;           // x * log2(e)
    float m = t + 12582912.0f;                   // round to nearest (2^23+2^22)
    int   n = __float_as_int(m) - 0x4B400000;    // integer part
    float f = t - (m - 12582912.0f);             // frac in [-0.5, 0.5]
    float p = 1.3333558146e-3f;                  // 2^f Taylor (ln2)^k/k!
    p = fmaf(p, f, 9.6181291081e-3f);
    p = fmaf(p, f, 5.5504108665e-2f);
    p = fmaf(p, f, 2.4022650696e-1f);
    p = fmaf(p, f, 6.9314718056e-1f);
    p = fmaf(p, f, 1.0f);
    return __int_as_float(__float_as_int(p) + (n << 23));
}

// ---------------------------------------------------------------------------
// Kernel 0: weight prep (unchanged)
// ---------------------------------------------------------------------------
__global__ void prep_weights(const float* __restrict__ Wq1, const float* __restrict__ Wq2,
                             const float* __restrict__ Wk1, const float* __restrict__ Wk2)
{
    int idx = blockIdx.x * 256 + threadIdx.x;
    {
        int n = idx >> 8, k = idx & 255;
        g_w2t_q[idx] = __float2bfloat16(Wq2[k * 256 + n]);
        g_w2t_k[idx] = __float2bfloat16(Wk2[k * 256 + n]);
    }
    if (idx < 32768) {
        int n = idx >> 7, k = idx & 127;
        g_w1t_q[idx] = __float2bfloat16(Wq1[k * 256 + n]);
        g_w1t_k[idx] = __float2bfloat16(Wk1[k * 256 + n]);
    }
}

// ---------------------------------------------------------------------------
// Kernel 0b: spatial grid build (unchanged)
// ---------------------------------------------------------------------------
__global__ void __launch_bounds__(1024, 1) grid_build(const float* __restrict__ mem_coor)
{
    __shared__ int hist[GCELLS];
    __shared__ int scn[GCELLS];
    const int b = blockIdx.x, tid = threadIdx.x;
    hist[tid] = 0;
    __syncthreads();

    const float2* mc = (const float2*)(mem_coor + (size_t)b * LM * 2);
    int cellid[8]; float2 pt[8];
    #pragma unroll
    for (int i = 0; i < 8; ++i) {
        int p = tid + i * 1024;
        float2 c = mc[p];
        int cx = min(GC - 1, (int)(c.x * (float)GC));
        int cy = min(GC - 1, (int)(c.y * (float)GC));
        cellid[i] = cy * GC + cx; pt[i] = c;
        atomicAdd(&hist[cellid[i]], 1);
    }
    __syncthreads();

    int v = hist[tid];
    scn[tid] = v;
    __syncthreads();
    for (int off = 1; off < GCELLS; off <<= 1) {
        int t = (tid >= off) ? scn[tid - off] : 0;
        __syncthreads();
        scn[tid] += t;
        __syncthreads();
    }
    int excl = scn[tid] - v;
    g_cellstart[b][tid] = excl;
    if (tid == GCELLS - 1) g_cellstart[b][GCELLS] = LM;
    hist[tid] = excl;
    __syncthreads();

    #pragma unroll
    for (int i = 0; i < 8; ++i) {
        int p = tid + i * 1024;
        int pos = atomicAdd(&hist[cellid[i]], 1);
        g_spt[b][pos] = make_float4(pt[i].x, pt[i].y, __int_as_float(p), 0.0f);
    }
}

// ---------------------------------------------------------------------------
// Kernel 1a: posemb + layer 1 (unchanged)
// ---------------------------------------------------------------------------
__global__ void __launch_bounds__(256, 2) mlp1_kernel(
    const float* __restrict__ q_coor, const float* __restrict__ mem_coor,
    const float* __restrict__ bq1, const float* __restrict__ bk1)
{
    extern __shared__ __nv_bfloat16 sm[];
    const int tid = threadIdx.x;
    const int w = tid >> 5, lane = tid & 31;
    const int wr = w >> 2, wc = w & 3;
    const int lr = lane >> 2, lc = lane & 3;

    const bool KV = blockIdx.x >= 256;
    const int lrow0 = (KV ? (blockIdx.x - 256) : blockIdx.x) * 64;
    const int grow0 = KV ? (NROW_Q + lrow0) : lrow0;
    const float* coor = KV ? mem_coor : q_coor;
    const __nv_bfloat16* w1t = KV ? g_w1t_k : g_w1t_q;
    const float* b1 = KV ? bk1 : bq1;

    for (int p = tid; p < 64 * 64; p += 256) {
        int r = p >> 6, pp = p & 63;
        int half = pp >> 5, j = pp & 31;
        float coord = coor[2 * (lrow0 + r) + (half ? 0 : 1)];
        float freq = exp2f(-(float)j * 0.4152410118609203f);
        float v = coord * 6.283185307179586477f * freq;
        float sv, cv;
        sincosf(v, &sv, &cv);
        *(__nv_bfloat162*)(sm + M1_A + r * LDA + half * 64 + 2 * j) =
            __floats2bfloat162_rn(sv, cv);
    }
    for (int p = tid; p < 256 * 16; p += 256) {
        int n = p >> 4, ch = p & 15;
        *(uint4*)(sm + M1_WB + n * LDB + ch * 8) = *(const uint4*)(w1t + n * 128 + ch * 8);
    }
    __syncthreads();

    float c1[2][8][4];
    #pragma unroll
    for (int mi = 0; mi < 2; ++mi)
        #pragma unroll
        for (int ni = 0; ni < 8; ++ni)
            #pragma unroll
            for (int q = 0; q < 4; ++q) c1[mi][ni][q] = 0.0f;

    #pragma unroll
    for (int ks = 0; ks < 8; ++ks) {
        const int k0 = ks * 16;
        uint32_t a[2][4], b[8][2];
        #pragma unroll
        for (int mi = 0; mi < 2; ++mi) {
            const __nv_bfloat16* ap = sm + M1_A + (wr * 32 + mi * 16 + lr) * LDA + k0 + lc * 2;
            a[mi][0] = *(const uint32_t*)ap;
            a[mi][1] = *(const uint32_t*)(ap + 8 * LDA);
            a[mi][2] = *(const uint32_t*)(ap + 8);
            a[mi][3] = *(const uint32_t*)(ap + 8 * LDA + 8);
        }
        #pragma unroll
        for (int ni = 0; ni < 8; ++ni) {
            const __nv_bfloat16* bp = sm + M1_WB + (wc * 64 + ni * 8 + lr) * LDB + k0 + lc * 2;
            b[ni][0] = *(const uint32_t*)bp;
            b[ni][1] = *(const uint32_t*)(bp + 8);
        }
        #pragma unroll
        for (int mi = 0; mi < 2; ++mi)
            #pragma unroll
            for (int ni = 0; ni < 8; ++ni)
                mma_bf16(c1[mi][ni], a[mi][0], a[mi][1], a[mi][2], a[mi][3],
                         b[ni][0], b[ni][1]);
    }

    #pragma unroll
    for (int mi = 0; mi < 2; ++mi)
        #pragma unroll
        for (int ni = 0; ni < 8; ++ni) {
            int col = wc * 64 + ni * 8 + lc * 2;
            int row = grow0 + wr * 32 + mi * 16 + lr;
            float bl = __ldg(&b1[col]), bh = __ldg(&b1[col + 1]);
            float v0 = fmaxf(c1[mi][ni][0] + bl, 0.0f);
            float v1 = fmaxf(c1[mi][ni][1] + bh, 0.0f);
            float v2 = fmaxf(c1[mi][ni][2] + bl, 0.0f);
            float v3 = fmaxf(c1[mi][ni][3] + bh, 0.0f);
            *(__nv_bfloat162*)(g_h + (size_t)row * 256 + col) = __floats2bfloat162_rn(v0, v1);
            *(__nv_bfloat162*)(g_h + (size_t)(row + 8) * 256 + col) = __floats2bfloat162_rn(v2, v3);
        }
}

// ---------------------------------------------------------------------------
// Kernel 1b: layer 2 (unchanged from R16 pass)
// ---------------------------------------------------------------------------
__global__ void __launch_bounds__(256, 2) mlp2_kernel(
    const float* __restrict__ bq2, const float* __restrict__ bk2,
    const float* __restrict__ memory)
{
    extern __shared__ __nv_bfloat16 sm[];
    const uint32_t smb = (uint32_t)__cvta_generic_to_shared(sm);
    const int tid = threadIdx.x;
    const int w = tid >> 5, lane = tid & 31;
    const int wr = w >> 2, wc = w & 3;
    const int lr = lane >> 2, lc = lane & 3;

    const int grow0 = blockIdx.x * 64;
    const int nh = blockIdx.y;
    const bool KV = grow0 >= NROW_Q;
    const __nv_bfloat16* w2t = (KV ? g_w2t_k : g_w2t_q) + (size_t)nh * 128 * 256;
    const float* b2 = (KV ? bk2 : bq2) + nh * 128;

    for (int p = tid; p < 64 * 32; p += 256) {
        int r = p >> 5, ch = p & 31;
        cp16(smb + (M2_A + r * LDH + ch * 8) * 2,
             g_h + (size_t)(grow0 + r) * 256 + ch * 8);
    }
    for (int p = tid; p < 128 * 32; p += 256) {
        int n = p >> 5, ch = p & 31;
        cp16(smb + (M2_W + n * LDW + ch * 8) * 2, w2t + n * 256 + ch * 8);
    }
    CP_COMMIT();

    float c2[2][4][4];
    #pragma unroll
    for (int mi = 0; mi < 2; ++mi)
        #pragma unroll
        for (int ni = 0; ni < 4; ++ni)
            #pragma unroll
            for (int q = 0; q < 4; ++q) c2[mi][ni][q] = 0.0f;

    CP_WAIT(0);
    __syncthreads();

    #pragma unroll
    for (int ks = 0; ks < 16; ++ks) {
        const int k0 = ks * 16;
        uint32_t a[2][4], b[4][2];
        #pragma unroll
        for (int mi = 0; mi < 2; ++mi) {
            const __nv_bfloat16* ap = sm + M2_A + (wr * 32 + mi * 16 + lr) * LDH + k0 + lc * 2;
            a[mi][0] = *(const uint32_t*)ap;
            a[mi][1] = *(const uint32_t*)(ap + 8 * LDH);
            a[mi][2] = *(const uint32_t*)(ap + 8);
            a[mi][3] = *(const uint32_t*)(ap + 8 * LDH + 8);
        }
        #pragma unroll
        for (int ni = 0; ni < 4; ++ni) {
            const __nv_bfloat16* bp = sm + M2_W + (wc * 32 + ni * 8 + lr) * LDW + k0 + lc * 2;
            b[ni][0] = *(const uint32_t*)bp;
            b[ni][1] = *(const uint32_t*)(bp + 8);
        }
        #pragma unroll
        for (int mi = 0; mi < 2; ++mi)
            #pragma unroll
            for (int ni = 0; ni < 4; ++ni)
                mma_bf16(c2[mi][ni], a[mi][0], a[mi][1], a[mi][2], a[mi][3],
                         b[ni][0], b[ni][1]);
    }

    #pragma unroll
    for (int mi = 0; mi < 2; ++mi)
        #pragma unroll
        for (int ni = 0; ni < 4; ++ni) {
            int cl = wc * 32 + ni * 8 + lc * 2;
            int col = nh * 128 + cl;
            int g = grow0 + wr * 32 + mi * 16 + lr;
            float bl = __ldg(&b2[cl]), bh = __ldg(&b2[cl + 1]);
            float v0 = c2[mi][ni][0] + bl, v1 = c2[mi][ni][1] + bh;
            float v2 = c2[mi][ni][2] + bl, v3 = c2[mi][ni][3] + bh;
            if (KV) {
                size_t l0 = (size_t)(g - NROW_Q) * 256 + col;
                size_t l1 = (size_t)(g + 8 - NROW_Q) * 256 + col;
                float2 m0 = *(const float2*)(memory + l0);
                float2 m1 = *(const float2*)(memory + l1);
                *(__nv_bfloat162*)(g_kv + l0) = __floats2bfloat162_rn(v0 + m0.x, v1 + m0.y);
                *(__nv_bfloat162*)(g_kv + l1) = __floats2bfloat162_rn(v2 + m1.x, v3 + m1.y);
            } else {
                *(__nv_bfloat162*)(g_q + (size_t)g * 256 + col) = __floats2bfloat162_rn(v0, v1);
                *(__nv_bfloat162*)(g_q + (size_t)(g + 8) * 256 + col) = __floats2bfloat162_rn(v2, v3);
            }
        }
}

// ---------------------------------------------------------------------------
// Kernel 2: exact top-16 via spatial grid (unchanged)
// ---------------------------------------------------------------------------
#define TKCAP 320
__global__ void __launch_bounds__(256) topk_kernel(
    const float* __restrict__ q_coor)
{
    __shared__ unsigned long long sbuf[8][TKCAP + 16];

    const int wid = threadIdx.x >> 5, lane = threadIdx.x & 31;
    const int b = blockIdx.y;
    const int s = blockIdx.x * 8 + wid;
    const int qn = b * SQ + s;
    const float qx = q_coor[2 * qn], qy = q_coor[2 * qn + 1];
    const float q2 = __fadd_rn(__fmul_rn(qx, qx), __fmul_rn(qy, qy));
    const int cx = min(GC - 1, (int)(qx * (float)GC));
    const int cy = min(GC - 1, (int)(qy * (float)GC));
    const int* cs = g_cellstart[b];
    const float4* spt = g_spt[b];
    unsigned long long* buf = sbuf[wid];

    const unsigned long long UMAX = 0xFFFFFFFFFFFFFFFFull;
    unsigned long long bestk = UMAX;
    float tau = __int_as_float(0x7f800000);
    int cnt = 0;

    auto select16 = [&]() {
        unsigned valid = __ballot_sync(0xffffffffu, lane < 16 && bestk != UMAX);
        if (lane < 16 && bestk != UMAX) buf[cnt + lane] = bestk;
        cnt += __popc(valid);
        const int nper = (cnt + 31) >> 5;
        unsigned long long nb = UMAX;
        #pragma unroll 1
        for (int r = 0; r < 16; ++r) {
            unsigned long long mk = UMAX; int mj = 0;
            for (int i = 0; i < nper; ++i) {
                int j = lane + i * 32;
                if (j < cnt) {
                    unsigned long long v = buf[j];
                    if (v < mk) { mk = v; mj = j; }
                }
            }
            unsigned long long rk = mk; int rl = lane;
            #pragma unroll
            for (int off = 16; off; off >>= 1) {
                unsigned long long ok = __shfl_down_sync(0xffffffffu, rk, off);
                int ol = __shfl_down_sync(0xffffffffu, rl, off);
                if (ok < rk) { rk = ok; rl = ol; }
            }
            rk = __shfl_sync(0xffffffffu, rk, 0);
            rl = __shfl_sync(0xffffffffu, rl, 0);
            if (rk == UMAX) break;
            if (lane == r) nb = rk;
            if (lane == rl) buf[mj] = UMAX;
        }
        bestk = nb;
        unsigned long long k15 = __shfl_sync(0xffffffffu, bestk, 15);
        tau = (k15 == UMAX) ? __int_as_float(0x7f800000)
                            : ord2f((uint32_t)(k15 >> 32));
        cnt = 0;
    };

    auto scan_range = [&](int s0, int e0) {
        for (int j0 = s0; j0 < e0; j0 += 32) {
            const int j = j0 + lane;
            const bool valid = j < e0;
            float d2 = 0.0f; int oi = 0;
            if (valid) {
                float4 p = __ldg(&spt[j]);
                float m2 = __fadd_rn(__fmul_rn(p.x, p.x), __fmul_rn(p.y, p.y));
                float dt = __fmaf_rn(qy, p.y, __fmul_rn(qx, p.x));
                d2 = __fsub_rn(__fadd_rn(q2, m2), __fmul_rn(2.0f, dt));
                oi = __float_as_int(p.z);
            }
            bool acc = valid && (d2 < tau);
            unsigned mask = __ballot_sync(0xffffffffu, acc);
            if (!mask) continue;
            int nacc = __popc(mask);
            if (cnt + nacc > TKCAP) {
                select16();
                acc = valid && (d2 < tau);
                mask = __ballot_sync(0xffffffffu, acc);
                nacc = __popc(mask);
            }
            if (acc) {
                int pos = cnt + __popc(mask & ((1u << lane) - 1u));
                buf[pos] = ((unsigned long long)f2ord(d2) << 32) | (uint32_t)oi;
            }
            cnt += nacc;
        }
    };

    {
        int x0 = max(0, cx - 1), x1 = min(GC - 1, cx + 1);
        int y0 = max(0, cy - 1), y1 = min(GC - 1, cy + 1);
        for (int y = y0; y <= y1; ++y)
            scan_range(__ldg(&cs[y * GC + x0]), __ldg(&cs[y * GC + x1 + 1]));
        select16();
    }

    int R = 1;
    while (true) {
        float bound = (float)R * GH;
        bool full = (cx - R <= 0) && (cx + R >= GC - 1) &&
                    (cy - R <= 0) && (cy + R >= GC - 1);
        if (full || tau < bound * bound - 2e-6f) break;
        ++R;
        const int nx0 = max(0, cx - R), nx1 = min(GC - 1, cx + R);
        if (cy - R >= 0)
            scan_range(__ldg(&cs[(cy - R) * GC + nx0]), __ldg(&cs[(cy - R) * GC + nx1 + 1]));
        if (cy + R <= GC - 1)
            scan_range(__ldg(&cs[(cy + R) * GC + nx0]), __ldg(&cs[(cy + R) * GC + nx1 + 1]));
        const int my0 = max(0, cy - R + 1), my1 = min(GC - 1, cy + R - 1);
        for (int y = my0; y <= my1; ++y) {
            if (cx - R >= 0)
                scan_range(__ldg(&cs[y * GC + cx - R]), __ldg(&cs[y * GC + cx - R + 1]));
            if (cx + R <= GC - 1)
                scan_range(__ldg(&cs[y * GC + cx + R]), __ldg(&cs[y * GC + cx + R + 1]));
        }
        if (cnt > 0) select16();
    }

    if (lane < 16) g_idx[qn * 16 + lane] = (int)(uint32_t)bestk;
}

// ---------------------------------------------------------------------------
// Kernel 3: gather + softmax over D + multiply. fexp on FMA/ALU pipes
// (replaces MUFU __expf — the measured bottleneck). bf16 q/kv gathers,
// fp32 memory, no-max softmax, streaming output stores.
// ---------------------------------------------------------------------------
__global__ void __launch_bounds__(128, 1) attn_kernel(
    const float* __restrict__ memory, float* __restrict__ out)
{
    const int s = blockIdx.x, b = blockIdx.y;
    const int qn = b * SQ + s;
    const int w = threadIdx.x >> 5, lane = threadIdx.x & 31;

    float qv[8];
    {
        uint4 u = ((const uint4*)(g_q + (size_t)qn * 256))[lane];
        bf2x(qv[0], qv[1], u.x); bf2x(qv[2], qv[3], u.y);
        bf2x(qv[4], qv[5], u.z); bf2x(qv[6], qv[7], u.w);
    }

    #pragma unroll
    for (int jj = 0; jj < 4; jj += 2) {
        const int j0 = w * 4 + jj;
        const int idx0 = __ldg(&g_idx[qn * 16 + j0]);
        const int idx1 = __ldg(&g_idx[qn * 16 + j0 + 1]);

        float ka[8], kb[8];
        {
            uint4 u = ((const uint4*)(g_kv + ((size_t)b * LM + idx0) * 256))[lane];
            bf2x(ka[0], ka[1], u.x); bf2x(ka[2], ka[3], u.y);
            bf2x(ka[4], ka[5], u.z); bf2x(ka[6], ka[7], u.w);
        }
        {
            uint4 u = ((const uint4*)(g_kv + ((size_t)b * LM + idx1) * 256))[lane];
            bf2x(kb[0], kb[1], u.x); bf2x(kb[2], kb[3], u.y);
            bf2x(kb[4], kb[5], u.z); bf2x(kb[6], kb[7], u.w);
        }

        float pa[8], pb[8];
        float sa = 0.0f, sb = 0.0f;
        #pragma unroll
        for (int i = 0; i < 8; ++i) {
            pa[i] = fexp(qv[i] * ka[i] * 0.0625f); sa += pa[i];
            pb[i] = fexp(qv[i] * kb[i] * 0.0625f); sb += pb[i];
        }
        #pragma unroll
        for (int off = 16; off; off >>= 1) {
            sa += __shfl_xor_sync(0xffffffffu, sa, off);
            sb += __shfl_xor_sync(0xffffffffu, sb, off);
        }
        const float ia = __frcp_rn(sa), ib = __frcp_rn(sb);

        const float4* mp0 = (const float4*)(memory + ((size_t)b * LM + idx0) * 256);
        const float4* mp1 = (const float4*)(memory + ((size_t)b * LM + idx1) * 256);
        float4 ma0 = mp0[lane * 2], ma1 = mp0[lane * 2 + 1];
        float4 mb0 = mp1[lane * 2], mb1 = mp1[lane * 2 + 1];

        float4 r;
        float4* op0 = (float4*)(out + ((size_t)(qn * 16 + j0)) * 256);
        float4* op1 = (float4*)(out + ((size_t)(qn * 16 + j0 + 1)) * 256);
        r.x = pa[0] * ia * ma0.x; r.y = pa[1] * ia * ma0.y;
        r.z = pa[2] * ia * ma0.z; r.w = pa[3] * ia * ma0.w;
        __stcs(&op0[lane * 2], r);
        r.x = pa[4] * ia * ma1.x; r.y = pa[5] * ia * ma1.y;
        r.z = pa[6] * ia * ma1.z; r.w = pa[7] * ia * ma1.w;
        __stcs(&op0[lane * 2 + 1], r);
        r.x = pb[0] * ib * mb0.x; r.y = pb[1] * ib * mb0.y;
        r.z = pb[2] * ib * mb0.z; r.w = pb[3] * ib * mb0.w;
        __stcs(&op1[lane * 2], r);
        r.x = pb[4] * ib * mb1.x; r.y = pb[5] * ib * mb1.y;
        r.z = pb[6] * ib * mb1.z; r.w = pb[7] * ib * mb1.w;
        __stcs(&op1[lane * 2 + 1], r);
    }
}

// ---------------------------------------------------------------------------

extern "C" void kernel_launch(void* const* d_in, const int* in_sizes, int n_in,
                              void* d_out, int out_size)
{
    const float* memory   = (const float*)d_in[0];
    const float* mem_coor = (const float*)d_in[1];
    const float* q_coor   = (const float*)d_in[2];
    const float* Wq1 = (const float*)d_in[3];
    const float* bq1 = (const float*)d_in[4];
    const float* Wq2 = (const float*)d_in[5];
    const float* bq2 = (const float*)d_in[6];
    const float* Wk1 = (const float*)d_in[7];
    const float* bk1 = (const float*)d_in[8];
    const float* Wk2 = (const float*)d_in[9];
    const float* bk2 = (const float*)d_in[10];
    float* out = (float*)d_out;

    cudaFuncSetAttribute(mlp1_kernel,
        cudaFuncAttributeMaxDynamicSharedMemorySize, SMEM_MLP1);
    cudaFuncSetAttribute(mlp2_kernel,
        cudaFuncAttributeMaxDynamicSharedMemorySize, SMEM_MLP2);

    // K0: weight transpose + bf16; spatial grid build
    prep_weights<<<256, 256>>>(Wq1, Wq2, Wk1, Wk2);
    grid_build<<<BQ, 1024>>>(mem_coor);

    // K1: MLP layers
    mlp1_kernel<<<768, 256, SMEM_MLP1>>>(q_coor, mem_coor, bq1, bk1);
    mlp2_kernel<<<dim3(NROW_T / 64, 2), 256, SMEM_MLP2>>>(bq2, bk2, memory);

    // K2: top-16 neighbors via spatial grid
    topk_kernel<<<dim3(SQ / 8, BQ), 256>>>(q_coor);

    // K3: gather + softmax(D) + multiply
    attn_kernel<<<dim3(SQ, BQ), 128>>>(memory, out);
}